// round 1
// baseline (speedup 1.0000x reference)
#include <cuda_runtime.h>
#include <cuda_bf16.h>
#include <math.h>

// Problem constants
#define BB   2
#define LL   2048
#define DD   2048
#define HH   16
#define DHD  128
#define DREL 64
#define KSEL 512
#define MROWS (BB*LL)   // 4096

// -------------------- scratch (device globals; no cudaMalloc allowed) ---------
__device__ float    g_q   [BB*LL*DD];
__device__ float    g_k   [BB*LL*DD];
__device__ float    g_v   [BB*LL*DD];
__device__ float    g_ctx [BB*LL*DD];
__device__ float    g_qrel[BB*LL*DREL];
__device__ float    g_krel[BB*LL*DREL];
__device__ unsigned g_mask[BB*LL*(LL/32)];

// ============================ SGEMM (C = A * B^T) =============================
// A: [M,Kd] row-major, B: [N,Kd] row-major, C: [M,Kd->N] row-major.
// Tile 128x128x8, 256 threads, 8x8 per thread.
__global__ __launch_bounds__(256) void sgemm_nt(
    const float* __restrict__ A, const float* __restrict__ B,
    float* __restrict__ C, int M, int N, int Kd)
{
    __shared__ float As[8][128];
    __shared__ float Bs[8][128];

    const int tid = threadIdx.x;
    const int tx  = tid & 15;
    const int ty  = tid >> 4;
    const int bm  = blockIdx.y * 128;
    const int bn  = blockIdx.x * 128;

    // load mapping: 128 rows * 8 k-cols = 256 float4
    const int lr = tid >> 1;
    const int lc = (tid & 1) * 4;

    float acc[8][8];
    #pragma unroll
    for (int i = 0; i < 8; i++)
        #pragma unroll
        for (int j = 0; j < 8; j++) acc[i][j] = 0.f;

    const float* Aptr = A + (size_t)(bm + lr) * Kd + lc;
    int brow = bn + lr; if (brow >= N) brow = 0;   // clamp for small-N (rel proj)
    const float* Bptr = B + (size_t)brow * Kd + lc;

    for (int k0 = 0; k0 < Kd; k0 += 8) {
        float4 a4 = *(const float4*)(Aptr + k0);
        float4 b4 = *(const float4*)(Bptr + k0);
        __syncthreads();
        As[lc+0][lr] = a4.x; As[lc+1][lr] = a4.y; As[lc+2][lr] = a4.z; As[lc+3][lr] = a4.w;
        Bs[lc+0][lr] = b4.x; Bs[lc+1][lr] = b4.y; Bs[lc+2][lr] = b4.z; Bs[lc+3][lr] = b4.w;
        __syncthreads();
        #pragma unroll
        for (int kk = 0; kk < 8; kk++) {
            float4 a0 = *(const float4*)&As[kk][ty*8];
            float4 a1 = *(const float4*)&As[kk][ty*8+4];
            float4 b0 = *(const float4*)&Bs[kk][tx*8];
            float4 b1 = *(const float4*)&Bs[kk][tx*8+4];
            float av[8] = {a0.x,a0.y,a0.z,a0.w,a1.x,a1.y,a1.z,a1.w};
            float bv[8] = {b0.x,b0.y,b0.z,b0.w,b1.x,b1.y,b1.z,b1.w};
            #pragma unroll
            for (int i = 0; i < 8; i++)
                #pragma unroll
                for (int j = 0; j < 8; j++)
                    acc[i][j] += av[i]*bv[j];
        }
    }

    const int nb = bn + tx*8;
    if (nb + 7 < N) {
        #pragma unroll
        for (int i = 0; i < 8; i++) {
            int m = bm + ty*8 + i;
            float4 c0 = make_float4(acc[i][0], acc[i][1], acc[i][2], acc[i][3]);
            float4 c1 = make_float4(acc[i][4], acc[i][5], acc[i][6], acc[i][7]);
            *(float4*)(C + (size_t)m*N + nb)     = c0;
            *(float4*)(C + (size_t)m*N + nb + 4) = c1;
        }
    }
}

// ====================== top-K mask build (one block per (b,q)) ================
__device__ __forceinline__ unsigned ford(float f) {
    unsigned u = __float_as_uint(f);
    return (u & 0x80000000u) ? ~u : (u | 0x80000000u);
}

__global__ __launch_bounds__(256) void build_mask(
    const float* __restrict__ qrel, const float* __restrict__ krel,
    unsigned* __restrict__ mask)
{
    const int q = blockIdx.x;
    const int b = blockIdx.y;
    const int tid = threadIdx.x;

    __shared__ float    s[LL];
    __shared__ unsigned mw[LL/32];
    __shared__ float    qv[DREL];
    __shared__ int      hist[256];
    __shared__ unsigned sh_prefix;
    __shared__ int      sh_R;

    if (tid < DREL) qv[tid] = qrel[(size_t)(b*LL + q)*DREL + tid];
    if (tid < LL/32) mw[tid] = 0u;
    __syncthreads();

    const int n = q + 1;
    // rel scores for k in [0, q]
    for (int k = tid; k < n; k += 256) {
        const float4* kr = (const float4*)&krel[(size_t)(b*LL + k)*DREL];
        float acc = 0.f;
        #pragma unroll
        for (int j = 0; j < 16; j++) {
            float4 v = kr[j];
            acc += qv[j*4+0]*v.x + qv[j*4+1]*v.y + qv[j*4+2]*v.z + qv[j*4+3]*v.w;
        }
        s[k] = acc;
    }
    __syncthreads();

    if (n <= KSEL) {
        for (int k = tid; k < n; k += 256)
            atomicOr(&mw[k>>5], 1u << (k & 31));
    } else {
        // 4-pass MSB-first radix select of K-th largest ordered key
        unsigned prefix = 0u; int R = KSEL;
        for (int byte = 3; byte >= 0; byte--) {
            if (tid < 256) hist[tid] = 0;
            __syncthreads();
            const int shift = byte * 8;
            const unsigned pm = (byte == 3) ? 0u : (0xFFFFFFFFu << (shift + 8));
            for (int k = tid; k < n; k += 256) {
                unsigned u = ford(s[k]);
                if ((u & pm) == (prefix & pm))
                    atomicAdd(&hist[(u >> shift) & 255], 1);
            }
            __syncthreads();
            if (tid == 0) {
                int cum = 0;
                for (int bb2 = 255; bb2 >= 0; bb2--) {
                    int h2 = hist[bb2];
                    if (cum + h2 >= R) {
                        sh_prefix = prefix | ((unsigned)bb2 << shift);
                        sh_R = R - cum;
                        break;
                    }
                    cum += h2;
                }
            }
            __syncthreads();
            prefix = sh_prefix; R = sh_R;
            __syncthreads();
        }
        const unsigned T = prefix;
        for (int k = tid; k < n; k += 256)
            if (ford(s[k]) > T) atomicOr(&mw[k>>5], 1u << (k & 31));
        __syncthreads();
        if (tid == 0) {
            int r2 = R;
            for (int k = 0; k < n && r2 > 0; k++) {
                if (ford(s[k]) == T) { mw[k>>5] |= 1u << (k & 31); r2--; }
            }
        }
    }
    __syncthreads();
    if (tid == 0) mw[q>>5] |= 1u << (q & 31);   // diag always allowed
    __syncthreads();
    if (tid < LL/32) mask[(size_t)(b*LL + q)*(LL/32) + tid] = mw[tid];
}

// =========================== flash attention (fp32) ===========================
// Q tile 64 rows x 128d, K tile 64, online softmax, additive sparse+causal mask.
#define SQK 68    // Qst/Kst inner stride (64 rows + pad)
#define SV  132   // Vs inner stride (128 d + pad)
#define FLASH_FLOATS (128*SQK*2 + 64*SV + 64*SQK + 64*3 + 256)
#define FLASH_SMEM (FLASH_FLOATS*4 + 128*4)

__global__ __launch_bounds__(256) void flash_kernel(
    const float* __restrict__ Q, const float* __restrict__ Km,
    const float* __restrict__ Vm, const unsigned* __restrict__ mask,
    float* __restrict__ ctx)
{
    const int qt = blockIdx.x, h = blockIdx.y, b = blockIdx.z;
    const int q0 = qt * 64;
    const int tid = threadIdx.x;
    const int tx = tid & 15, ty = tid >> 4;

    extern __shared__ float sm[];
    float* Qst  = sm;                    // [128][SQK] transposed: [d][row]
    float* Kst  = Qst + 128*SQK;         // [128][SQK]
    float* Vs   = Kst + 128*SQK;         // [64][SV]  : [k][d]
    float* Ss   = Vs  + 64*SV;           // [64][SQK] : [q][k]
    float* m_s  = Ss  + 64*SQK;          // [64]
    float* l_s  = m_s + 64;              // [64]
    float* al_s = l_s + 64;              // [64]
    float* red  = al_s + 64;             // [64][4]
    unsigned* mwS = (unsigned*)(red + 256); // [64][2]

    // Load Q tile (transposed)
    const size_t baseQ = ((size_t)(b*LL + q0) * DD) + (size_t)h * DHD;
    for (int it = tid; it < 64*32; it += 256) {
        int r = it >> 5; int dj = (it & 31) << 2;
        float4 v = *(const float4*)(Q + baseQ + (size_t)r*DD + dj);
        Qst[(dj+0)*SQK + r] = v.x; Qst[(dj+1)*SQK + r] = v.y;
        Qst[(dj+2)*SQK + r] = v.z; Qst[(dj+3)*SQK + r] = v.w;
    }
    if (tid < 64) { m_s[tid] = -1e30f; l_s[tid] = 0.f; }

    float o[4][8];
    #pragma unroll
    for (int i = 0; i < 4; i++)
        #pragma unroll
        for (int j = 0; j < 8; j++) o[i][j] = 0.f;

    const float scale = 0.08838834764831845f;  // 1/sqrt(128)

    for (int kt = 0; kt <= qt; kt++) {
        const int k0 = kt * 64;
        __syncthreads();
        // load K (transposed) and V tiles
        const size_t baseK = ((size_t)(b*LL + k0) * DD) + (size_t)h * DHD;
        for (int it = tid; it < 64*32; it += 256) {
            int r = it >> 5; int dj = (it & 31) << 2;
            float4 kv = *(const float4*)(Km + baseK + (size_t)r*DD + dj);
            Kst[(dj+0)*SQK + r] = kv.x; Kst[(dj+1)*SQK + r] = kv.y;
            Kst[(dj+2)*SQK + r] = kv.z; Kst[(dj+3)*SQK + r] = kv.w;
            float4 vv = *(const float4*)(Vm + baseK + (size_t)r*DD + dj);
            *(float4*)&Vs[r*SV + dj] = vv;
        }
        if (tid < 128) {
            int r = tid >> 1, w = tid & 1;
            mwS[tid] = mask[(size_t)(b*LL + q0 + r)*(LL/32) + (k0 >> 5) + w];
        }
        __syncthreads();

        // S = Q*K^T
        float acc[4][4];
        #pragma unroll
        for (int i = 0; i < 4; i++)
            #pragma unroll
            for (int j = 0; j < 4; j++) acc[i][j] = 0.f;
        #pragma unroll 8
        for (int d = 0; d < 128; d++) {
            float4 a  = *(const float4*)&Qst[d*SQK + ty*4];
            float4 bq = *(const float4*)&Kst[d*SQK + tx*4];
            float av[4] = {a.x, a.y, a.z, a.w};
            float bv[4] = {bq.x, bq.y, bq.z, bq.w};
            #pragma unroll
            for (int i = 0; i < 4; i++)
                #pragma unroll
                for (int j = 0; j < 4; j++)
                    acc[i][j] += av[i]*bv[j];
        }
        // apply mask, write S
        #pragma unroll
        for (int i = 0; i < 4; i++) {
            int qr = ty*4 + i; int qg = q0 + qr;
            #pragma unroll
            for (int j = 0; j < 4; j++) {
                int kc = tx*4 + j; int kg = k0 + kc;
                unsigned w = mwS[qr*2 + (kc >> 5)];
                bool ok = (kg <= qg) && ((w >> (kc & 31)) & 1u);
                Ss[qr*SQK + kc] = ok ? acc[i][j]*scale : -1e30f;
            }
        }
        __syncthreads();
        // row max partials
        {
            int r = tid >> 2, c0 = (tid & 3) * 16;
            float mx = -1e30f;
            #pragma unroll
            for (int j = 0; j < 16; j++) mx = fmaxf(mx, Ss[r*SQK + c0 + j]);
            red[r*4 + (tid & 3)] = mx;
        }
        __syncthreads();
        if (tid < 64) {
            float mnew = fmaxf(fmaxf(red[tid*4], red[tid*4+1]),
                               fmaxf(red[tid*4+2], red[tid*4+3]));
            mnew = fmaxf(mnew, m_s[tid]);
            al_s[tid] = __expf(m_s[tid] - mnew);
            m_s[tid]  = mnew;
        }
        __syncthreads();
        // exp + row sum partials
        {
            int r = tid >> 2, c0 = (tid & 3) * 16;
            float mrow = m_s[r];
            float sum = 0.f;
            #pragma unroll
            for (int j = 0; j < 16; j++) {
                float sv = Ss[r*SQK + c0 + j];
                float p = (sv > -1e29f) ? __expf(sv - mrow) : 0.f;
                Ss[r*SQK + c0 + j] = p;
                sum += p;
            }
            red[r*4 + (tid & 3)] = sum;
        }
        __syncthreads();
        if (tid < 64) {
            float sum = red[tid*4] + red[tid*4+1] + red[tid*4+2] + red[tid*4+3];
            l_s[tid] = l_s[tid]*al_s[tid] + sum;
        }
        // rescale O accumulators
        #pragma unroll
        for (int i = 0; i < 4; i++) {
            float a = al_s[ty*4 + i];
            #pragma unroll
            for (int j = 0; j < 8; j++) o[i][j] *= a;
        }
        // O += P * V
        #pragma unroll 4
        for (int kc = 0; kc < 64; kc++) {
            float p0 = Ss[(ty*4+0)*SQK + kc];
            float p1 = Ss[(ty*4+1)*SQK + kc];
            float p2 = Ss[(ty*4+2)*SQK + kc];
            float p3 = Ss[(ty*4+3)*SQK + kc];
            float4 v0 = *(const float4*)&Vs[kc*SV + tx*8];
            float4 v1 = *(const float4*)&Vs[kc*SV + tx*8 + 4];
            float vv[8] = {v0.x,v0.y,v0.z,v0.w,v1.x,v1.y,v1.z,v1.w};
            float pp[4] = {p0,p1,p2,p3};
            #pragma unroll
            for (int i = 0; i < 4; i++)
                #pragma unroll
                for (int j = 0; j < 8; j++)
                    o[i][j] += pp[i]*vv[j];
        }
    }
    __syncthreads();
    // epilogue
    #pragma unroll
    for (int i = 0; i < 4; i++) {
        int qr = ty*4 + i;
        float inv = 1.f / l_s[qr];
        float4 r0 = make_float4(o[i][0]*inv, o[i][1]*inv, o[i][2]*inv, o[i][3]*inv);
        float4 r1 = make_float4(o[i][4]*inv, o[i][5]*inv, o[i][6]*inv, o[i][7]*inv);
        size_t off = ((size_t)(b*LL + q0 + qr)*DD) + (size_t)h*DHD + tx*8;
        *(float4*)(ctx + off)     = r0;
        *(float4*)(ctx + off + 4) = r1;
    }
}

// ================================ launch ======================================
extern "C" void kernel_launch(void* const* d_in, const int* in_sizes, int n_in,
                              void* d_out, int out_size)
{
    const float* hidden    = (const float*)d_in[0];
    const float* relevance = (const float*)d_in[1];
    const float* Wqr       = (const float*)d_in[2];
    const float* Wkr       = (const float*)d_in[3];
    const float* Wq        = (const float*)d_in[4];
    const float* Wk        = (const float*)d_in[5];
    const float* Wv        = (const float*)d_in[6];
    const float* Wo        = (const float*)d_in[7];
    float* out = (float*)d_out;

    float *q, *k, *v, *ctx, *qrel, *krel; unsigned* mask;
    cudaGetSymbolAddress((void**)&q,    g_q);
    cudaGetSymbolAddress((void**)&k,    g_k);
    cudaGetSymbolAddress((void**)&v,    g_v);
    cudaGetSymbolAddress((void**)&ctx,  g_ctx);
    cudaGetSymbolAddress((void**)&qrel, g_qrel);
    cudaGetSymbolAddress((void**)&krel, g_krel);
    cudaGetSymbolAddress((void**)&mask, g_mask);

    dim3 gProj(DD/128, MROWS/128);   // (16, 32)
    sgemm_nt<<<gProj, 256>>>(hidden, Wq, q, MROWS, DD, DD);
    sgemm_nt<<<gProj, 256>>>(hidden, Wk, k, MROWS, DD, DD);
    sgemm_nt<<<gProj, 256>>>(hidden, Wv, v, MROWS, DD, DD);

    dim3 gRel(1, MROWS/128);
    sgemm_nt<<<gRel, 256>>>(relevance, Wqr, qrel, MROWS, DREL, DD);
    sgemm_nt<<<gRel, 256>>>(relevance, Wkr, krel, MROWS, DREL, DD);

    build_mask<<<dim3(LL, BB), 256>>>(qrel, krel, mask);

    cudaFuncSetAttribute(flash_kernel,
                         cudaFuncAttributeMaxDynamicSharedMemorySize, FLASH_SMEM);
    flash_kernel<<<dim3(LL/64, HH, BB), 256, FLASH_SMEM>>>(q, k, v, mask, ctx);

    sgemm_nt<<<gProj, 256>>>(ctx, Wo, out, MROWS, DD, DD);
}

// round 3
// speedup vs baseline: 1.5900x; 1.5900x over previous
#include <cuda_runtime.h>
#include <cuda_fp16.h>
#include <cstdint>
#include <math.h>

// Problem constants
#define BB   2
#define LL   2048
#define DD   2048
#define HH   16
#define DHD  128
#define DREL 64
#define KSEL 512
#define MROWS (BB*LL)   // 4096

// -------------------- scratch (device globals; no cudaMalloc allowed) ---------
__device__ __align__(256) float    g_q   [BB*LL*DD];
__device__ __align__(256) float    g_k   [BB*LL*DD];
__device__ __align__(256) float    g_v   [BB*LL*DD];
__device__ __align__(256) float    g_ctx [BB*LL*DD];
__device__ __align__(256) float    g_qrel[BB*LL*DREL];
__device__ __align__(256) float    g_krel[BB*LL*DREL];
__device__ __align__(256) float    g_relp[4*MROWS*128];
__device__ __align__(256) unsigned g_mask[BB*LL*(LL/32)];

// ========================= inline PTX helpers =================================
__device__ __forceinline__ uint32_t smem_u32(const void* p) {
    uint32_t a;
    asm("{ .reg .u64 t; cvta.to.shared.u64 t, %1; cvt.u32.u64 %0, t; }" : "=r"(a) : "l"(p));
    return a;
}

__device__ __forceinline__ void ldsm4(uint32_t* r, uint32_t addr) {
    asm volatile("ldmatrix.sync.aligned.m8n8.x4.shared.b16 {%0,%1,%2,%3}, [%4];"
        : "=r"(r[0]), "=r"(r[1]), "=r"(r[2]), "=r"(r[3]) : "r"(addr));
}

__device__ __forceinline__ void mma16816(float* c, const uint32_t* a, const uint32_t* b) {
    asm volatile("mma.sync.aligned.m16n8k16.row.col.f32.f16.f16.f32 "
        "{%0,%1,%2,%3}, {%4,%5,%6,%7}, {%8,%9}, {%0,%1,%2,%3};"
        : "+f"(c[0]), "+f"(c[1]), "+f"(c[2]), "+f"(c[3])
        : "r"(a[0]), "r"(a[1]), "r"(a[2]), "r"(a[3]), "r"(b[0]), "r"(b[1]));
}

// ============== fp16-split GEMM: C[4096,2048] = A[4096,2048] · B[2048,2048]^T ==
// CTA tile 128x128, K-chunk 32 (fp32). Split x = hi + lo (fp16), compute
// C = Ah·Bh + Al·Bh + Ah·Bl (error ~2^-22). Smem: 4 segments (Ah,Al,Bh,Bl),
// each [128][40] halves (stride 80B -> conflict-free ldmatrix).
#define SEG_HALVES (128*40)
#define SEG_BYTES  (SEG_HALVES*2)

__device__ __forceinline__ void cvt_store16(__half* hiP, __half* loP, const float* f) {
    uint32_t hi[8], lo[8];
    #pragma unroll
    for (int i = 0; i < 8; i++) {
        __half h0 = __float2half_rn(f[2*i]);
        __half h1 = __float2half_rn(f[2*i+1]);
        __half l0 = __float2half_rn(f[2*i]   - __half2float(h0));
        __half l1 = __float2half_rn(f[2*i+1] - __half2float(h1));
        hi[i] = ((uint32_t)__half_as_ushort(h1) << 16) | __half_as_ushort(h0);
        lo[i] = ((uint32_t)__half_as_ushort(l1) << 16) | __half_as_ushort(l0);
    }
    *(uint4*)hiP       = make_uint4(hi[0], hi[1], hi[2], hi[3]);
    *(uint4*)(hiP + 8) = make_uint4(hi[4], hi[5], hi[6], hi[7]);
    *(uint4*)loP       = make_uint4(lo[0], lo[1], lo[2], lo[3]);
    *(uint4*)(loP + 8) = make_uint4(lo[4], lo[5], lo[6], lo[7]);
}

__global__ __launch_bounds__(256) void gemm_mma(
    const float* __restrict__ A, const float* __restrict__ B, float* __restrict__ C)
{
    __shared__ __half S[4 * SEG_HALVES];   // 0=Ah 1=Al 2=Bh 3=Bl

    const int tid = threadIdx.x;
    const int l   = tid & 31;
    const int wid = tid >> 5;
    const int wm  = wid >> 2;       // 0..1
    const int wn  = wid & 3;        // 0..3
    const int bm  = blockIdx.y * 128;
    const int bn  = blockIdx.x * 128;

    // global load mapping: 2 threads per row, 16 floats each
    const int row = tid >> 1;                 // 0..127
    const int cb  = (tid & 1) * 16;           // 0 or 16
    const float4* Ap = (const float4*)(A + (size_t)(bm + row) * DD) + (cb >> 2);
    const float4* Bp = (const float4*)(B + (size_t)(bn + row) * DD) + (cb >> 2);

    const uint32_t base = smem_u32(S);

    // ldmatrix lane offsets
    const int rA = wm * 64 + ((l >> 3) & 1) * 8 + (l & 7);
    const int kA = (l >> 4) * 16;                       // bytes
    const int rB = wn * 32 + ((l >> 4) & 1) * 8 + (l & 7);
    const int kB = ((l >> 3) & 1) * 16;                 // bytes

    float acc[4][4][4];
    #pragma unroll
    for (int i = 0; i < 4; i++)
        #pragma unroll
        for (int j = 0; j < 4; j++)
            #pragma unroll
            for (int t = 0; t < 4; t++) acc[i][j][t] = 0.f;

    // prefetch chunk 0
    float4 av[4], bv[4];
    #pragma unroll
    for (int j = 0; j < 4; j++) { av[j] = Ap[j]; bv[j] = Bp[j]; }

    for (int c = 0; c < DD / 32; c++) {
        float cav[16], cbv[16];
        #pragma unroll
        for (int j = 0; j < 4; j++) {
            ((float4*)cav)[j] = av[j];
            ((float4*)cbv)[j] = bv[j];
        }
        if (c + 1 < DD / 32) {
            const int o = (c + 1) * 8;
            #pragma unroll
            for (int j = 0; j < 4; j++) { av[j] = Ap[o + j]; bv[j] = Bp[o + j]; }
        }
        __syncthreads();   // previous compute done; safe to overwrite smem
        {
            __half* aH = S + 0 * SEG_HALVES + row * 40 + cb;
            __half* aL = S + 1 * SEG_HALVES + row * 40 + cb;
            __half* bH = S + 2 * SEG_HALVES + row * 40 + cb;
            __half* bL = S + 3 * SEG_HALVES + row * 40 + cb;
            cvt_store16(aH, aL, cav);
            cvt_store16(bH, bL, cbv);
        }
        __syncthreads();

        // 3 passes: (Ah,Bh), (Al,Bh), (Ah,Bl)
        #pragma unroll
        for (int p = 0; p < 3; p++) {
            const uint32_t aSegBase = base + ((p == 1) ? 1u : 0u) * SEG_BYTES;
            const uint32_t bSegBase = base + ((p == 2) ? 3u : 2u) * SEG_BYTES;
            #pragma unroll
            for (int ks = 0; ks < 2; ks++) {
                uint32_t afr[4][4];
                #pragma unroll
                for (int mf = 0; mf < 4; mf++)
                    ldsm4(afr[mf], aSegBase + (uint32_t)(rA + mf*16) * 80u + kA + ks*32);
                uint32_t bw0[4], bw1[4];
                ldsm4(bw0, bSegBase + (uint32_t)(rB)      * 80u + kB + ks*32);
                ldsm4(bw1, bSegBase + (uint32_t)(rB + 16) * 80u + kB + ks*32);
                uint32_t bfr[4][2] = {
                    {bw0[0], bw0[1]}, {bw0[2], bw0[3]},
                    {bw1[0], bw1[1]}, {bw1[2], bw1[3]}
                };
                #pragma unroll
                for (int mf = 0; mf < 4; mf++)
                    #pragma unroll
                    for (int nf = 0; nf < 4; nf++)
                        mma16816(acc[mf][nf], afr[mf], bfr[nf]);
            }
        }
    }

    // epilogue
    const int gid = l >> 2, tig = l & 3;
    #pragma unroll
    for (int mf = 0; mf < 4; mf++) {
        #pragma unroll
        for (int nf = 0; nf < 4; nf++) {
            int r0 = bm + wm*64 + mf*16 + gid;
            int cc = bn + wn*32 + nf*8 + tig*2;
            *(float2*)(C + (size_t)r0 * DD + cc)       = make_float2(acc[mf][nf][0], acc[mf][nf][1]);
            *(float2*)(C + (size_t)(r0 + 8) * DD + cc) = make_float2(acc[mf][nf][2], acc[mf][nf][3]);
        }
    }
}

// ===================== rel projection (split-K, fused q/k) ====================
__global__ __launch_bounds__(256) void rel_proj(
    const float* __restrict__ A, const float* __restrict__ Wq,
    const float* __restrict__ Wk, float* __restrict__ part)
{
    __shared__ __align__(16) float As[32][65];
    __shared__ __align__(16) float Ws[32][132];
    const int tid = threadIdx.x;
    const int m0 = blockIdx.x * 64;
    const int kb = blockIdx.y * 512;
    const int r0 = (tid >> 5) * 8;
    const int c0 = (tid & 31) * 4;

    float acc[8][4];
    #pragma unroll
    for (int i = 0; i < 8; i++)
        #pragma unroll
        for (int j = 0; j < 4; j++) acc[i][j] = 0.f;

    for (int k0 = 0; k0 < 512; k0 += 32) {
        #pragma unroll
        for (int t = 0; t < 2; t++) {
            int idx = tid + t * 256;
            int row = idx >> 3, gg = idx & 7;
            float4 v = *(const float4*)(A + (size_t)(m0 + row) * DD + kb + k0 + gg * 4);
            As[gg*4+0][row] = v.x; As[gg*4+1][row] = v.y;
            As[gg*4+2][row] = v.z; As[gg*4+3][row] = v.w;
        }
        #pragma unroll
        for (int t = 0; t < 4; t++) {
            int idx = tid + t * 256;
            int col = idx >> 3, gg = idx & 7;
            const float* src = (col < 64) ? (Wq + (size_t)col * DD)
                                          : (Wk + (size_t)(col - 64) * DD);
            float4 v = *(const float4*)(src + kb + k0 + gg * 4);
            Ws[gg*4+0][col] = v.x; Ws[gg*4+1][col] = v.y;
            Ws[gg*4+2][col] = v.z; Ws[gg*4+3][col] = v.w;
        }
        __syncthreads();
        #pragma unroll 8
        for (int kk = 0; kk < 32; kk++) {
            float4 w = *(const float4*)&Ws[kk][c0];
            #pragma unroll
            for (int i = 0; i < 8; i++) {
                float a = As[kk][r0 + i];
                acc[i][0] += a * w.x; acc[i][1] += a * w.y;
                acc[i][2] += a * w.z; acc[i][3] += a * w.w;
            }
        }
        __syncthreads();
    }
    float* dst = part + (size_t)blockIdx.y * MROWS * 128;
    #pragma unroll
    for (int i = 0; i < 8; i++) {
        float4 o = make_float4(acc[i][0], acc[i][1], acc[i][2], acc[i][3]);
        *(float4*)(dst + (size_t)(m0 + r0 + i) * 128 + c0) = o;
    }
}

__global__ __launch_bounds__(256) void rel_reduce(
    const float* __restrict__ part, float* __restrict__ qrel, float* __restrict__ krel)
{
    int idx = blockIdx.x * 256 + threadIdx.x;   // 4096*64
    int row = idx >> 6, col = idx & 63;
    float sq = 0.f, sk = 0.f;
    #pragma unroll
    for (int s = 0; s < 4; s++) {
        const float* p = part + (size_t)s * MROWS * 128 + (size_t)row * 128;
        sq += p[col]; sk += p[col + 64];
    }
    qrel[(size_t)row * 64 + col] = sq;
    krel[(size_t)row * 64 + col] = sk;
}

// ====================== top-K mask build (one block per (b,q)) ================
__device__ __forceinline__ unsigned ford(float f) {
    unsigned u = __float_as_uint(f);
    return (u & 0x80000000u) ? ~u : (u | 0x80000000u);
}

__global__ __launch_bounds__(256) void build_mask(
    const float* __restrict__ qrel, const float* __restrict__ krel,
    unsigned* __restrict__ mask)
{
    const int q = blockIdx.x;
    const int b = blockIdx.y;
    const int tid = threadIdx.x;

    __shared__ float    s[LL];
    __shared__ unsigned mw[LL/32];
    __shared__ float    qv[DREL];
    __shared__ int      hist[256];
    __shared__ unsigned sh_prefix;
    __shared__ int      sh_R;

    if (tid < DREL) qv[tid] = qrel[(size_t)(b*LL + q)*DREL + tid];
    if (tid < LL/32) mw[tid] = 0u;
    __syncthreads();

    const int n = q + 1;
    for (int k = tid; k < n; k += 256) {
        const float4* kr = (const float4*)&krel[(size_t)(b*LL + k)*DREL];
        float acc = 0.f;
        #pragma unroll
        for (int j = 0; j < 16; j++) {
            float4 v = kr[j];
            acc += qv[j*4+0]*v.x + qv[j*4+1]*v.y + qv[j*4+2]*v.z + qv[j*4+3]*v.w;
        }
        s[k] = acc;
    }
    __syncthreads();

    if (n <= KSEL) {
        for (int k = tid; k < n; k += 256)
            atomicOr(&mw[k>>5], 1u << (k & 31));
    } else {
        unsigned prefix = 0u; int R = KSEL;
        for (int byte = 3; byte >= 0; byte--) {
            if (tid < 256) hist[tid] = 0;
            __syncthreads();
            const int shift = byte * 8;
            const unsigned pm = (byte == 3) ? 0u : (0xFFFFFFFFu << (shift + 8));
            for (int k = tid; k < n; k += 256) {
                unsigned u = ford(s[k]);
                if ((u & pm) == (prefix & pm))
                    atomicAdd(&hist[(u >> shift) & 255], 1);
            }
            __syncthreads();
            if (tid == 0) {
                int cum = 0;
                for (int bb2 = 255; bb2 >= 0; bb2--) {
                    int h2 = hist[bb2];
                    if (cum + h2 >= R) {
                        sh_prefix = prefix | ((unsigned)bb2 << shift);
                        sh_R = R - cum;
                        break;
                    }
                    cum += h2;
                }
            }
            __syncthreads();
            prefix = sh_prefix; R = sh_R;
            __syncthreads();
        }
        const unsigned T = prefix;
        for (int k = tid; k < n; k += 256)
            if (ford(s[k]) > T) atomicOr(&mw[k>>5], 1u << (k & 31));
        __syncthreads();
        if (tid == 0) {
            int r2 = R;
            for (int k = 0; k < n && r2 > 0; k++) {
                if (ford(s[k]) == T) { mw[k>>5] |= 1u << (k & 31); r2--; }
            }
        }
    }
    __syncthreads();
    if (tid == 0) mw[q>>5] |= 1u << (q & 31);
    __syncthreads();
    if (tid < LL/32) mask[(size_t)(b*LL + q)*(LL/32) + tid] = mw[tid];
}

// =========================== flash attention (fp32) ===========================
#define SQK 68
#define SV  132
#define FLASH_FLOATS (128*SQK*2 + 64*SV + 64*SQK + 64*3 + 256)
#define FLASH_SMEM (FLASH_FLOATS*4 + 128*4)

__global__ __launch_bounds__(256) void flash_kernel(
    const float* __restrict__ Q, const float* __restrict__ Km,
    const float* __restrict__ Vm, const unsigned* __restrict__ mask,
    float* __restrict__ ctx)
{
    const int qt = blockIdx.x, h = blockIdx.y, b = blockIdx.z;
    const int q0 = qt * 64;
    const int tid = threadIdx.x;
    const int tx = tid & 15, ty = tid >> 4;

    extern __shared__ float sm[];
    float* Qst  = sm;
    float* Kst  = Qst + 128*SQK;
    float* Vs   = Kst + 128*SQK;
    float* Ss   = Vs  + 64*SV;
    float* m_s  = Ss  + 64*SQK;
    float* l_s  = m_s + 64;
    float* al_s = l_s + 64;
    float* red  = al_s + 64;
    unsigned* mwS = (unsigned*)(red + 256);

    const size_t baseQ = ((size_t)(b*LL + q0) * DD) + (size_t)h * DHD;
    for (int it = tid; it < 64*32; it += 256) {
        int r = it >> 5; int dj = (it & 31) << 2;
        float4 v = *(const float4*)(Q + baseQ + (size_t)r*DD + dj);
        Qst[(dj+0)*SQK + r] = v.x; Qst[(dj+1)*SQK + r] = v.y;
        Qst[(dj+2)*SQK + r] = v.z; Qst[(dj+3)*SQK + r] = v.w;
    }
    if (tid < 64) { m_s[tid] = -1e30f; l_s[tid] = 0.f; }

    float o[4][8];
    #pragma unroll
    for (int i = 0; i < 4; i++)
        #pragma unroll
        for (int j = 0; j < 8; j++) o[i][j] = 0.f;

    const float scale = 0.08838834764831845f;

    for (int kt = 0; kt <= qt; kt++) {
        const int k0 = kt * 64;
        __syncthreads();
        const size_t baseK = ((size_t)(b*LL + k0) * DD) + (size_t)h * DHD;
        for (int it = tid; it < 64*32; it += 256) {
            int r = it >> 5; int dj = (it & 31) << 2;
            float4 kv = *(const float4*)(Km + baseK + (size_t)r*DD + dj);
            Kst[(dj+0)*SQK + r] = kv.x; Kst[(dj+1)*SQK + r] = kv.y;
            Kst[(dj+2)*SQK + r] = kv.z; Kst[(dj+3)*SQK + r] = kv.w;
            float4 vv = *(const float4*)(Vm + baseK + (size_t)r*DD + dj);
            *(float4*)&Vs[r*SV + dj] = vv;
        }
        if (tid < 128) {
            int r = tid >> 1, w = tid & 1;
            mwS[tid] = mask[(size_t)(b*LL + q0 + r)*(LL/32) + (k0 >> 5) + w];
        }
        __syncthreads();

        float acc[4][4];
        #pragma unroll
        for (int i = 0; i < 4; i++)
            #pragma unroll
            for (int j = 0; j < 4; j++) acc[i][j] = 0.f;
        #pragma unroll 8
        for (int d = 0; d < 128; d++) {
            float4 a  = *(const float4*)&Qst[d*SQK + ty*4];
            float4 bq = *(const float4*)&Kst[d*SQK + tx*4];
            float av[4] = {a.x, a.y, a.z, a.w};
            float bv[4] = {bq.x, bq.y, bq.z, bq.w};
            #pragma unroll
            for (int i = 0; i < 4; i++)
                #pragma unroll
                for (int j = 0; j < 4; j++)
                    acc[i][j] += av[i]*bv[j];
        }
        #pragma unroll
        for (int i = 0; i < 4; i++) {
            int qr = ty*4 + i; int qg = q0 + qr;
            #pragma unroll
            for (int j = 0; j < 4; j++) {
                int kc = tx*4 + j; int kg = k0 + kc;
                unsigned w = mwS[qr*2 + (kc >> 5)];
                bool ok = (kg <= qg) && ((w >> (kc & 31)) & 1u);
                Ss[qr*SQK + kc] = ok ? acc[i][j]*scale : -1e30f;
            }
        }
        __syncthreads();
        {
            int r = tid >> 2, c0 = (tid & 3) * 16;
            float mx = -1e30f;
            #pragma unroll
            for (int j = 0; j < 16; j++) mx = fmaxf(mx, Ss[r*SQK + c0 + j]);
            red[r*4 + (tid & 3)] = mx;
        }
        __syncthreads();
        if (tid < 64) {
            float mnew = fmaxf(fmaxf(red[tid*4], red[tid*4+1]),
                               fmaxf(red[tid*4+2], red[tid*4+3]));
            mnew = fmaxf(mnew, m_s[tid]);
            al_s[tid] = __expf(m_s[tid] - mnew);
            m_s[tid]  = mnew;
        }
        __syncthreads();
        {
            int r = tid >> 2, c0 = (tid & 3) * 16;
            float mrow = m_s[r];
            float sum = 0.f;
            #pragma unroll
            for (int j = 0; j < 16; j++) {
                float sv = Ss[r*SQK + c0 + j];
                float p = (sv > -1e29f) ? __expf(sv - mrow) : 0.f;
                Ss[r*SQK + c0 + j] = p;
                sum += p;
            }
            red[r*4 + (tid & 3)] = sum;
        }
        __syncthreads();
        if (tid < 64) {
            float sum = red[tid*4] + red[tid*4+1] + red[tid*4+2] + red[tid*4+3];
            l_s[tid] = l_s[tid]*al_s[tid] + sum;
        }
        #pragma unroll
        for (int i = 0; i < 4; i++) {
            float a = al_s[ty*4 + i];
            #pragma unroll
            for (int j = 0; j < 8; j++) o[i][j] *= a;
        }
        #pragma unroll 4
        for (int kc = 0; kc < 64; kc++) {
            float p0 = Ss[(ty*4+0)*SQK + kc];
            float p1 = Ss[(ty*4+1)*SQK + kc];
            float p2 = Ss[(ty*4+2)*SQK + kc];
            float p3 = Ss[(ty*4+3)*SQK + kc];
            float4 v0 = *(const float4*)&Vs[kc*SV + tx*8];
            float4 v1 = *(const float4*)&Vs[kc*SV + tx*8 + 4];
            float vv[8] = {v0.x,v0.y,v0.z,v0.w,v1.x,v1.y,v1.z,v1.w};
            float pp[4] = {p0,p1,p2,p3};
            #pragma unroll
            for (int i = 0; i < 4; i++)
                #pragma unroll
                for (int j = 0; j < 8; j++)
                    o[i][j] += pp[i]*vv[j];
        }
    }
    __syncthreads();
    #pragma unroll
    for (int i = 0; i < 4; i++) {
        int qr = ty*4 + i;
        float inv = 1.f / l_s[qr];
        float4 r0 = make_float4(o[i][0]*inv, o[i][1]*inv, o[i][2]*inv, o[i][3]*inv);
        float4 r1 = make_float4(o[i][4]*inv, o[i][5]*inv, o[i][6]*inv, o[i][7]*inv);
        size_t off = ((size_t)(b*LL + q0 + qr)*DD) + (size_t)h*DHD + tx*8;
        *(float4*)(ctx + off)     = r0;
        *(float4*)(ctx + off + 4) = r1;
    }
}

// ================================ launch ======================================
extern "C" void kernel_launch(void* const* d_in, const int* in_sizes, int n_in,
                              void* d_out, int out_size)
{
    const float* hidden    = (const float*)d_in[0];
    const float* relevance = (const float*)d_in[1];
    const float* Wqr       = (const float*)d_in[2];
    const float* Wkr       = (const float*)d_in[3];
    const float* Wq        = (const float*)d_in[4];
    const float* Wk        = (const float*)d_in[5];
    const float* Wv        = (const float*)d_in[6];
    const float* Wo        = (const float*)d_in[7];
    float* out = (float*)d_out;

    float *q, *k, *v, *ctx, *qrel, *krel, *relp; unsigned* mask;
    cudaGetSymbolAddress((void**)&q,    g_q);
    cudaGetSymbolAddress((void**)&k,    g_k);
    cudaGetSymbolAddress((void**)&v,    g_v);
    cudaGetSymbolAddress((void**)&ctx,  g_ctx);
    cudaGetSymbolAddress((void**)&qrel, g_qrel);
    cudaGetSymbolAddress((void**)&krel, g_krel);
    cudaGetSymbolAddress((void**)&relp, g_relp);
    cudaGetSymbolAddress((void**)&mask, g_mask);

    cudaFuncSetAttribute(flash_kernel,
                         cudaFuncAttributeMaxDynamicSharedMemorySize, FLASH_SMEM);

    dim3 gG(DD/128, MROWS/128);   // (16, 32)

    // relevance path first (independent)
    rel_proj<<<dim3(MROWS/64, 4), 256>>>(relevance, Wqr, Wkr, relp);
    rel_reduce<<<(MROWS*64)/256, 256>>>(relp, qrel, krel);
    build_mask<<<dim3(LL, BB), 256>>>(qrel, krel, mask);

    gemm_mma<<<gG, 256>>>(hidden, Wq, q);
    gemm_mma<<<gG, 256>>>(hidden, Wk, k);
    gemm_mma<<<gG, 256>>>(hidden, Wv, v);

    flash_kernel<<<dim3(LL/64, HH, BB), 256, FLASH_SMEM>>>(q, k, v, mask, ctx);

    gemm_mma<<<gG, 256>>>(ctx, Wo, out);
}

// round 4
// speedup vs baseline: 2.7204x; 1.7109x over previous
#include <cuda_runtime.h>
#include <cuda_fp16.h>
#include <cstdint>
#include <math.h>

// Problem constants
#define BB   2
#define LL   2048
#define DD   2048
#define HH   16
#define DHD  128
#define DREL 64
#define KSEL 512
#define MROWS (BB*LL)   // 4096

// -------------------- scratch (device globals; no cudaMalloc allowed) ---------
__device__ __align__(256) __half g_hidh[MROWS*DD];
__device__ __align__(256) __half g_hidl[MROWS*DD];
__device__ __align__(256) __half g_wqh [DD*DD];
__device__ __align__(256) __half g_wql [DD*DD];
__device__ __align__(256) __half g_wkh [DD*DD];
__device__ __align__(256) __half g_wkl [DD*DD];
__device__ __align__(256) __half g_wvh [DD*DD];
__device__ __align__(256) __half g_wvl [DD*DD];
__device__ __align__(256) __half g_woh [DD*DD];
__device__ __align__(256) __half g_wol [DD*DD];
__device__ __align__(256) __half g_qh  [MROWS*DD];
__device__ __align__(256) __half g_ql  [MROWS*DD];
__device__ __align__(256) __half g_kh  [MROWS*DD];
__device__ __align__(256) __half g_kl  [MROWS*DD];
__device__ __align__(256) __half g_vh  [MROWS*DD];
__device__ __align__(256) __half g_vl  [MROWS*DD];
__device__ __align__(256) __half g_ctxh[MROWS*DD];
__device__ __align__(256) __half g_ctxl[MROWS*DD];
__device__ __align__(256) float    g_qrel[BB*LL*DREL];
__device__ __align__(256) float    g_krel[BB*LL*DREL];
__device__ __align__(256) float    g_relp[4*MROWS*128];
__device__ __align__(256) unsigned g_mask[BB*LL*(LL/32)];

// ========================= inline PTX helpers =================================
__device__ __forceinline__ uint32_t smem_u32(const void* p) {
    uint32_t a;
    asm("{ .reg .u64 t; cvta.to.shared.u64 t, %1; cvt.u32.u64 %0, t; }" : "=r"(a) : "l"(p));
    return a;
}
__device__ __forceinline__ void ldsm4(uint32_t* r, uint32_t addr) {
    asm volatile("ldmatrix.sync.aligned.m8n8.x4.shared.b16 {%0,%1,%2,%3}, [%4];"
        : "=r"(r[0]), "=r"(r[1]), "=r"(r[2]), "=r"(r[3]) : "r"(addr));
}
__device__ __forceinline__ void ldsm4t(uint32_t* r, uint32_t addr) {
    asm volatile("ldmatrix.sync.aligned.m8n8.x4.trans.shared.b16 {%0,%1,%2,%3}, [%4];"
        : "=r"(r[0]), "=r"(r[1]), "=r"(r[2]), "=r"(r[3]) : "r"(addr));
}
__device__ __forceinline__ void mma16816(float* c, const uint32_t* a, const uint32_t* b) {
    asm volatile("mma.sync.aligned.m16n8k16.row.col.f32.f16.f16.f32 "
        "{%0,%1,%2,%3}, {%4,%5,%6,%7}, {%8,%9}, {%0,%1,%2,%3};"
        : "+f"(c[0]), "+f"(c[1]), "+f"(c[2]), "+f"(c[3])
        : "r"(a[0]), "r"(a[1]), "r"(a[2]), "r"(a[3]), "r"(b[0]), "r"(b[1]));
}
#define CP_ASYNC16(dst, src) \
    asm volatile("cp.async.cg.shared.global [%0], [%1], 16;" :: "r"(dst), "l"(src) : "memory")
#define CP_COMMIT() asm volatile("cp.async.commit_group;" ::: "memory")
#define CP_WAIT(n)  asm volatile("cp.async.wait_group %0;" :: "n"(n) : "memory")

__device__ __forceinline__ float ex2f(float x) {
    float y; asm("ex2.approx.f32 %0, %1;" : "=f"(y) : "f"(x)); return y;
}
__device__ __forceinline__ void split2(float x, float y, uint32_t& hi, uint32_t& lo) {
    __half hx = __float2half_rn(x), hy = __float2half_rn(y);
    __half lx = __float2half_rn(x - __half2float(hx));
    __half ly = __float2half_rn(y - __half2float(hy));
    hi = ((uint32_t)__half_as_ushort(hy) << 16) | __half_as_ushort(hx);
    lo = ((uint32_t)__half_as_ushort(ly) << 16) | __half_as_ushort(lx);
}

// =========================== fp32 -> hi/lo fp16 split =========================
__global__ __launch_bounds__(256) void cvt_split(
    const float4* __restrict__ x, uint2* __restrict__ h, uint2* __restrict__ lo, int n4)
{
    int i = blockIdx.x * 256 + threadIdx.x;
    if (i >= n4) return;
    float4 v = x[i];
    uint32_t h0, l0, h1, l1;
    split2(v.x, v.y, h0, l0);
    split2(v.z, v.w, h1, l1);
    h[i]  = make_uint2(h0, h1);
    lo[i] = make_uint2(l0, l1);
}

// ============== fp16-split GEMM: C[4096,2048] = A · B^T (hi/lo inputs) ========
// CTA 128x128, k-chunk 32, 3-stage cp.async pipeline.
#define SEGH 5120               // halves per segment (128 rows x 40)
#define SEGB 10240              // bytes
#define GSMEM (3*4*SEGB)        // 122880 B

template<int OUTF32>
__global__ __launch_bounds__(256) void gemm_h(
    const __half* __restrict__ Ah, const __half* __restrict__ Al,
    const __half* __restrict__ Bh, const __half* __restrict__ Bl,
    float* __restrict__ Cf, __half* __restrict__ Ch, __half* __restrict__ Cl)
{
    extern __shared__ __half GS[];
    const uint32_t base = smem_u32(GS);
    const int tid = threadIdx.x;
    const int l   = tid & 31;
    const int wid = tid >> 5;
    const int wm  = wid >> 2;
    const int wn  = wid & 3;
    const int bm  = blockIdx.y * 128;
    const int bn  = blockIdx.x * 128;

    // cp.async mapping: which segment (Ah,Al,Bh,Bl) by tid>>6
    const int which = tid >> 6;
    const int cid0  = tid & 63;
    const __half* srcs[4] = {Ah, Al, Bh, Bl};
    const __half* srcBase = srcs[which] + (size_t)((which < 2 ? bm : bn)) * DD;

    // ldmatrix lane offsets (byte units; smem row stride 80B)
    const int rA = wm * 64 + ((l >> 3) & 1) * 8 + (l & 7);
    const int kA = (l >> 4) * 16;
    const int rB = wn * 32 + ((l >> 4) & 1) * 8 + (l & 7);
    const int kB = ((l >> 3) & 1) * 16;

    float acc[4][4][4];
    #pragma unroll
    for (int i = 0; i < 4; i++)
        #pragma unroll
        for (int j = 0; j < 4; j++)
            #pragma unroll
            for (int t = 0; t < 4; t++) acc[i][j][t] = 0.f;

    auto issue_stage = [&](int c, int st) {
        #pragma unroll
        for (int j = 0; j < 8; j++) {
            int cid = cid0 + j * 64;
            int row = cid >> 2, c16 = cid & 3;
            uint32_t dst = base + (uint32_t)(st * 4 + which) * SEGB + (uint32_t)row * 80 + c16 * 16;
            const __half* src = srcBase + (size_t)row * DD + c * 32 + c16 * 8;
            CP_ASYNC16(dst, src);
        }
        CP_COMMIT();
    };

    issue_stage(0, 0);
    issue_stage(1, 1);

    for (int c = 0; c < DD / 32; c++) {
        CP_WAIT(1);
        __syncthreads();
        if (c + 2 < DD / 32) issue_stage(c + 2, (c + 2) % 3);
        else CP_COMMIT();

        const int st = c % 3;
        const uint32_t sAh = base + (uint32_t)(st * 4 + 0) * SEGB;
        const uint32_t sAl = base + (uint32_t)(st * 4 + 1) * SEGB;
        const uint32_t sBh = base + (uint32_t)(st * 4 + 2) * SEGB;
        const uint32_t sBl = base + (uint32_t)(st * 4 + 3) * SEGB;

        #pragma unroll
        for (int ks = 0; ks < 2; ks++) {
            uint32_t aH[4][4], aL[4][4];
            #pragma unroll
            for (int mf = 0; mf < 4; mf++) {
                ldsm4(aH[mf], sAh + (uint32_t)(rA + mf*16) * 80 + kA + ks*32);
                ldsm4(aL[mf], sAl + (uint32_t)(rA + mf*16) * 80 + kA + ks*32);
            }
            #pragma unroll
            for (int nf2 = 0; nf2 < 2; nf2++) {
                uint32_t bH[4], bL[4];
                ldsm4(bH, sBh + (uint32_t)(rB + nf2*16) * 80 + kB + ks*32);
                #pragma unroll
                for (int mf = 0; mf < 4; mf++) {
                    mma16816(acc[mf][2*nf2],   aH[mf], bH + 0);
                    mma16816(acc[mf][2*nf2+1], aH[mf], bH + 2);
                    mma16816(acc[mf][2*nf2],   aL[mf], bH + 0);
                    mma16816(acc[mf][2*nf2+1], aL[mf], bH + 2);
                }
                ldsm4(bL, sBl + (uint32_t)(rB + nf2*16) * 80 + kB + ks*32);
                #pragma unroll
                for (int mf = 0; mf < 4; mf++) {
                    mma16816(acc[mf][2*nf2],   aH[mf], bL + 0);
                    mma16816(acc[mf][2*nf2+1], aH[mf], bL + 2);
                }
            }
        }
    }

    // epilogue
    const int gid = l >> 2, tig = l & 3;
    #pragma unroll
    for (int mf = 0; mf < 4; mf++) {
        #pragma unroll
        for (int nf = 0; nf < 4; nf++) {
            int r0 = bm + wm*64 + mf*16 + gid;
            int cc = bn + wn*32 + nf*8 + tig*2;
            if (OUTF32) {
                *(float2*)(Cf + (size_t)r0 * DD + cc)       = make_float2(acc[mf][nf][0], acc[mf][nf][1]);
                *(float2*)(Cf + (size_t)(r0 + 8) * DD + cc) = make_float2(acc[mf][nf][2], acc[mf][nf][3]);
            } else {
                uint32_t h0, l0v, h1, l1v;
                split2(acc[mf][nf][0], acc[mf][nf][1], h0, l0v);
                split2(acc[mf][nf][2], acc[mf][nf][3], h1, l1v);
                *(uint32_t*)(Ch + (size_t)r0 * DD + cc)       = h0;
                *(uint32_t*)(Cl + (size_t)r0 * DD + cc)       = l0v;
                *(uint32_t*)(Ch + (size_t)(r0 + 8) * DD + cc) = h1;
                *(uint32_t*)(Cl + (size_t)(r0 + 8) * DD + cc) = l1v;
            }
        }
    }
}

// ===================== rel projection (split-K, fused q/k) ====================
__global__ __launch_bounds__(256) void rel_proj(
    const float* __restrict__ A, const float* __restrict__ Wq,
    const float* __restrict__ Wk, float* __restrict__ part)
{
    __shared__ __align__(16) float As[32][65];
    __shared__ __align__(16) float Ws[32][132];
    const int tid = threadIdx.x;
    const int m0 = blockIdx.x * 64;
    const int kb = blockIdx.y * 512;
    const int r0 = (tid >> 5) * 8;
    const int c0 = (tid & 31) * 4;

    float acc[8][4];
    #pragma unroll
    for (int i = 0; i < 8; i++)
        #pragma unroll
        for (int j = 0; j < 4; j++) acc[i][j] = 0.f;

    for (int k0 = 0; k0 < 512; k0 += 32) {
        #pragma unroll
        for (int t = 0; t < 2; t++) {
            int idx = tid + t * 256;
            int row = idx >> 3, gg = idx & 7;
            float4 v = *(const float4*)(A + (size_t)(m0 + row) * DD + kb + k0 + gg * 4);
            As[gg*4+0][row] = v.x; As[gg*4+1][row] = v.y;
            As[gg*4+2][row] = v.z; As[gg*4+3][row] = v.w;
        }
        #pragma unroll
        for (int t = 0; t < 4; t++) {
            int idx = tid + t * 256;
            int col = idx >> 3, gg = idx & 7;
            const float* src = (col < 64) ? (Wq + (size_t)col * DD)
                                          : (Wk + (size_t)(col - 64) * DD);
            float4 v = *(const float4*)(src + kb + k0 + gg * 4);
            Ws[gg*4+0][col] = v.x; Ws[gg*4+1][col] = v.y;
            Ws[gg*4+2][col] = v.z; Ws[gg*4+3][col] = v.w;
        }
        __syncthreads();
        #pragma unroll 8
        for (int kk = 0; kk < 32; kk++) {
            float4 w = *(const float4*)&Ws[kk][c0];
            #pragma unroll
            for (int i = 0; i < 8; i++) {
                float a = As[kk][r0 + i];
                acc[i][0] += a * w.x; acc[i][1] += a * w.y;
                acc[i][2] += a * w.z; acc[i][3] += a * w.w;
            }
        }
        __syncthreads();
    }
    float* dst = part + (size_t)blockIdx.y * MROWS * 128;
    #pragma unroll
    for (int i = 0; i < 8; i++) {
        float4 o = make_float4(acc[i][0], acc[i][1], acc[i][2], acc[i][3]);
        *(float4*)(dst + (size_t)(m0 + r0 + i) * 128 + c0) = o;
    }
}

__global__ __launch_bounds__(256) void rel_reduce(
    const float* __restrict__ part, float* __restrict__ qrel, float* __restrict__ krel)
{
    int idx = blockIdx.x * 256 + threadIdx.x;
    int row = idx >> 6, col = idx & 63;
    float sq = 0.f, sk = 0.f;
    #pragma unroll
    for (int s = 0; s < 4; s++) {
        const float* p = part + (size_t)s * MROWS * 128 + (size_t)row * 128;
        sq += p[col]; sk += p[col + 64];
    }
    qrel[(size_t)row * 64 + col] = sq;
    krel[(size_t)row * 64 + col] = sk;
}

// ====================== top-K mask build (one block per (b,q)) ================
__device__ __forceinline__ unsigned ford(float f) {
    unsigned u = __float_as_uint(f);
    return (u & 0x80000000u) ? ~u : (u | 0x80000000u);
}

__global__ __launch_bounds__(256) void build_mask(
    const float* __restrict__ qrel, const float* __restrict__ krel,
    unsigned* __restrict__ mask)
{
    const int q = blockIdx.x;
    const int b = blockIdx.y;
    const int tid = threadIdx.x;

    __shared__ float    s[LL];
    __shared__ unsigned mw[LL/32];
    __shared__ float    qv[DREL];
    __shared__ int      hist[256];
    __shared__ unsigned sh_prefix;
    __shared__ int      sh_R;

    if (tid < DREL) qv[tid] = qrel[(size_t)(b*LL + q)*DREL + tid];
    if (tid < LL/32) mw[tid] = 0u;
    __syncthreads();

    const int n = q + 1;
    for (int k = tid; k < n; k += 256) {
        const float4* kr = (const float4*)&krel[(size_t)(b*LL + k)*DREL];
        float acc = 0.f;
        #pragma unroll
        for (int j = 0; j < 16; j++) {
            float4 v = kr[j];
            acc += qv[j*4+0]*v.x + qv[j*4+1]*v.y + qv[j*4+2]*v.z + qv[j*4+3]*v.w;
        }
        s[k] = acc;
    }
    __syncthreads();

    if (n <= KSEL) {
        for (int k = tid; k < n; k += 256)
            atomicOr(&mw[k>>5], 1u << (k & 31));
    } else {
        unsigned prefix = 0u; int R = KSEL;
        for (int byte = 3; byte >= 0; byte--) {
            if (tid < 256) hist[tid] = 0;
            __syncthreads();
            const int shift = byte * 8;
            const unsigned pm = (byte == 3) ? 0u : (0xFFFFFFFFu << (shift + 8));
            for (int k = tid; k < n; k += 256) {
                unsigned u = ford(s[k]);
                if ((u & pm) == (prefix & pm))
                    atomicAdd(&hist[(u >> shift) & 255], 1);
            }
            __syncthreads();
            if (tid == 0) {
                int cum = 0;
                for (int bb2 = 255; bb2 >= 0; bb2--) {
                    int h2 = hist[bb2];
                    if (cum + h2 >= R) {
                        sh_prefix = prefix | ((unsigned)bb2 << shift);
                        sh_R = R - cum;
                        break;
                    }
                    cum += h2;
                }
            }
            __syncthreads();
            prefix = sh_prefix; R = sh_R;
            __syncthreads();
        }
        const unsigned T = prefix;
        for (int k = tid; k < n; k += 256)
            if (ford(s[k]) > T) atomicOr(&mw[k>>5], 1u << (k & 31));
        __syncthreads();
        if (tid == 0) {
            int r2 = R;
            for (int k = 0; k < n && r2 > 0; k++) {
                if (ford(s[k]) == T) { mw[k>>5] |= 1u << (k & 31); r2--; }
            }
        }
    }
    __syncthreads();
    if (tid == 0) mw[q>>5] |= 1u << (q & 31);
    __syncthreads();
    if (tid < LL/32) mask[(size_t)(b*LL + q)*(LL/32) + tid] = mw[tid];
}

// ====================== flash attention (fp16-split mma) ======================
// CTA: 8 warps, Q-tile 128 rows (16 per warp), K/V tiles 64. All operands hi/lo fp16.
#define QSEG 17408      // 128*136 halves
#define KSEG 8704       // 64*136 halves
#define FOFF_QH 0
#define FOFF_QL QSEG
#define FOFF_KH (2*QSEG)
#define FOFF_KL (2*QSEG + KSEG)
#define FOFF_VH (2*QSEG + 2*KSEG)
#define FOFF_VL (2*QSEG + 3*KSEG)
#define FMASK_B ((2*QSEG + 4*KSEG)*2)          // byte offset of mask words
#define FSMEM   (FMASK_B + 256*4)
#define SC2 0.12751744416168355f               // (1/sqrt(128)) * log2(e)

__global__ __launch_bounds__(256) void flash_mma(
    const __half* __restrict__ Qh, const __half* __restrict__ Ql,
    const __half* __restrict__ Kh, const __half* __restrict__ Kl,
    const __half* __restrict__ Vh, const __half* __restrict__ Vl,
    const unsigned* __restrict__ mask,
    __half* __restrict__ Ch, __half* __restrict__ Cl)
{
    extern __shared__ __half FS[];
    const uint32_t base = smem_u32(FS);
    uint32_t* maskS = (uint32_t*)((char*)FS + FMASK_B);

    const int qt = blockIdx.x, h = blockIdx.y, b = blockIdx.z;
    const int q0 = qt * 128;
    const int tid = threadIdx.x;
    const int w = tid >> 5, l = tid & 31;
    const int gid = l >> 2, tig = l & 3;

    // Q load (one-time): 2 segs x 128 rows x 16 chunks = 4096 -> 16/thread
    {
        const __half* qs[2] = {Qh, Ql};
        #pragma unroll
        for (int j = 0; j < 16; j++) {
            int idx = tid + j * 256;
            int seg = idx >> 11, rem = idx & 2047;
            int row = rem >> 4, c16 = rem & 15;
            uint32_t dst = base + (uint32_t)(seg * QSEG + row * 136 + c16 * 8) * 2;
            const __half* src = qs[seg] + (size_t)(b*LL + q0 + row) * DD + h * DHD + c16 * 8;
            CP_ASYNC16(dst, src);
        }
        CP_COMMIT();
    }

    // ldmatrix lane bases
    const int qa_row = w * 16 + ((l >> 3) & 1) * 8 + (l & 7);
    const int qa_colB = (l >> 4) * 16;
    const int kb_rowBase = ((l >> 4) & 1) * 8 + (l & 7);
    const int kb_colB = ((l >> 3) & 1) * 16;
    const int v_row = l & 15;
    const int v_colB = (l >> 4) * 16;

    float O[16][4];
    #pragma unroll
    for (int i = 0; i < 16; i++)
        #pragma unroll
        for (int t = 0; t < 4; t++) O[i][t] = 0.f;
    float m0 = -1e30f, m1 = -1e30f, rl0 = 0.f, rl1 = 0.f;

    const int rlo2 = (w*16 + gid) * 2;
    const int rhi2 = rlo2 + 16;

    const int ktiles = 2 * qt + 2;
    for (int kt = 0; kt < ktiles; kt++) {
        const int k0g = kt * 64;
        __syncthreads();   // previous tile's smem reads done
        // K/V tiles: 4 segs x 64 rows x 16 chunks = 4096 -> 16/thread
        {
            const __half* ks[4] = {Kh, Kl, Vh, Vl};
            const uint32_t off[4] = {FOFF_KH, FOFF_KL, FOFF_VH, FOFF_VL};
            #pragma unroll
            for (int j = 0; j < 16; j++) {
                int idx = tid + j * 256;
                int seg = idx >> 10, rem = idx & 1023;
                int row = rem >> 4, c16 = rem & 15;
                uint32_t dst = base + (uint32_t)(off[seg] + row * 136 + c16 * 8) * 2;
                const __half* src = ks[seg] + (size_t)(b*LL + k0g + row) * DD + h * DHD + c16 * 8;
                CP_ASYNC16(dst, src);
            }
        }
        {   // mask words: 128 rows x 2
            int r = tid >> 1, wd = tid & 1;
            maskS[tid] = mask[(size_t)(b*LL + q0 + r) * (LL/32) + kt*2 + wd];
        }
        CP_COMMIT();
        CP_WAIT(0);
        __syncthreads();

        // ---- S = Q K^T (3-pass fp16 split) ----
        float Sc[8][4];
        #pragma unroll
        for (int i = 0; i < 8; i++)
            #pragma unroll
            for (int t = 0; t < 4; t++) Sc[i][t] = 0.f;

        #pragma unroll
        for (int kf = 0; kf < 8; kf++) {
            uint32_t aH[4], aL[4];
            ldsm4(aH, base + (uint32_t)(FOFF_QH + qa_row * 136) * 2 + kf*32 + qa_colB);
            ldsm4(aL, base + (uint32_t)(FOFF_QL + qa_row * 136) * 2 + kf*32 + qa_colB);
            #pragma unroll
            for (int nf2 = 0; nf2 < 4; nf2++) {
                uint32_t bH[4], bL[4];
                ldsm4(bH, base + (uint32_t)(FOFF_KH + (nf2*16 + kb_rowBase) * 136) * 2 + kf*32 + kb_colB);
                mma16816(Sc[2*nf2],   aH, bH + 0);
                mma16816(Sc[2*nf2+1], aH, bH + 2);
                mma16816(Sc[2*nf2],   aL, bH + 0);
                mma16816(Sc[2*nf2+1], aL, bH + 2);
                ldsm4(bL, base + (uint32_t)(FOFF_KL + (nf2*16 + kb_rowBase) * 136) * 2 + kf*32 + kb_colB);
                mma16816(Sc[2*nf2],   aH, bL + 0);
                mma16816(Sc[2*nf2+1], aH, bL + 2);
            }
        }

        // ---- mask ----
        #pragma unroll
        for (int nf = 0; nf < 8; nf++) {
            unsigned wlo = maskS[rlo2 + (nf >> 2)];
            unsigned whi = maskS[rhi2 + (nf >> 2)];
            int sh = ((nf & 3) << 3) + (tig << 1);
            Sc[nf][0] = ((wlo >> sh) & 1u)     ? Sc[nf][0] : -1e30f;
            Sc[nf][1] = ((wlo >> (sh+1)) & 1u) ? Sc[nf][1] : -1e30f;
            Sc[nf][2] = ((whi >> sh) & 1u)     ? Sc[nf][2] : -1e30f;
            Sc[nf][3] = ((whi >> (sh+1)) & 1u) ? Sc[nf][3] : -1e30f;
        }

        // ---- online softmax (per-warp rows in registers) ----
        float mx0 = -1e30f, mx1 = -1e30f;
        #pragma unroll
        for (int nf = 0; nf < 8; nf++) {
            mx0 = fmaxf(mx0, fmaxf(Sc[nf][0], Sc[nf][1]));
            mx1 = fmaxf(mx1, fmaxf(Sc[nf][2], Sc[nf][3]));
        }
        mx0 = fmaxf(mx0, __shfl_xor_sync(0xffffffffu, mx0, 1));
        mx0 = fmaxf(mx0, __shfl_xor_sync(0xffffffffu, mx0, 2));
        mx1 = fmaxf(mx1, __shfl_xor_sync(0xffffffffu, mx1, 1));
        mx1 = fmaxf(mx1, __shfl_xor_sync(0xffffffffu, mx1, 2));
        float nm0 = fmaxf(m0, mx0), nm1 = fmaxf(m1, mx1);
        float a0 = ex2f((m0 - nm0) * SC2), a1 = ex2f((m1 - nm1) * SC2);
        m0 = nm0; m1 = nm1;

        float s0 = 0.f, s1 = 0.f;
        #pragma unroll
        for (int nf = 0; nf < 8; nf++) {
            float p0 = ex2f((Sc[nf][0] - m0) * SC2);
            float p1 = ex2f((Sc[nf][1] - m0) * SC2);
            float p2 = ex2f((Sc[nf][2] - m1) * SC2);
            float p3 = ex2f((Sc[nf][3] - m1) * SC2);
            Sc[nf][0] = p0; Sc[nf][1] = p1; Sc[nf][2] = p2; Sc[nf][3] = p3;
            s0 += p0 + p1; s1 += p2 + p3;
        }
        s0 += __shfl_xor_sync(0xffffffffu, s0, 1);
        s0 += __shfl_xor_sync(0xffffffffu, s0, 2);
        s1 += __shfl_xor_sync(0xffffffffu, s1, 1);
        s1 += __shfl_xor_sync(0xffffffffu, s1, 2);
        rl0 = rl0 * a0 + s0;
        rl1 = rl1 * a1 + s1;

        #pragma unroll
        for (int df = 0; df < 16; df++) {
            O[df][0] *= a0; O[df][1] *= a0;
            O[df][2] *= a1; O[df][3] *= a1;
        }

        // ---- O += P V (3-pass split; P from Sc fragments) ----
        #pragma unroll
        for (int kf = 0; kf < 4; kf++) {
            uint32_t Pha[4], Pla[4];
            split2(Sc[2*kf][0],   Sc[2*kf][1],   Pha[0], Pla[0]);
            split2(Sc[2*kf][2],   Sc[2*kf][3],   Pha[1], Pla[1]);
            split2(Sc[2*kf+1][0], Sc[2*kf+1][1], Pha[2], Pla[2]);
            split2(Sc[2*kf+1][2], Sc[2*kf+1][3], Pha[3], Pla[3]);
            #pragma unroll
            for (int df2 = 0; df2 < 8; df2++) {
                uint32_t vh4[4], vl4[4];
                ldsm4t(vh4, base + (uint32_t)(FOFF_VH + (kf*16 + v_row) * 136) * 2 + df2*32 + v_colB);
                mma16816(O[2*df2],   Pha, vh4 + 0);
                mma16816(O[2*df2+1], Pha, vh4 + 2);
                mma16816(O[2*df2],   Pla, vh4 + 0);
                mma16816(O[2*df2+1], Pla, vh4 + 2);
                ldsm4t(vl4, base + (uint32_t)(FOFF_VL + (kf*16 + v_row) * 136) * 2 + df2*32 + v_colB);
                mma16816(O[2*df2],   Pha, vl4 + 0);
                mma16816(O[2*df2+1], Pha, vl4 + 2);
            }
        }
    }

    // ---- epilogue: ctx = O / l, emitted as hi/lo fp16 ----
    float inv0 = 1.f / rl0, inv1 = 1.f / rl1;
    const size_t rowlo = (size_t)(b*LL + q0 + w*16 + gid) * DD + h * DHD + tig * 2;
    const size_t rowhi = rowlo + 8 * DD;
    #pragma unroll
    for (int df = 0; df < 16; df++) {
        uint32_t hv, lv;
        split2(O[df][0] * inv0, O[df][1] * inv0, hv, lv);
        *(uint32_t*)(Ch + rowlo + df*8) = hv;
        *(uint32_t*)(Cl + rowlo + df*8) = lv;
        split2(O[df][2] * inv1, O[df][3] * inv1, hv, lv);
        *(uint32_t*)(Ch + rowhi + df*8) = hv;
        *(uint32_t*)(Cl + rowhi + df*8) = lv;
    }
}

// ================================ launch ======================================
extern "C" void kernel_launch(void* const* d_in, const int* in_sizes, int n_in,
                              void* d_out, int out_size)
{
    const float* hidden    = (const float*)d_in[0];
    const float* relevance = (const float*)d_in[1];
    const float* Wqr       = (const float*)d_in[2];
    const float* Wkr       = (const float*)d_in[3];
    const float* Wq        = (const float*)d_in[4];
    const float* Wk        = (const float*)d_in[5];
    const float* Wv        = (const float*)d_in[6];
    const float* Wo        = (const float*)d_in[7];
    float* out = (float*)d_out;

    __half *hidh,*hidl,*wqh,*wql,*wkh,*wkl,*wvh,*wvl,*woh,*wol;
    __half *qh,*ql,*kh,*kl,*vh,*vl,*ctxh,*ctxl;
    float *qrel,*krel,*relp; unsigned* mask;
    cudaGetSymbolAddress((void**)&hidh, g_hidh); cudaGetSymbolAddress((void**)&hidl, g_hidl);
    cudaGetSymbolAddress((void**)&wqh,  g_wqh);  cudaGetSymbolAddress((void**)&wql,  g_wql);
    cudaGetSymbolAddress((void**)&wkh,  g_wkh);  cudaGetSymbolAddress((void**)&wkl,  g_wkl);
    cudaGetSymbolAddress((void**)&wvh,  g_wvh);  cudaGetSymbolAddress((void**)&wvl,  g_wvl);
    cudaGetSymbolAddress((void**)&woh,  g_woh);  cudaGetSymbolAddress((void**)&wol,  g_wol);
    cudaGetSymbolAddress((void**)&qh,   g_qh);   cudaGetSymbolAddress((void**)&ql,   g_ql);
    cudaGetSymbolAddress((void**)&kh,   g_kh);   cudaGetSymbolAddress((void**)&kl,   g_kl);
    cudaGetSymbolAddress((void**)&vh,   g_vh);   cudaGetSymbolAddress((void**)&vl,   g_vl);
    cudaGetSymbolAddress((void**)&ctxh, g_ctxh); cudaGetSymbolAddress((void**)&ctxl, g_ctxl);
    cudaGetSymbolAddress((void**)&qrel, g_qrel); cudaGetSymbolAddress((void**)&krel, g_krel);
    cudaGetSymbolAddress((void**)&relp, g_relp); cudaGetSymbolAddress((void**)&mask, g_mask);

    cudaFuncSetAttribute(gemm_h<0>, cudaFuncAttributeMaxDynamicSharedMemorySize, GSMEM);
    cudaFuncSetAttribute(gemm_h<1>, cudaFuncAttributeMaxDynamicSharedMemorySize, GSMEM);
    cudaFuncSetAttribute(flash_mma, cudaFuncAttributeMaxDynamicSharedMemorySize, FSMEM);

    // fp32 -> hi/lo fp16 conversions
    const int nh4 = MROWS * DD / 4, nw4 = DD * DD / 4;
    cvt_split<<<(nh4 + 255)/256, 256>>>((const float4*)hidden, (uint2*)hidh, (uint2*)hidl, nh4);
    cvt_split<<<(nw4 + 255)/256, 256>>>((const float4*)Wq, (uint2*)wqh, (uint2*)wql, nw4);
    cvt_split<<<(nw4 + 255)/256, 256>>>((const float4*)Wk, (uint2*)wkh, (uint2*)wkl, nw4);
    cvt_split<<<(nw4 + 255)/256, 256>>>((const float4*)Wv, (uint2*)wvh, (uint2*)wvl, nw4);
    cvt_split<<<(nw4 + 255)/256, 256>>>((const float4*)Wo, (uint2*)woh, (uint2*)wol, nw4);

    // relevance path
    rel_proj<<<dim3(MROWS/64, 4), 256>>>(relevance, Wqr, Wkr, relp);
    rel_reduce<<<(MROWS*64)/256, 256>>>(relp, qrel, krel);
    build_mask<<<dim3(LL, BB), 256>>>(qrel, krel, mask);

    // projections
    dim3 gG(DD/128, MROWS/128);
    gemm_h<0><<<gG, 256, GSMEM>>>(hidh, hidl, wqh, wql, nullptr, qh, ql);
    gemm_h<0><<<gG, 256, GSMEM>>>(hidh, hidl, wkh, wkl, nullptr, kh, kl);
    gemm_h<0><<<gG, 256, GSMEM>>>(hidh, hidl, wvh, wvl, nullptr, vh, vl);

    // attention
    flash_mma<<<dim3(LL/128, HH, BB), 256, FSMEM>>>(qh, ql, kh, kl, vh, vl, mask, ctxh, ctxl);

    // output projection
    gemm_h<1><<<gG, 256, GSMEM>>>(ctxh, ctxl, woh, wol, out, nullptr, nullptr);
}

// round 5
// speedup vs baseline: 3.1926x; 1.1736x over previous
#include <cuda_runtime.h>
#include <cuda_fp16.h>
#include <cstdint>
#include <math.h>

// Problem constants
#define BB   2
#define LL   2048
#define DD   2048
#define HH   16
#define DHD  128
#define DREL 64
#define KSEL 512
#define MROWS (BB*LL)   // 4096

// -------------------- scratch (device globals; no cudaMalloc allowed) ---------
__device__ __align__(256) __half g_hidh[MROWS*DD];
__device__ __align__(256) __half g_hidl[MROWS*DD];
__device__ __align__(256) __half g_wqh [DD*DD];
__device__ __align__(256) __half g_wql [DD*DD];
__device__ __align__(256) __half g_wkh [DD*DD];
__device__ __align__(256) __half g_wkl [DD*DD];
__device__ __align__(256) __half g_wvh [DD*DD];
__device__ __align__(256) __half g_wvl [DD*DD];
__device__ __align__(256) __half g_woh [DD*DD];
__device__ __align__(256) __half g_wol [DD*DD];
__device__ __align__(256) __half g_qh  [MROWS*DD];
__device__ __align__(256) __half g_ql  [MROWS*DD];
__device__ __align__(256) __half g_kh  [MROWS*DD];
__device__ __align__(256) __half g_kl  [MROWS*DD];
__device__ __align__(256) __half g_vh  [MROWS*DD];
__device__ __align__(256) __half g_vl  [MROWS*DD];
__device__ __align__(256) __half g_ctxh[MROWS*DD];
__device__ __align__(256) __half g_ctxl[MROWS*DD];
__device__ __align__(256) float    g_qrel[BB*LL*DREL];
__device__ __align__(256) float    g_krel[BB*LL*DREL];
__device__ __align__(256) float    g_relp[4*MROWS*128];
__device__ __align__(256) unsigned g_mask[BB*LL*(LL/32)];

// ========================= inline PTX helpers =================================
__device__ __forceinline__ uint32_t smem_u32(const void* p) {
    uint32_t a;
    asm("{ .reg .u64 t; cvta.to.shared.u64 t, %1; cvt.u32.u64 %0, t; }" : "=r"(a) : "l"(p));
    return a;
}
__device__ __forceinline__ void ldsm4(uint32_t* r, uint32_t addr) {
    asm volatile("ldmatrix.sync.aligned.m8n8.x4.shared.b16 {%0,%1,%2,%3}, [%4];"
        : "=r"(r[0]), "=r"(r[1]), "=r"(r[2]), "=r"(r[3]) : "r"(addr));
}
__device__ __forceinline__ void ldsm4t(uint32_t* r, uint32_t addr) {
    asm volatile("ldmatrix.sync.aligned.m8n8.x4.trans.shared.b16 {%0,%1,%2,%3}, [%4];"
        : "=r"(r[0]), "=r"(r[1]), "=r"(r[2]), "=r"(r[3]) : "r"(addr));
}
__device__ __forceinline__ void mma16816(float* c, const uint32_t* a, const uint32_t* b) {
    asm volatile("mma.sync.aligned.m16n8k16.row.col.f32.f16.f16.f32 "
        "{%0,%1,%2,%3}, {%4,%5,%6,%7}, {%8,%9}, {%0,%1,%2,%3};"
        : "+f"(c[0]), "+f"(c[1]), "+f"(c[2]), "+f"(c[3])
        : "r"(a[0]), "r"(a[1]), "r"(a[2]), "r"(a[3]), "r"(b[0]), "r"(b[1]));
}
#define CP_ASYNC16(dst, src) \
    asm volatile("cp.async.cg.shared.global [%0], [%1], 16;" :: "r"(dst), "l"(src) : "memory")
#define CP_ASYNC8(dst, src) \
    asm volatile("cp.async.ca.shared.global [%0], [%1], 8;" :: "r"(dst), "l"(src) : "memory")
#define CP_COMMIT() asm volatile("cp.async.commit_group;" ::: "memory")
#define CP_WAIT(n)  asm volatile("cp.async.wait_group %0;" :: "n"(n) : "memory")

__device__ __forceinline__ float ex2f(float x) {
    float y; asm("ex2.approx.f32 %0, %1;" : "=f"(y) : "f"(x)); return y;
}
__device__ __forceinline__ void split2(float x, float y, uint32_t& hi, uint32_t& lo) {
    __half hx = __float2half_rn(x), hy = __float2half_rn(y);
    __half lx = __float2half_rn(x - __half2float(hx));
    __half ly = __float2half_rn(y - __half2float(hy));
    hi = ((uint32_t)__half_as_ushort(hy) << 16) | __half_as_ushort(hx);
    lo = ((uint32_t)__half_as_ushort(ly) << 16) | __half_as_ushort(lx);
}

// =========================== fp32 -> hi/lo fp16 split =========================
__global__ __launch_bounds__(256) void cvt_split(
    const float4* __restrict__ x, uint2* __restrict__ h, uint2* __restrict__ lo, int n4)
{
    int i = blockIdx.x * 256 + threadIdx.x;
    if (i >= n4) return;
    float4 v = x[i];
    uint32_t h0, l0, h1, l1;
    split2(v.x, v.y, h0, l0);
    split2(v.z, v.w, h1, l1);
    h[i]  = make_uint2(h0, h1);
    lo[i] = make_uint2(l0, l1);
}

// ============== fp16-split GEMM: C[4096,2048] = A · B^T (hi/lo inputs) ========
// CTA 128x128, k-chunk 32, 3-stage cp.async pipeline.
#define SEGB 10240              // bytes per segment (128 rows x 40 halves)
#define GSMEM (3*4*SEGB)        // 122880 B

template<int OUTF32>
__device__ __forceinline__ void gemm_body(
    const __half* __restrict__ Ah, const __half* __restrict__ Al,
    const __half* __restrict__ Bh, const __half* __restrict__ Bl,
    float* __restrict__ Cf, __half* __restrict__ Ch, __half* __restrict__ Cl,
    __half* GS)
{
    const uint32_t base = smem_u32(GS);
    const int tid = threadIdx.x;
    const int l   = tid & 31;
    const int wid = tid >> 5;
    const int wm  = wid >> 2;
    const int wn  = wid & 3;
    const int bm  = blockIdx.y * 128;
    const int bn  = blockIdx.x * 128;

    const int which = tid >> 6;
    const int cid0  = tid & 63;
    const __half* srcs[4] = {Ah, Al, Bh, Bl};
    const __half* srcBase = srcs[which] + (size_t)((which < 2 ? bm : bn)) * DD;

    const int rA = wm * 64 + ((l >> 3) & 1) * 8 + (l & 7);
    const int kA = (l >> 4) * 16;
    const int rB = wn * 32 + ((l >> 4) & 1) * 8 + (l & 7);
    const int kB = ((l >> 3) & 1) * 16;

    float acc[4][4][4];
    #pragma unroll
    for (int i = 0; i < 4; i++)
        #pragma unroll
        for (int j = 0; j < 4; j++)
            #pragma unroll
            for (int t = 0; t < 4; t++) acc[i][j][t] = 0.f;

    auto issue_stage = [&](int c, int st) {
        #pragma unroll
        for (int j = 0; j < 8; j++) {
            int cid = cid0 + j * 64;
            int row = cid >> 2, c16 = cid & 3;
            uint32_t dst = base + (uint32_t)(st * 4 + which) * SEGB + (uint32_t)row * 80 + c16 * 16;
            const __half* src = srcBase + (size_t)row * DD + c * 32 + c16 * 8;
            CP_ASYNC16(dst, src);
        }
        CP_COMMIT();
    };

    issue_stage(0, 0);
    issue_stage(1, 1);

    for (int c = 0; c < DD / 32; c++) {
        CP_WAIT(1);
        __syncthreads();
        if (c + 2 < DD / 32) issue_stage(c + 2, (c + 2) % 3);
        else CP_COMMIT();

        const int st = c % 3;
        const uint32_t sAh = base + (uint32_t)(st * 4 + 0) * SEGB;
        const uint32_t sAl = base + (uint32_t)(st * 4 + 1) * SEGB;
        const uint32_t sBh = base + (uint32_t)(st * 4 + 2) * SEGB;
        const uint32_t sBl = base + (uint32_t)(st * 4 + 3) * SEGB;

        #pragma unroll
        for (int ks = 0; ks < 2; ks++) {
            uint32_t aH[4][4], aL[4][4];
            #pragma unroll
            for (int mf = 0; mf < 4; mf++) {
                ldsm4(aH[mf], sAh + (uint32_t)(rA + mf*16) * 80 + kA + ks*32);
                ldsm4(aL[mf], sAl + (uint32_t)(rA + mf*16) * 80 + kA + ks*32);
            }
            #pragma unroll
            for (int nf2 = 0; nf2 < 2; nf2++) {
                uint32_t bH[4], bL[4];
                ldsm4(bH, sBh + (uint32_t)(rB + nf2*16) * 80 + kB + ks*32);
                #pragma unroll
                for (int mf = 0; mf < 4; mf++) {
                    mma16816(acc[mf][2*nf2],   aH[mf], bH + 0);
                    mma16816(acc[mf][2*nf2+1], aH[mf], bH + 2);
                    mma16816(acc[mf][2*nf2],   aL[mf], bH + 0);
                    mma16816(acc[mf][2*nf2+1], aL[mf], bH + 2);
                }
                ldsm4(bL, sBl + (uint32_t)(rB + nf2*16) * 80 + kB + ks*32);
                #pragma unroll
                for (int mf = 0; mf < 4; mf++) {
                    mma16816(acc[mf][2*nf2],   aH[mf], bL + 0);
                    mma16816(acc[mf][2*nf2+1], aH[mf], bL + 2);
                }
            }
        }
    }

    const int gid = l >> 2, tig = l & 3;
    #pragma unroll
    for (int mf = 0; mf < 4; mf++) {
        #pragma unroll
        for (int nf = 0; nf < 4; nf++) {
            int r0 = bm + wm*64 + mf*16 + gid;
            int cc = bn + wn*32 + nf*8 + tig*2;
            if (OUTF32) {
                *(float2*)(Cf + (size_t)r0 * DD + cc)       = make_float2(acc[mf][nf][0], acc[mf][nf][1]);
                *(float2*)(Cf + (size_t)(r0 + 8) * DD + cc) = make_float2(acc[mf][nf][2], acc[mf][nf][3]);
            } else {
                uint32_t h0, l0v, h1, l1v;
                split2(acc[mf][nf][0], acc[mf][nf][1], h0, l0v);
                split2(acc[mf][nf][2], acc[mf][nf][3], h1, l1v);
                *(uint32_t*)(Ch + (size_t)r0 * DD + cc)       = h0;
                *(uint32_t*)(Cl + (size_t)r0 * DD + cc)       = l0v;
                *(uint32_t*)(Ch + (size_t)(r0 + 8) * DD + cc) = h1;
                *(uint32_t*)(Cl + (size_t)(r0 + 8) * DD + cc) = l1v;
            }
        }
    }
}

// QKV fused over blockIdx.z
__global__ __launch_bounds__(256) void gemm_qkv(
    const __half* __restrict__ Ah, const __half* __restrict__ Al,
    const __half* __restrict__ Wqh, const __half* __restrict__ Wql,
    __half* __restrict__ Qh, __half* __restrict__ Ql,
    const __half* __restrict__ Wkh, const __half* __restrict__ Wkl,
    __half* __restrict__ Kh, __half* __restrict__ Kl,
    const __half* __restrict__ Wvh, const __half* __restrict__ Wvl,
    __half* __restrict__ Vh, __half* __restrict__ Vl)
{
    extern __shared__ __half GS[];
    const __half *Bh, *Bl; __half *Ch, *Cl;
    if (blockIdx.z == 0)      { Bh = Wqh; Bl = Wql; Ch = Qh; Cl = Ql; }
    else if (blockIdx.z == 1) { Bh = Wkh; Bl = Wkl; Ch = Kh; Cl = Kl; }
    else                      { Bh = Wvh; Bl = Wvl; Ch = Vh; Cl = Vl; }
    gemm_body<0>(Ah, Al, Bh, Bl, nullptr, Ch, Cl, GS);
}

__global__ __launch_bounds__(256) void gemm_o(
    const __half* __restrict__ Ah, const __half* __restrict__ Al,
    const __half* __restrict__ Bh, const __half* __restrict__ Bl,
    float* __restrict__ Cf)
{
    extern __shared__ __half GS[];
    gemm_body<1>(Ah, Al, Bh, Bl, Cf, nullptr, nullptr, GS);
}

// ===================== rel projection (split-K, fused q/k) ====================
__global__ __launch_bounds__(256) void rel_proj(
    const float* __restrict__ A, const float* __restrict__ Wq,
    const float* __restrict__ Wk, float* __restrict__ part)
{
    __shared__ __align__(16) float As[32][65];
    __shared__ __align__(16) float Ws[32][132];
    const int tid = threadIdx.x;
    const int m0 = blockIdx.x * 64;
    const int kb = blockIdx.y * 512;
    const int r0 = (tid >> 5) * 8;
    const int c0 = (tid & 31) * 4;

    float acc[8][4];
    #pragma unroll
    for (int i = 0; i < 8; i++)
        #pragma unroll
        for (int j = 0; j < 4; j++) acc[i][j] = 0.f;

    for (int k0 = 0; k0 < 512; k0 += 32) {
        #pragma unroll
        for (int t = 0; t < 2; t++) {
            int idx = tid + t * 256;
            int row = idx >> 3, gg = idx & 7;
            float4 v = *(const float4*)(A + (size_t)(m0 + row) * DD + kb + k0 + gg * 4);
            As[gg*4+0][row] = v.x; As[gg*4+1][row] = v.y;
            As[gg*4+2][row] = v.z; As[gg*4+3][row] = v.w;
        }
        #pragma unroll
        for (int t = 0; t < 4; t++) {
            int idx = tid + t * 256;
            int col = idx >> 3, gg = idx & 7;
            const float* src = (col < 64) ? (Wq + (size_t)col * DD)
                                          : (Wk + (size_t)(col - 64) * DD);
            float4 v = *(const float4*)(src + kb + k0 + gg * 4);
            Ws[gg*4+0][col] = v.x; Ws[gg*4+1][col] = v.y;
            Ws[gg*4+2][col] = v.z; Ws[gg*4+3][col] = v.w;
        }
        __syncthreads();
        #pragma unroll 8
        for (int kk = 0; kk < 32; kk++) {
            float4 w = *(const float4*)&Ws[kk][c0];
            #pragma unroll
            for (int i = 0; i < 8; i++) {
                float a = As[kk][r0 + i];
                acc[i][0] += a * w.x; acc[i][1] += a * w.y;
                acc[i][2] += a * w.z; acc[i][3] += a * w.w;
            }
        }
        __syncthreads();
    }
    float* dst = part + (size_t)blockIdx.y * MROWS * 128;
    #pragma unroll
    for (int i = 0; i < 8; i++) {
        float4 o = make_float4(acc[i][0], acc[i][1], acc[i][2], acc[i][3]);
        *(float4*)(dst + (size_t)(m0 + r0 + i) * 128 + c0) = o;
    }
}

__global__ __launch_bounds__(256) void rel_reduce(
    const float* __restrict__ part, float* __restrict__ qrel, float* __restrict__ krel)
{
    int idx = blockIdx.x * 256 + threadIdx.x;
    int row = idx >> 6, col = idx & 63;
    float sq = 0.f, sk = 0.f;
    #pragma unroll
    for (int s = 0; s < 4; s++) {
        const float* p = part + (size_t)s * MROWS * 128 + (size_t)row * 128;
        sq += p[col]; sk += p[col + 64];
    }
    qrel[(size_t)row * 64 + col] = sq;
    krel[(size_t)row * 64 + col] = sk;
}

// ====================== top-K mask build (one block per (b,q)) ================
__device__ __forceinline__ unsigned ford(float f) {
    unsigned u = __float_as_uint(f);
    return (u & 0x80000000u) ? ~u : (u | 0x80000000u);
}

__global__ __launch_bounds__(256) void build_mask(
    const float* __restrict__ qrel, const float* __restrict__ krel,
    unsigned* __restrict__ mask)
{
    const int q = blockIdx.x;
    const int b = blockIdx.y;
    const int tid = threadIdx.x;

    __shared__ float    s[LL];
    __shared__ unsigned mw[LL/32];
    __shared__ float    qv[DREL];
    __shared__ int      hist[256];
    __shared__ int      scan[256];
    __shared__ unsigned sh_prefix;
    __shared__ int      sh_R;

    if (tid < DREL) qv[tid] = qrel[(size_t)(b*LL + q)*DREL + tid];
    if (tid < LL/32) mw[tid] = 0u;
    __syncthreads();

    const int n = q + 1;
    for (int k = tid; k < n; k += 256) {
        const float4* kr = (const float4*)&krel[(size_t)(b*LL + k)*DREL];
        float acc = 0.f;
        #pragma unroll
        for (int j = 0; j < 16; j++) {
            float4 v = kr[j];
            acc += qv[j*4+0]*v.x + qv[j*4+1]*v.y + qv[j*4+2]*v.z + qv[j*4+3]*v.w;
        }
        s[k] = acc;
    }
    __syncthreads();

    if (n <= KSEL) {
        for (int k = tid; k < n; k += 256)
            atomicOr(&mw[k>>5], 1u << (k & 31));
    } else {
        unsigned prefix = 0u; int R = KSEL;
        for (int byte = 3; byte >= 0; byte--) {
            hist[tid] = 0;
            __syncthreads();
            const int shift = byte * 8;
            const unsigned pm = (byte == 3) ? 0u : (0xFFFFFFFFu << (shift + 8));
            for (int k = tid; k < n; k += 256) {
                unsigned u = ford(s[k]);
                if ((u & pm) == (prefix & pm))
                    atomicAdd(&hist[(u >> shift) & 255], 1);
            }
            __syncthreads();
            // parallel suffix scan: scan[t] = sum_{j>=t} hist[j]
            int hv = hist[tid];
            scan[tid] = hv;
            __syncthreads();
            #pragma unroll
            for (int off = 1; off < 256; off <<= 1) {
                int t = (tid + off < 256) ? scan[tid + off] : 0;
                __syncthreads();
                scan[tid] += t;
                __syncthreads();
            }
            int inc = scan[tid];
            int above = inc - hv;
            if (above < R && inc >= R) {
                sh_prefix = prefix | ((unsigned)tid << shift);
                sh_R = R - above;
            }
            __syncthreads();
            prefix = sh_prefix; R = sh_R;
            __syncthreads();
        }
        const unsigned T = prefix;
        for (int k = tid; k < n; k += 256)
            if (ford(s[k]) > T) atomicOr(&mw[k>>5], 1u << (k & 31));
        // parallel tie fill: first R ties by index
        const int per = (n + 255) >> 8;
        const int lo = tid * per;
        const int hi = (lo + per < n) ? lo + per : n;
        int cnt = 0;
        for (int k = lo; k < hi; k++)
            if (ford(s[k]) == T) cnt++;
        scan[tid] = cnt;
        __syncthreads();
        #pragma unroll
        for (int off = 1; off < 256; off <<= 1) {
            int t = (tid >= off) ? scan[tid - off] : 0;
            __syncthreads();
            scan[tid] += t;
            __syncthreads();
        }
        int excl = scan[tid] - cnt;
        int r2 = R - excl;
        if (r2 > 0) {
            for (int k = lo; k < hi && r2 > 0; k++)
                if (ford(s[k]) == T) { atomicOr(&mw[k>>5], 1u << (k & 31)); r2--; }
        }
    }
    __syncthreads();
    if (tid == 0) mw[q>>5] |= 1u << (q & 31);
    __syncthreads();
    if (tid < LL/32) mask[(size_t)(b*LL + q)*(LL/32) + tid] = mw[tid];
}

// ====================== flash attention (fp16-split mma) ======================
// 8 warps, Q-tile 128 rows, K/V tiles 64, double-buffered K/V/mask via cp.async.
#define QSEG 17408      // 128*136 halves
#define KSEG 8704       // 64*136 halves
#define FOFF_QH 0
#define FOFF_QL QSEG
#define KVOFF(st, seg) (2*QSEG + (st)*4*KSEG + (seg)*KSEG)
#define FMASK_B ((2*QSEG + 8*KSEG)*2)          // byte offset of mask buffers
#define FSMEM   (FMASK_B + 2*256*4)
#define SC2 0.12751744416168355f               // (1/sqrt(128)) * log2(e)

__global__ __launch_bounds__(256) void flash_mma(
    const __half* __restrict__ Qh, const __half* __restrict__ Ql,
    const __half* __restrict__ Kh, const __half* __restrict__ Kl,
    const __half* __restrict__ Vh, const __half* __restrict__ Vl,
    const unsigned* __restrict__ mask,
    __half* __restrict__ Ch, __half* __restrict__ Cl)
{
    extern __shared__ __half FS[];
    const uint32_t base = smem_u32(FS);
    const uint32_t maskB = base + FMASK_B;

    const int qt = blockIdx.x, h = blockIdx.y, b = blockIdx.z;
    const int q0 = qt * 128;
    const int tid = threadIdx.x;
    const int w = tid >> 5, l = tid & 31;
    const int gid = l >> 2, tig = l & 3;

    // Q load (one-time)
    {
        const __half* qs[2] = {Qh, Ql};
        #pragma unroll
        for (int j = 0; j < 16; j++) {
            int idx = tid + j * 256;
            int seg = idx >> 11, rem = idx & 2047;
            int row = rem >> 4, c16 = rem & 15;
            uint32_t dst = base + (uint32_t)(seg * QSEG + row * 136 + c16 * 8) * 2;
            const __half* src = qs[seg] + (size_t)(b*LL + q0 + row) * DD + h * DHD + c16 * 8;
            CP_ASYNC16(dst, src);
        }
        CP_COMMIT();
    }

    auto issue_kv = [&](int kt, int st) {
        const __half* ks[4] = {Kh, Kl, Vh, Vl};
        #pragma unroll
        for (int j = 0; j < 16; j++) {
            int idx = tid + j * 256;
            int seg = idx >> 10, rem = idx & 1023;
            int row = rem >> 4, c16 = rem & 15;
            uint32_t dst = base + (uint32_t)(KVOFF(st, seg) + row * 136 + c16 * 8) * 2;
            const __half* src = ks[seg] + (size_t)(b*LL + kt*64 + row) * DD + h * DHD + c16 * 8;
            CP_ASYNC16(dst, src);
        }
        if (tid < 128) {
            uint32_t dst = maskB + st * 1024 + tid * 8;
            const unsigned* src = &mask[(size_t)(b*LL + q0 + tid) * (LL/32) + kt*2];
            CP_ASYNC8(dst, src);
        }
        CP_COMMIT();
    };

    issue_kv(0, 0);

    // ldmatrix lane bases
    const int qa_row = w * 16 + ((l >> 3) & 1) * 8 + (l & 7);
    const int qa_colB = (l >> 4) * 16;
    const int kb_rowBase = ((l >> 4) & 1) * 8 + (l & 7);
    const int kb_colB = ((l >> 3) & 1) * 16;
    const int v_row = l & 15;
    const int v_colB = (l >> 4) * 16;

    float O[16][4];
    #pragma unroll
    for (int i = 0; i < 16; i++)
        #pragma unroll
        for (int t = 0; t < 4; t++) O[i][t] = 0.f;
    float m0 = -1e30f, m1 = -1e30f, rl0 = 0.f, rl1 = 0.f;

    const int rlo2 = (w*16 + gid) * 2;
    const int rhi2 = rlo2 + 16;

    const int ktiles = 2 * qt + 2;
    for (int kt = 0; kt < ktiles; kt++) {
        const int st = kt & 1;
        if (kt + 1 < ktiles) {
            __syncthreads();            // prior compute done before overwriting st^1
            issue_kv(kt + 1, st ^ 1);
            CP_WAIT(1);
        } else {
            CP_WAIT(0);
        }
        __syncthreads();

        const uint32_t sKH = base + (uint32_t)KVOFF(st, 0) * 2;
        const uint32_t sKL = base + (uint32_t)KVOFF(st, 1) * 2;
        const uint32_t sVH = base + (uint32_t)KVOFF(st, 2) * 2;
        const uint32_t sVL = base + (uint32_t)KVOFF(st, 3) * 2;
        const uint32_t* maskS = (const uint32_t*)(FS) + (FMASK_B >> 2) + st * 256;

        // ---- S = Q K^T (3-pass fp16 split) ----
        float Sc[8][4];
        #pragma unroll
        for (int i = 0; i < 8; i++)
            #pragma unroll
            for (int t = 0; t < 4; t++) Sc[i][t] = 0.f;

        #pragma unroll
        for (int kf = 0; kf < 8; kf++) {
            uint32_t aH[4], aL[4];
            ldsm4(aH, base + (uint32_t)(FOFF_QH + qa_row * 136) * 2 + kf*32 + qa_colB);
            ldsm4(aL, base + (uint32_t)(FOFF_QL + qa_row * 136) * 2 + kf*32 + qa_colB);
            #pragma unroll
            for (int nf2 = 0; nf2 < 4; nf2++) {
                uint32_t bH[4], bL[4];
                ldsm4(bH, sKH + (uint32_t)((nf2*16 + kb_rowBase) * 136) * 2 + kf*32 + kb_colB);
                mma16816(Sc[2*nf2],   aH, bH + 0);
                mma16816(Sc[2*nf2+1], aH, bH + 2);
                mma16816(Sc[2*nf2],   aL, bH + 0);
                mma16816(Sc[2*nf2+1], aL, bH + 2);
                ldsm4(bL, sKL + (uint32_t)((nf2*16 + kb_rowBase) * 136) * 2 + kf*32 + kb_colB);
                mma16816(Sc[2*nf2],   aH, bL + 0);
                mma16816(Sc[2*nf2+1], aH, bL + 2);
            }
        }

        // ---- mask ----
        #pragma unroll
        for (int nf = 0; nf < 8; nf++) {
            unsigned wlo = maskS[rlo2 + (nf >> 2)];
            unsigned whi = maskS[rhi2 + (nf >> 2)];
            int sh = ((nf & 3) << 3) + (tig << 1);
            Sc[nf][0] = ((wlo >> sh) & 1u)     ? Sc[nf][0] : -1e30f;
            Sc[nf][1] = ((wlo >> (sh+1)) & 1u) ? Sc[nf][1] : -1e30f;
            Sc[nf][2] = ((whi >> sh) & 1u)     ? Sc[nf][2] : -1e30f;
            Sc[nf][3] = ((whi >> (sh+1)) & 1u) ? Sc[nf][3] : -1e30f;
        }

        // ---- online softmax ----
        float mx0 = -1e30f, mx1 = -1e30f;
        #pragma unroll
        for (int nf = 0; nf < 8; nf++) {
            mx0 = fmaxf(mx0, fmaxf(Sc[nf][0], Sc[nf][1]));
            mx1 = fmaxf(mx1, fmaxf(Sc[nf][2], Sc[nf][3]));
        }
        mx0 = fmaxf(mx0, __shfl_xor_sync(0xffffffffu, mx0, 1));
        mx0 = fmaxf(mx0, __shfl_xor_sync(0xffffffffu, mx0, 2));
        mx1 = fmaxf(mx1, __shfl_xor_sync(0xffffffffu, mx1, 1));
        mx1 = fmaxf(mx1, __shfl_xor_sync(0xffffffffu, mx1, 2));
        float nm0 = fmaxf(m0, mx0), nm1 = fmaxf(m1, mx1);
        float a0 = ex2f((m0 - nm0) * SC2), a1 = ex2f((m1 - nm1) * SC2);
        m0 = nm0; m1 = nm1;

        float s0 = 0.f, s1 = 0.f;
        #pragma unroll
        for (int nf = 0; nf < 8; nf++) {
            float p0 = ex2f((Sc[nf][0] - m0) * SC2);
            float p1 = ex2f((Sc[nf][1] - m0) * SC2);
            float p2 = ex2f((Sc[nf][2] - m1) * SC2);
            float p3 = ex2f((Sc[nf][3] - m1) * SC2);
            Sc[nf][0] = p0; Sc[nf][1] = p1; Sc[nf][2] = p2; Sc[nf][3] = p3;
            s0 += p0 + p1; s1 += p2 + p3;
        }
        s0 += __shfl_xor_sync(0xffffffffu, s0, 1);
        s0 += __shfl_xor_sync(0xffffffffu, s0, 2);
        s1 += __shfl_xor_sync(0xffffffffu, s1, 1);
        s1 += __shfl_xor_sync(0xffffffffu, s1, 2);
        rl0 = rl0 * a0 + s0;
        rl1 = rl1 * a1 + s1;

        #pragma unroll
        for (int df = 0; df < 16; df++) {
            O[df][0] *= a0; O[df][1] *= a0;
            O[df][2] *= a1; O[df][3] *= a1;
        }

        // ---- O += P V (3-pass split) ----
        #pragma unroll
        for (int kf = 0; kf < 4; kf++) {
            uint32_t Pha[4], Pla[4];
            split2(Sc[2*kf][0],   Sc[2*kf][1],   Pha[0], Pla[0]);
            split2(Sc[2*kf][2],   Sc[2*kf][3],   Pha[1], Pla[1]);
            split2(Sc[2*kf+1][0], Sc[2*kf+1][1], Pha[2], Pla[2]);
            split2(Sc[2*kf+1][2], Sc[2*kf+1][3], Pha[3], Pla[3]);
            #pragma unroll
            for (int df2 = 0; df2 < 8; df2++) {
                uint32_t vh4[4], vl4[4];
                ldsm4t(vh4, sVH + (uint32_t)((kf*16 + v_row) * 136) * 2 + df2*32 + v_colB);
                mma16816(O[2*df2],   Pha, vh4 + 0);
                mma16816(O[2*df2+1], Pha, vh4 + 2);
                mma16816(O[2*df2],   Pla, vh4 + 0);
                mma16816(O[2*df2+1], Pla, vh4 + 2);
                ldsm4t(vl4, sVL + (uint32_t)((kf*16 + v_row) * 136) * 2 + df2*32 + v_colB);
                mma16816(O[2*df2],   Pha, vl4 + 0);
                mma16816(O[2*df2+1], Pha, vl4 + 2);
            }
        }
    }

    // ---- epilogue ----
    float inv0 = 1.f / rl0, inv1 = 1.f / rl1;
    const size_t rowlo = (size_t)(b*LL + q0 + w*16 + gid) * DD + h * DHD + tig * 2;
    const size_t rowhi = rowlo + 8 * DD;
    #pragma unroll
    for (int df = 0; df < 16; df++) {
        uint32_t hv, lv;
        split2(O[df][0] * inv0, O[df][1] * inv0, hv, lv);
        *(uint32_t*)(Ch + rowlo + df*8) = hv;
        *(uint32_t*)(Cl + rowlo + df*8) = lv;
        split2(O[df][2] * inv1, O[df][3] * inv1, hv, lv);
        *(uint32_t*)(Ch + rowhi + df*8) = hv;
        *(uint32_t*)(Cl + rowhi + df*8) = lv;
    }
}

// ================================ launch ======================================
extern "C" void kernel_launch(void* const* d_in, const int* in_sizes, int n_in,
                              void* d_out, int out_size)
{
    const float* hidden    = (const float*)d_in[0];
    const float* relevance = (const float*)d_in[1];
    const float* Wqr       = (const float*)d_in[2];
    const float* Wkr       = (const float*)d_in[3];
    const float* Wq        = (const float*)d_in[4];
    const float* Wk        = (const float*)d_in[5];
    const float* Wv        = (const float*)d_in[6];
    const float* Wo        = (const float*)d_in[7];
    float* out = (float*)d_out;

    __half *hidh,*hidl,*wqh,*wql,*wkh,*wkl,*wvh,*wvl,*woh,*wol;
    __half *qh,*ql,*kh,*kl,*vh,*vl,*ctxh,*ctxl;
    float *qrel,*krel,*relp; unsigned* mask;
    cudaGetSymbolAddress((void**)&hidh, g_hidh); cudaGetSymbolAddress((void**)&hidl, g_hidl);
    cudaGetSymbolAddress((void**)&wqh,  g_wqh);  cudaGetSymbolAddress((void**)&wql,  g_wql);
    cudaGetSymbolAddress((void**)&wkh,  g_wkh);  cudaGetSymbolAddress((void**)&wkl,  g_wkl);
    cudaGetSymbolAddress((void**)&wvh,  g_wvh);  cudaGetSymbolAddress((void**)&wvl,  g_wvl);
    cudaGetSymbolAddress((void**)&woh,  g_woh);  cudaGetSymbolAddress((void**)&wol,  g_wol);
    cudaGetSymbolAddress((void**)&qh,   g_qh);   cudaGetSymbolAddress((void**)&ql,   g_ql);
    cudaGetSymbolAddress((void**)&kh,   g_kh);   cudaGetSymbolAddress((void**)&kl,   g_kl);
    cudaGetSymbolAddress((void**)&vh,   g_vh);   cudaGetSymbolAddress((void**)&vl,   g_vl);
    cudaGetSymbolAddress((void**)&ctxh, g_ctxh); cudaGetSymbolAddress((void**)&ctxl, g_ctxl);
    cudaGetSymbolAddress((void**)&qrel, g_qrel); cudaGetSymbolAddress((void**)&krel, g_krel);
    cudaGetSymbolAddress((void**)&relp, g_relp); cudaGetSymbolAddress((void**)&mask, g_mask);

    cudaFuncSetAttribute(gemm_qkv, cudaFuncAttributeMaxDynamicSharedMemorySize, GSMEM);
    cudaFuncSetAttribute(gemm_o,   cudaFuncAttributeMaxDynamicSharedMemorySize, GSMEM);
    cudaFuncSetAttribute(flash_mma, cudaFuncAttributeMaxDynamicSharedMemorySize, FSMEM);

    // fp32 -> hi/lo fp16 conversions
    const int nh4 = MROWS * DD / 4, nw4 = DD * DD / 4;
    cvt_split<<<(nh4 + 255)/256, 256>>>((const float4*)hidden, (uint2*)hidh, (uint2*)hidl, nh4);
    cvt_split<<<(nw4 + 255)/256, 256>>>((const float4*)Wq, (uint2*)wqh, (uint2*)wql, nw4);
    cvt_split<<<(nw4 + 255)/256, 256>>>((const float4*)Wk, (uint2*)wkh, (uint2*)wkl, nw4);
    cvt_split<<<(nw4 + 255)/256, 256>>>((const float4*)Wv, (uint2*)wvh, (uint2*)wvl, nw4);
    cvt_split<<<(nw4 + 255)/256, 256>>>((const float4*)Wo, (uint2*)woh, (uint2*)wol, nw4);

    // relevance path
    rel_proj<<<dim3(MROWS/64, 4), 256>>>(relevance, Wqr, Wkr, relp);
    rel_reduce<<<(MROWS*64)/256, 256>>>(relp, qrel, krel);
    build_mask<<<dim3(LL, BB), 256>>>(qrel, krel, mask);

    // fused QKV projections
    gemm_qkv<<<dim3(DD/128, MROWS/128, 3), 256, GSMEM>>>(
        hidh, hidl, wqh, wql, qh, ql, wkh, wkl, kh, kl, wvh, wvl, vh, vl);

    // attention
    flash_mma<<<dim3(LL/128, HH, BB), 256, FSMEM>>>(qh, ql, kh, kl, vh, vl, mask, ctxh, ctxl);

    // output projection
    gemm_o<<<dim3(DD/128, MROWS/128), 256, GSMEM>>>(ctxh, ctxl, woh, wol, out);
}

// round 6
// speedup vs baseline: 4.6466x; 1.4554x over previous
#include <cuda_runtime.h>
#include <cuda_fp16.h>
#include <cstdint>
#include <math.h>

// Problem constants
#define BB   2
#define LL   2048
#define DD   2048
#define HH   16
#define DHD  128
#define DREL 64
#define KSEL 512
#define MROWS (BB*LL)   // 4096

// -------------------- scratch (device globals; no cudaMalloc allowed) ---------
__device__ __align__(256) __half g_hidh[MROWS*DD];
__device__ __align__(256) __half g_hidl[MROWS*DD];
__device__ __align__(256) __half g_wqh [DD*DD];
__device__ __align__(256) __half g_wkh [DD*DD];
__device__ __align__(256) __half g_wvh [DD*DD];
__device__ __align__(256) __half g_woh [DD*DD];
__device__ __align__(256) __half g_qh  [MROWS*DD];
__device__ __align__(256) __half g_ql  [MROWS*DD];
__device__ __align__(256) __half g_kh  [MROWS*DD];
__device__ __align__(256) __half g_vh  [MROWS*DD];
__device__ __align__(256) __half g_ctxh[MROWS*DD];
__device__ __align__(256) __half g_ctxl[MROWS*DD];
__device__ __align__(256) float    g_qrel[BB*LL*DREL];
__device__ __align__(256) float    g_krel[BB*LL*DREL];
__device__ __align__(256) float    g_relp[4*MROWS*128];
__device__ __align__(256) unsigned g_mask[BB*LL*(LL/32)];

// ========================= inline PTX helpers =================================
__device__ __forceinline__ uint32_t smem_u32(const void* p) {
    uint32_t a;
    asm("{ .reg .u64 t; cvta.to.shared.u64 t, %1; cvt.u32.u64 %0, t; }" : "=r"(a) : "l"(p));
    return a;
}
__device__ __forceinline__ void ldsm4(uint32_t* r, uint32_t addr) {
    asm volatile("ldmatrix.sync.aligned.m8n8.x4.shared.b16 {%0,%1,%2,%3}, [%4];"
        : "=r"(r[0]), "=r"(r[1]), "=r"(r[2]), "=r"(r[3]) : "r"(addr));
}
__device__ __forceinline__ void ldsm4t(uint32_t* r, uint32_t addr) {
    asm volatile("ldmatrix.sync.aligned.m8n8.x4.trans.shared.b16 {%0,%1,%2,%3}, [%4];"
        : "=r"(r[0]), "=r"(r[1]), "=r"(r[2]), "=r"(r[3]) : "r"(addr));
}
__device__ __forceinline__ void mma16816(float* c, const uint32_t* a, const uint32_t* b) {
    asm volatile("mma.sync.aligned.m16n8k16.row.col.f32.f16.f16.f32 "
        "{%0,%1,%2,%3}, {%4,%5,%6,%7}, {%8,%9}, {%0,%1,%2,%3};"
        : "+f"(c[0]), "+f"(c[1]), "+f"(c[2]), "+f"(c[3])
        : "r"(a[0]), "r"(a[1]), "r"(a[2]), "r"(a[3]), "r"(b[0]), "r"(b[1]));
}
#define CP_ASYNC16(dst, src) \
    asm volatile("cp.async.cg.shared.global [%0], [%1], 16;" :: "r"(dst), "l"(src) : "memory")
#define CP_ASYNC8(dst, src) \
    asm volatile("cp.async.ca.shared.global [%0], [%1], 8;" :: "r"(dst), "l"(src) : "memory")
#define CP_COMMIT() asm volatile("cp.async.commit_group;" ::: "memory")
#define CP_WAIT(n)  asm volatile("cp.async.wait_group %0;" :: "n"(n) : "memory")

__device__ __forceinline__ float ex2f(float x) {
    float y; asm("ex2.approx.f32 %0, %1;" : "=f"(y) : "f"(x)); return y;
}
__device__ __forceinline__ void split2(float x, float y, uint32_t& hi, uint32_t& lo) {
    __half hx = __float2half_rn(x), hy = __float2half_rn(y);
    __half lx = __float2half_rn(x - __half2float(hx));
    __half ly = __float2half_rn(y - __half2float(hy));
    hi = ((uint32_t)__half_as_ushort(hy) << 16) | __half_as_ushort(hx);
    lo = ((uint32_t)__half_as_ushort(ly) << 16) | __half_as_ushort(lx);
}
__device__ __forceinline__ uint32_t pack_h2(float x, float y) {
    __half hx = __float2half_rn(x), hy = __float2half_rn(y);
    return ((uint32_t)__half_as_ushort(hy) << 16) | __half_as_ushort(hx);
}

// =========================== fp32 -> fp16 conversions =========================
__global__ __launch_bounds__(256) void cvt_split(
    const float4* __restrict__ x, uint2* __restrict__ h, uint2* __restrict__ lo, int n4)
{
    int i = blockIdx.x * 256 + threadIdx.x;
    if (i >= n4) return;
    float4 v = x[i];
    uint32_t h0, l0, h1, l1;
    split2(v.x, v.y, h0, l0);
    split2(v.z, v.w, h1, l1);
    h[i]  = make_uint2(h0, h1);
    lo[i] = make_uint2(l0, l1);
}

__global__ __launch_bounds__(256) void cvt_hi(
    const float4* __restrict__ x, uint2* __restrict__ h, int n4)
{
    int i = blockIdx.x * 256 + threadIdx.x;
    if (i >= n4) return;
    float4 v = x[i];
    h[i] = make_uint2(pack_h2(v.x, v.y), pack_h2(v.z, v.w));
}

// ===== 2-pass fp16-split GEMM: C = (Ah+Al) · Bh^T, CTA 128x128, kc 32 =========
#define SEGB 10240              // bytes per segment (128 rows x 40 halves)
#define STB  (3*SEGB)           // stage: Ah, Al, Bh
#define GSMEM (3*STB)           // 92160 B

// OUTMODE: 0 = hi+lo fp16 out, 1 = hi fp16 out, 2 = fp32 out
template<int OUTMODE>
__device__ __forceinline__ void gemm_body(
    const __half* __restrict__ Ah, const __half* __restrict__ Al,
    const __half* __restrict__ Bh,
    float* __restrict__ Cf, __half* __restrict__ Ch, __half* __restrict__ Cl,
    __half* GS)
{
    const uint32_t base = smem_u32(GS);
    const int tid = threadIdx.x;
    const int l   = tid & 31;
    const int wid = tid >> 5;
    const int wm  = wid >> 2;
    const int wn  = wid & 3;
    const int bm  = blockIdx.y * 128;
    const int bn  = blockIdx.x * 128;

    const __half* segsrc[3] = {Ah + (size_t)bm * DD, Al + (size_t)bm * DD,
                               Bh + (size_t)bn * DD};

    const int rA = wm * 64 + ((l >> 3) & 1) * 8 + (l & 7);
    const int kA = (l >> 4) * 16;
    const int rB = wn * 32 + ((l >> 4) & 1) * 8 + (l & 7);
    const int kB = ((l >> 3) & 1) * 16;

    float acc[4][4][4];
    #pragma unroll
    for (int i = 0; i < 4; i++)
        #pragma unroll
        for (int j = 0; j < 4; j++)
            #pragma unroll
            for (int t = 0; t < 4; t++) acc[i][j][t] = 0.f;

    auto issue_stage = [&](int c, int st) {
        #pragma unroll
        for (int j = 0; j < 6; j++) {
            int idx = tid + j * 256;          // 1536 float4 per stage
            int seg = idx >> 9, rem = idx & 511;
            int row = rem >> 2, c16 = rem & 3;
            uint32_t dst = base + (uint32_t)(st * 3 + seg) * SEGB + (uint32_t)row * 80 + c16 * 16;
            const __half* src = segsrc[seg] + (size_t)row * DD + c * 32 + c16 * 8;
            CP_ASYNC16(dst, src);
        }
        CP_COMMIT();
    };

    issue_stage(0, 0);
    issue_stage(1, 1);

    for (int c = 0; c < DD / 32; c++) {
        CP_WAIT(1);
        __syncthreads();
        if (c + 2 < DD / 32) issue_stage(c + 2, (c + 2) % 3);
        else CP_COMMIT();

        const int st = c % 3;
        const uint32_t sAh = base + (uint32_t)(st * 3 + 0) * SEGB;
        const uint32_t sAl = base + (uint32_t)(st * 3 + 1) * SEGB;
        const uint32_t sBh = base + (uint32_t)(st * 3 + 2) * SEGB;

        #pragma unroll
        for (int ks = 0; ks < 2; ks++) {
            uint32_t aH[4][4], aL[4][4];
            #pragma unroll
            for (int mf = 0; mf < 4; mf++) {
                ldsm4(aH[mf], sAh + (uint32_t)(rA + mf*16) * 80 + kA + ks*32);
                ldsm4(aL[mf], sAl + (uint32_t)(rA + mf*16) * 80 + kA + ks*32);
            }
            #pragma unroll
            for (int nf2 = 0; nf2 < 2; nf2++) {
                uint32_t bH[4];
                ldsm4(bH, sBh + (uint32_t)(rB + nf2*16) * 80 + kB + ks*32);
                #pragma unroll
                for (int mf = 0; mf < 4; mf++) {
                    mma16816(acc[mf][2*nf2],   aH[mf], bH + 0);
                    mma16816(acc[mf][2*nf2+1], aH[mf], bH + 2);
                    mma16816(acc[mf][2*nf2],   aL[mf], bH + 0);
                    mma16816(acc[mf][2*nf2+1], aL[mf], bH + 2);
                }
            }
        }
    }

    const int gid = l >> 2, tig = l & 3;
    #pragma unroll
    for (int mf = 0; mf < 4; mf++) {
        #pragma unroll
        for (int nf = 0; nf < 4; nf++) {
            int r0 = bm + wm*64 + mf*16 + gid;
            int cc = bn + wn*32 + nf*8 + tig*2;
            if (OUTMODE == 2) {
                *(float2*)(Cf + (size_t)r0 * DD + cc)       = make_float2(acc[mf][nf][0], acc[mf][nf][1]);
                *(float2*)(Cf + (size_t)(r0 + 8) * DD + cc) = make_float2(acc[mf][nf][2], acc[mf][nf][3]);
            } else if (OUTMODE == 1) {
                *(uint32_t*)(Ch + (size_t)r0 * DD + cc)       = pack_h2(acc[mf][nf][0], acc[mf][nf][1]);
                *(uint32_t*)(Ch + (size_t)(r0 + 8) * DD + cc) = pack_h2(acc[mf][nf][2], acc[mf][nf][3]);
            } else {
                uint32_t h0, l0v, h1, l1v;
                split2(acc[mf][nf][0], acc[mf][nf][1], h0, l0v);
                split2(acc[mf][nf][2], acc[mf][nf][3], h1, l1v);
                *(uint32_t*)(Ch + (size_t)r0 * DD + cc)       = h0;
                *(uint32_t*)(Cl + (size_t)r0 * DD + cc)       = l0v;
                *(uint32_t*)(Ch + (size_t)(r0 + 8) * DD + cc) = h1;
                *(uint32_t*)(Cl + (size_t)(r0 + 8) * DD + cc) = l1v;
            }
        }
    }
}

__global__ __launch_bounds__(256) void gemm_qkv(
    const __half* __restrict__ Ah, const __half* __restrict__ Al,
    const __half* __restrict__ Wqh, __half* __restrict__ Qh, __half* __restrict__ Ql,
    const __half* __restrict__ Wkh, __half* __restrict__ Kh,
    const __half* __restrict__ Wvh, __half* __restrict__ Vh)
{
    extern __shared__ __half GS[];
    if (blockIdx.z == 0)
        gemm_body<0>(Ah, Al, Wqh, nullptr, Qh, Ql, GS);
    else if (blockIdx.z == 1)
        gemm_body<1>(Ah, Al, Wkh, nullptr, Kh, nullptr, GS);
    else
        gemm_body<1>(Ah, Al, Wvh, nullptr, Vh, nullptr, GS);
}

__global__ __launch_bounds__(256) void gemm_o(
    const __half* __restrict__ Ah, const __half* __restrict__ Al,
    const __half* __restrict__ Bh, float* __restrict__ Cf)
{
    extern __shared__ __half GS[];
    gemm_body<2>(Ah, Al, Bh, Cf, nullptr, nullptr, GS);
}

// ===================== rel projection (split-K, fused q/k) ====================
__global__ __launch_bounds__(256) void rel_proj(
    const float* __restrict__ A, const float* __restrict__ Wq,
    const float* __restrict__ Wk, float* __restrict__ part)
{
    __shared__ __align__(16) float As[32][65];
    __shared__ __align__(16) float Ws[32][132];
    const int tid = threadIdx.x;
    const int m0 = blockIdx.x * 64;
    const int kb = blockIdx.y * 512;
    const int r0 = (tid >> 5) * 8;
    const int c0 = (tid & 31) * 4;

    float acc[8][4];
    #pragma unroll
    for (int i = 0; i < 8; i++)
        #pragma unroll
        for (int j = 0; j < 4; j++) acc[i][j] = 0.f;

    for (int k0 = 0; k0 < 512; k0 += 32) {
        #pragma unroll
        for (int t = 0; t < 2; t++) {
            int idx = tid + t * 256;
            int row = idx >> 3, gg = idx & 7;
            float4 v = *(const float4*)(A + (size_t)(m0 + row) * DD + kb + k0 + gg * 4);
            As[gg*4+0][row] = v.x; As[gg*4+1][row] = v.y;
            As[gg*4+2][row] = v.z; As[gg*4+3][row] = v.w;
        }
        #pragma unroll
        for (int t = 0; t < 4; t++) {
            int idx = tid + t * 256;
            int col = idx >> 3, gg = idx & 7;
            const float* src = (col < 64) ? (Wq + (size_t)col * DD)
                                          : (Wk + (size_t)(col - 64) * DD);
            float4 v = *(const float4*)(src + kb + k0 + gg * 4);
            Ws[gg*4+0][col] = v.x; Ws[gg*4+1][col] = v.y;
            Ws[gg*4+2][col] = v.z; Ws[gg*4+3][col] = v.w;
        }
        __syncthreads();
        #pragma unroll 8
        for (int kk = 0; kk < 32; kk++) {
            float4 w = *(const float4*)&Ws[kk][c0];
            #pragma unroll
            for (int i = 0; i < 8; i++) {
                float a = As[kk][r0 + i];
                acc[i][0] += a * w.x; acc[i][1] += a * w.y;
                acc[i][2] += a * w.z; acc[i][3] += a * w.w;
            }
        }
        __syncthreads();
    }
    float* dst = part + (size_t)blockIdx.y * MROWS * 128;
    #pragma unroll
    for (int i = 0; i < 8; i++) {
        float4 o = make_float4(acc[i][0], acc[i][1], acc[i][2], acc[i][3]);
        *(float4*)(dst + (size_t)(m0 + r0 + i) * 128 + c0) = o;
    }
}

__global__ __launch_bounds__(256) void rel_reduce(
    const float* __restrict__ part, float* __restrict__ qrel, float* __restrict__ krel)
{
    int idx = blockIdx.x * 256 + threadIdx.x;
    int row = idx >> 6, col = idx & 63;
    float sq = 0.f, sk = 0.f;
    #pragma unroll
    for (int s = 0; s < 4; s++) {
        const float* p = part + (size_t)s * MROWS * 128 + (size_t)row * 128;
        sq += p[col]; sk += p[col + 64];
    }
    qrel[(size_t)row * 64 + col] = sq;
    krel[(size_t)row * 64 + col] = sk;
}

// ====================== top-K mask build (one block per (b,q)) ================
__device__ __forceinline__ unsigned ford(float f) {
    unsigned u = __float_as_uint(f);
    return (u & 0x80000000u) ? ~u : (u | 0x80000000u);
}

__global__ __launch_bounds__(256) void build_mask(
    const float* __restrict__ qrel, const float* __restrict__ krel,
    unsigned* __restrict__ mask)
{
    const int q = blockIdx.x;
    const int b = blockIdx.y;
    const int tid = threadIdx.x;

    __shared__ float    s[LL];
    __shared__ unsigned mw[LL/32];
    __shared__ float    qv[DREL];
    __shared__ int      hist[256];
    __shared__ int      scan[256];
    __shared__ unsigned sh_prefix;
    __shared__ int      sh_R;

    if (tid < DREL) qv[tid] = qrel[(size_t)(b*LL + q)*DREL + tid];
    if (tid < LL/32) mw[tid] = 0u;
    __syncthreads();

    const int n = q + 1;
    for (int k = tid; k < n; k += 256) {
        const float4* kr = (const float4*)&krel[(size_t)(b*LL + k)*DREL];
        float acc = 0.f;
        #pragma unroll
        for (int j = 0; j < 16; j++) {
            float4 v = kr[j];
            acc += qv[j*4+0]*v.x + qv[j*4+1]*v.y + qv[j*4+2]*v.z + qv[j*4+3]*v.w;
        }
        s[k] = acc;
    }
    __syncthreads();

    if (n <= KSEL) {
        for (int k = tid; k < n; k += 256)
            atomicOr(&mw[k>>5], 1u << (k & 31));
    } else {
        unsigned prefix = 0u; int R = KSEL;
        for (int byte = 3; byte >= 0; byte--) {
            hist[tid] = 0;
            __syncthreads();
            const int shift = byte * 8;
            const unsigned pm = (byte == 3) ? 0u : (0xFFFFFFFFu << (shift + 8));
            for (int k = tid; k < n; k += 256) {
                unsigned u = ford(s[k]);
                if ((u & pm) == (prefix & pm))
                    atomicAdd(&hist[(u >> shift) & 255], 1);
            }
            __syncthreads();
            int hv = hist[tid];
            scan[tid] = hv;
            __syncthreads();
            #pragma unroll
            for (int off = 1; off < 256; off <<= 1) {
                int t = (tid + off < 256) ? scan[tid + off] : 0;
                __syncthreads();
                scan[tid] += t;
                __syncthreads();
            }
            int inc = scan[tid];
            int above = inc - hv;
            if (above < R && inc >= R) {
                sh_prefix = prefix | ((unsigned)tid << shift);
                sh_R = R - above;
            }
            __syncthreads();
            prefix = sh_prefix; R = sh_R;
            __syncthreads();
        }
        const unsigned T = prefix;
        for (int k = tid; k < n; k += 256)
            if (ford(s[k]) > T) atomicOr(&mw[k>>5], 1u << (k & 31));
        const int per = (n + 255) >> 8;
        const int lo = tid * per;
        const int hi = (lo + per < n) ? lo + per : n;
        int cnt = 0;
        for (int k = lo; k < hi; k++)
            if (ford(s[k]) == T) cnt++;
        scan[tid] = cnt;
        __syncthreads();
        #pragma unroll
        for (int off = 1; off < 256; off <<= 1) {
            int t = (tid >= off) ? scan[tid - off] : 0;
            __syncthreads();
            scan[tid] += t;
            __syncthreads();
        }
        int excl = scan[tid] - cnt;
        int r2 = R - excl;
        if (r2 > 0) {
            for (int k = lo; k < hi && r2 > 0; k++)
                if (ford(s[k]) == T) { atomicOr(&mw[k>>5], 1u << (k & 31)); r2--; }
        }
    }
    __syncthreads();
    if (tid == 0) mw[q>>5] |= 1u << (q & 31);
    __syncthreads();
    if (tid < LL/32) mask[(size_t)(b*LL + q)*(LL/32) + tid] = mw[tid];
}

// ====================== flash attention (2-pass fp16 mma) =====================
// 8 warps, Q-tile 128 rows (hi+lo), K/V tiles 64 (hi only), double-buffered.
#define QSEG 17408      // 128*136 halves
#define KSEG 8704       // 64*136 halves
#define FOFF_QH 0
#define FOFF_QL QSEG
#define KVOFF(st, seg) (2*QSEG + (st)*2*KSEG + (seg)*KSEG)
#define FMASK_B ((2*QSEG + 4*KSEG)*2)          // byte offset of mask buffers
#define FSMEM   (FMASK_B + 2*1024)
#define SC2 0.12751744416168355f               // (1/sqrt(128)) * log2(e)

__global__ __launch_bounds__(256) void flash_mma(
    const __half* __restrict__ Qh, const __half* __restrict__ Ql,
    const __half* __restrict__ Kh, const __half* __restrict__ Vh,
    const unsigned* __restrict__ mask,
    __half* __restrict__ Ch, __half* __restrict__ Cl)
{
    extern __shared__ __half FS[];
    const uint32_t base = smem_u32(FS);
    const uint32_t maskB = base + FMASK_B;

    const int qt = blockIdx.x, h = blockIdx.y, b = blockIdx.z;
    const int q0 = qt * 128;
    const int tid = threadIdx.x;
    const int w = tid >> 5, l = tid & 31;
    const int gid = l >> 2, tig = l & 3;

    // Q load (one-time): 2 segs x 128 rows x 16 chunks = 4096 -> 16/thread
    {
        const __half* qs[2] = {Qh, Ql};
        #pragma unroll
        for (int j = 0; j < 16; j++) {
            int idx = tid + j * 256;
            int seg = idx >> 11, rem = idx & 2047;
            int row = rem >> 4, c16 = rem & 15;
            uint32_t dst = base + (uint32_t)(seg * QSEG + row * 136 + c16 * 8) * 2;
            const __half* src = qs[seg] + (size_t)(b*LL + q0 + row) * DD + h * DHD + c16 * 8;
            CP_ASYNC16(dst, src);
        }
        CP_COMMIT();
    }

    auto issue_kv = [&](int kt, int st) {
        const __half* ks[2] = {Kh, Vh};
        #pragma unroll
        for (int j = 0; j < 8; j++) {
            int idx = tid + j * 256;           // 2048 float4
            int seg = idx >> 10, rem = idx & 1023;
            int row = rem >> 4, c16 = rem & 15;
            uint32_t dst = base + (uint32_t)(KVOFF(st, seg) + row * 136 + c16 * 8) * 2;
            const __half* src = ks[seg] + (size_t)(b*LL + kt*64 + row) * DD + h * DHD + c16 * 8;
            CP_ASYNC16(dst, src);
        }
        if (tid < 128) {
            uint32_t dst = maskB + st * 1024 + tid * 8;
            const unsigned* src = &mask[(size_t)(b*LL + q0 + tid) * (LL/32) + kt*2];
            CP_ASYNC8(dst, src);
        }
        CP_COMMIT();
    };

    issue_kv(0, 0);

    const int qa_row = w * 16 + ((l >> 3) & 1) * 8 + (l & 7);
    const int qa_colB = (l >> 4) * 16;
    const int kb_rowBase = ((l >> 4) & 1) * 8 + (l & 7);
    const int kb_colB = ((l >> 3) & 1) * 16;
    const int v_row = l & 15;
    const int v_colB = (l >> 4) * 16;

    float O[16][4];
    #pragma unroll
    for (int i = 0; i < 16; i++)
        #pragma unroll
        for (int t = 0; t < 4; t++) O[i][t] = 0.f;
    float m0 = -1e30f, m1 = -1e30f, rl0 = 0.f, rl1 = 0.f;

    const int rlo2 = (w*16 + gid) * 2;
    const int rhi2 = rlo2 + 16;

    const int ktiles = 2 * qt + 2;
    for (int kt = 0; kt < ktiles; kt++) {
        const int st = kt & 1;
        if (kt + 1 < ktiles) {
            __syncthreads();
            issue_kv(kt + 1, st ^ 1);
            CP_WAIT(1);
        } else {
            CP_WAIT(0);
        }
        __syncthreads();

        const uint32_t sKH = base + (uint32_t)KVOFF(st, 0) * 2;
        const uint32_t sVH = base + (uint32_t)KVOFF(st, 1) * 2;
        const uint32_t* maskS = (const uint32_t*)(FS) + (FMASK_B >> 2) + st * 256;

        // ---- S = Q K^T (2-pass: Qh·Kh + Ql·Kh) ----
        float Sc[8][4];
        #pragma unroll
        for (int i = 0; i < 8; i++)
            #pragma unroll
            for (int t = 0; t < 4; t++) Sc[i][t] = 0.f;

        #pragma unroll
        for (int kf = 0; kf < 8; kf++) {
            uint32_t aH[4], aL[4];
            ldsm4(aH, base + (uint32_t)(FOFF_QH + qa_row * 136) * 2 + kf*32 + qa_colB);
            ldsm4(aL, base + (uint32_t)(FOFF_QL + qa_row * 136) * 2 + kf*32 + qa_colB);
            #pragma unroll
            for (int nf2 = 0; nf2 < 4; nf2++) {
                uint32_t bH[4];
                ldsm4(bH, sKH + (uint32_t)((nf2*16 + kb_rowBase) * 136) * 2 + kf*32 + kb_colB);
                mma16816(Sc[2*nf2],   aH, bH + 0);
                mma16816(Sc[2*nf2+1], aH, bH + 2);
                mma16816(Sc[2*nf2],   aL, bH + 0);
                mma16816(Sc[2*nf2+1], aL, bH + 2);
            }
        }

        // ---- mask ----
        #pragma unroll
        for (int nf = 0; nf < 8; nf++) {
            unsigned wlo = maskS[rlo2 + (nf >> 2)];
            unsigned whi = maskS[rhi2 + (nf >> 2)];
            int sh = ((nf & 3) << 3) + (tig << 1);
            Sc[nf][0] = ((wlo >> sh) & 1u)     ? Sc[nf][0] : -1e30f;
            Sc[nf][1] = ((wlo >> (sh+1)) & 1u) ? Sc[nf][1] : -1e30f;
            Sc[nf][2] = ((whi >> sh) & 1u)     ? Sc[nf][2] : -1e30f;
            Sc[nf][3] = ((whi >> (sh+1)) & 1u) ? Sc[nf][3] : -1e30f;
        }

        // ---- online softmax ----
        float mx0 = -1e30f, mx1 = -1e30f;
        #pragma unroll
        for (int nf = 0; nf < 8; nf++) {
            mx0 = fmaxf(mx0, fmaxf(Sc[nf][0], Sc[nf][1]));
            mx1 = fmaxf(mx1, fmaxf(Sc[nf][2], Sc[nf][3]));
        }
        mx0 = fmaxf(mx0, __shfl_xor_sync(0xffffffffu, mx0, 1));
        mx0 = fmaxf(mx0, __shfl_xor_sync(0xffffffffu, mx0, 2));
        mx1 = fmaxf(mx1, __shfl_xor_sync(0xffffffffu, mx1, 1));
        mx1 = fmaxf(mx1, __shfl_xor_sync(0xffffffffu, mx1, 2));
        float nm0 = fmaxf(m0, mx0), nm1 = fmaxf(m1, mx1);
        float a0 = ex2f((m0 - nm0) * SC2), a1 = ex2f((m1 - nm1) * SC2);
        m0 = nm0; m1 = nm1;

        float s0 = 0.f, s1 = 0.f;
        #pragma unroll
        for (int nf = 0; nf < 8; nf++) {
            float p0 = ex2f((Sc[nf][0] - m0) * SC2);
            float p1 = ex2f((Sc[nf][1] - m0) * SC2);
            float p2 = ex2f((Sc[nf][2] - m1) * SC2);
            float p3 = ex2f((Sc[nf][3] - m1) * SC2);
            Sc[nf][0] = p0; Sc[nf][1] = p1; Sc[nf][2] = p2; Sc[nf][3] = p3;
            s0 += p0 + p1; s1 += p2 + p3;
        }
        s0 += __shfl_xor_sync(0xffffffffu, s0, 1);
        s0 += __shfl_xor_sync(0xffffffffu, s0, 2);
        s1 += __shfl_xor_sync(0xffffffffu, s1, 1);
        s1 += __shfl_xor_sync(0xffffffffu, s1, 2);
        rl0 = rl0 * a0 + s0;
        rl1 = rl1 * a1 + s1;

        #pragma unroll
        for (int df = 0; df < 16; df++) {
            O[df][0] *= a0; O[df][1] *= a0;
            O[df][2] *= a1; O[df][3] *= a1;
        }

        // ---- O += P V (2-pass: Ph·Vh + Pl·Vh) ----
        #pragma unroll
        for (int kf = 0; kf < 4; kf++) {
            uint32_t Pha[4], Pla[4];
            split2(Sc[2*kf][0],   Sc[2*kf][1],   Pha[0], Pla[0]);
            split2(Sc[2*kf][2],   Sc[2*kf][3],   Pha[1], Pla[1]);
            split2(Sc[2*kf+1][0], Sc[2*kf+1][1], Pha[2], Pla[2]);
            split2(Sc[2*kf+1][2], Sc[2*kf+1][3], Pha[3], Pla[3]);
            #pragma unroll
            for (int df2 = 0; df2 < 8; df2++) {
                uint32_t vh4[4];
                ldsm4t(vh4, sVH + (uint32_t)((kf*16 + v_row) * 136) * 2 + df2*32 + v_colB);
                mma16816(O[2*df2],   Pha, vh4 + 0);
                mma16816(O[2*df2+1], Pha, vh4 + 2);
                mma16816(O[2*df2],   Pla, vh4 + 0);
                mma16816(O[2*df2+1], Pla, vh4 + 2);
            }
        }
    }

    // ---- epilogue ----
    float inv0 = 1.f / rl0, inv1 = 1.f / rl1;
    const size_t rowlo = (size_t)(b*LL + q0 + w*16 + gid) * DD + h * DHD + tig * 2;
    const size_t rowhi = rowlo + 8 * DD;
    #pragma unroll
    for (int df = 0; df < 16; df++) {
        uint32_t hv, lv;
        split2(O[df][0] * inv0, O[df][1] * inv0, hv, lv);
        *(uint32_t*)(Ch + rowlo + df*8) = hv;
        *(uint32_t*)(Cl + rowlo + df*8) = lv;
        split2(O[df][2] * inv1, O[df][3] * inv1, hv, lv);
        *(uint32_t*)(Ch + rowhi + df*8) = hv;
        *(uint32_t*)(Cl + rowhi + df*8) = lv;
    }
}

// ================================ launch ======================================
extern "C" void kernel_launch(void* const* d_in, const int* in_sizes, int n_in,
                              void* d_out, int out_size)
{
    const float* hidden    = (const float*)d_in[0];
    const float* relevance = (const float*)d_in[1];
    const float* Wqr       = (const float*)d_in[2];
    const float* Wkr       = (const float*)d_in[3];
    const float* Wq        = (const float*)d_in[4];
    const float* Wk        = (const float*)d_in[5];
    const float* Wv        = (const float*)d_in[6];
    const float* Wo        = (const float*)d_in[7];
    float* out = (float*)d_out;

    __half *hidh,*hidl,*wqh,*wkh,*wvh,*woh;
    __half *qh,*ql,*kh,*vh,*ctxh,*ctxl;
    float *qrel,*krel,*relp; unsigned* mask;
    cudaGetSymbolAddress((void**)&hidh, g_hidh); cudaGetSymbolAddress((void**)&hidl, g_hidl);
    cudaGetSymbolAddress((void**)&wqh,  g_wqh);
    cudaGetSymbolAddress((void**)&wkh,  g_wkh);
    cudaGetSymbolAddress((void**)&wvh,  g_wvh);
    cudaGetSymbolAddress((void**)&woh,  g_woh);
    cudaGetSymbolAddress((void**)&qh,   g_qh);   cudaGetSymbolAddress((void**)&ql,   g_ql);
    cudaGetSymbolAddress((void**)&kh,   g_kh);
    cudaGetSymbolAddress((void**)&vh,   g_vh);
    cudaGetSymbolAddress((void**)&ctxh, g_ctxh); cudaGetSymbolAddress((void**)&ctxl, g_ctxl);
    cudaGetSymbolAddress((void**)&qrel, g_qrel); cudaGetSymbolAddress((void**)&krel, g_krel);
    cudaGetSymbolAddress((void**)&relp, g_relp); cudaGetSymbolAddress((void**)&mask, g_mask);

    cudaFuncSetAttribute(gemm_qkv, cudaFuncAttributeMaxDynamicSharedMemorySize, GSMEM);
    cudaFuncSetAttribute(gemm_o,   cudaFuncAttributeMaxDynamicSharedMemorySize, GSMEM);
    cudaFuncSetAttribute(flash_mma, cudaFuncAttributeMaxDynamicSharedMemorySize, FSMEM);

    // conversions: hidden -> hi+lo, weights -> hi only
    const int nh4 = MROWS * DD / 4, nw4 = DD * DD / 4;
    cvt_split<<<(nh4 + 255)/256, 256>>>((const float4*)hidden, (uint2*)hidh, (uint2*)hidl, nh4);
    cvt_hi<<<(nw4 + 255)/256, 256>>>((const float4*)Wq, (uint2*)wqh, nw4);
    cvt_hi<<<(nw4 + 255)/256, 256>>>((const float4*)Wk, (uint2*)wkh, nw4);
    cvt_hi<<<(nw4 + 255)/256, 256>>>((const float4*)Wv, (uint2*)wvh, nw4);
    cvt_hi<<<(nw4 + 255)/256, 256>>>((const float4*)Wo, (uint2*)woh, nw4);

    // relevance path (fp32, unchanged)
    rel_proj<<<dim3(MROWS/64, 4), 256>>>(relevance, Wqr, Wkr, relp);
    rel_reduce<<<(MROWS*64)/256, 256>>>(relp, qrel, krel);
    build_mask<<<dim3(LL, BB), 256>>>(qrel, krel, mask);

    // fused QKV projections
    gemm_qkv<<<dim3(DD/128, MROWS/128, 3), 256, GSMEM>>>(
        hidh, hidl, wqh, qh, ql, wkh, kh, wvh, vh);

    // attention
    flash_mma<<<dim3(LL/128, HH, BB), 256, FSMEM>>>(qh, ql, kh, vh, mask, ctxh, ctxl);

    // output projection
    gemm_o<<<dim3(DD/128, MROWS/128), 256, GSMEM>>>(ctxh, ctxl, woh, out);
}

// round 7
// speedup vs baseline: 4.8291x; 1.0393x over previous
#include <cuda_runtime.h>
#include <cuda_fp16.h>
#include <cstdint>
#include <math.h>

// Problem constants
#define BB   2
#define LL   2048
#define DD   2048
#define HH   16
#define DHD  128
#define DREL 64
#define KSEL 512
#define MROWS (BB*LL)   // 4096

// -------------------- scratch (device globals; no cudaMalloc allowed) ---------
__device__ __align__(256) __half g_hidh[MROWS*DD];
__device__ __align__(256) __half g_hidl[MROWS*DD];
__device__ __align__(256) __half g_wqh [DD*DD];
__device__ __align__(256) __half g_wkh [DD*DD];
__device__ __align__(256) __half g_wvh [DD*DD];
__device__ __align__(256) __half g_woh [DD*DD];
__device__ __align__(256) __half g_qh  [MROWS*DD];
__device__ __align__(256) __half g_ql  [MROWS*DD];
__device__ __align__(256) __half g_kh  [MROWS*DD];
__device__ __align__(256) __half g_vh  [MROWS*DD];
__device__ __align__(256) __half g_ctxh[MROWS*DD];
__device__ __align__(256) __half g_ctxl[MROWS*DD];
__device__ __align__(256) float    g_qrel[BB*LL*DREL];
__device__ __align__(256) float    g_krel[BB*LL*DREL];
__device__ __align__(256) float    g_relp[4*MROWS*128];
__device__ __align__(256) unsigned g_mask[BB*LL*(LL/32)];

// ========================= inline PTX helpers =================================
__device__ __forceinline__ uint32_t smem_u32(const void* p) {
    uint32_t a;
    asm("{ .reg .u64 t; cvta.to.shared.u64 t, %1; cvt.u32.u64 %0, t; }" : "=r"(a) : "l"(p));
    return a;
}
__device__ __forceinline__ void ldsm4(uint32_t* r, uint32_t addr) {
    asm volatile("ldmatrix.sync.aligned.m8n8.x4.shared.b16 {%0,%1,%2,%3}, [%4];"
        : "=r"(r[0]), "=r"(r[1]), "=r"(r[2]), "=r"(r[3]) : "r"(addr));
}
__device__ __forceinline__ void ldsm4t(uint32_t* r, uint32_t addr) {
    asm volatile("ldmatrix.sync.aligned.m8n8.x4.trans.shared.b16 {%0,%1,%2,%3}, [%4];"
        : "=r"(r[0]), "=r"(r[1]), "=r"(r[2]), "=r"(r[3]) : "r"(addr));
}
__device__ __forceinline__ void mma16816(float* c, const uint32_t* a, const uint32_t* b) {
    asm volatile("mma.sync.aligned.m16n8k16.row.col.f32.f16.f16.f32 "
        "{%0,%1,%2,%3}, {%4,%5,%6,%7}, {%8,%9}, {%0,%1,%2,%3};"
        : "+f"(c[0]), "+f"(c[1]), "+f"(c[2]), "+f"(c[3])
        : "r"(a[0]), "r"(a[1]), "r"(a[2]), "r"(a[3]), "r"(b[0]), "r"(b[1]));
}
#define CP_ASYNC16(dst, src) \
    asm volatile("cp.async.cg.shared.global [%0], [%1], 16;" :: "r"(dst), "l"(src) : "memory")
#define CP_ASYNC8(dst, src) \
    asm volatile("cp.async.ca.shared.global [%0], [%1], 8;" :: "r"(dst), "l"(src) : "memory")
#define CP_COMMIT() asm volatile("cp.async.commit_group;" ::: "memory")
#define CP_WAIT(n)  asm volatile("cp.async.wait_group %0;" :: "n"(n) : "memory")

__device__ __forceinline__ float ex2f(float x) {
    float y; asm("ex2.approx.f32 %0, %1;" : "=f"(y) : "f"(x)); return y;
}
__device__ __forceinline__ void split2(float x, float y, uint32_t& hi, uint32_t& lo) {
    __half hx = __float2half_rn(x), hy = __float2half_rn(y);
    __half lx = __float2half_rn(x - __half2float(hx));
    __half ly = __float2half_rn(y - __half2float(hy));
    hi = ((uint32_t)__half_as_ushort(hy) << 16) | __half_as_ushort(hx);
    lo = ((uint32_t)__half_as_ushort(ly) << 16) | __half_as_ushort(lx);
}
__device__ __forceinline__ uint32_t pack_h2(float x, float y) {
    __half hx = __float2half_rn(x), hy = __float2half_rn(y);
    return ((uint32_t)__half_as_ushort(hy) << 16) | __half_as_ushort(hx);
}

// =========================== fp32 -> fp16 conversions =========================
__global__ __launch_bounds__(256) void cvt_split(
    const float4* __restrict__ x, uint2* __restrict__ h, uint2* __restrict__ lo, int n4)
{
    int i = blockIdx.x * 256 + threadIdx.x;
    if (i >= n4) return;
    float4 v = x[i];
    uint32_t h0, l0, h1, l1;
    split2(v.x, v.y, h0, l0);
    split2(v.z, v.w, h1, l1);
    h[i]  = make_uint2(h0, h1);
    lo[i] = make_uint2(l0, l1);
}

__global__ __launch_bounds__(256) void cvt_hi(
    const float4* __restrict__ x, uint2* __restrict__ h, int n4)
{
    int i = blockIdx.x * 256 + threadIdx.x;
    if (i >= n4) return;
    float4 v = x[i];
    h[i] = make_uint2(pack_h2(v.x, v.y), pack_h2(v.z, v.w));
}

// merged 3-weight hi conversion (grid.y selects weight)
__global__ __launch_bounds__(256) void cvt_hi3(
    const float4* __restrict__ w0, const float4* __restrict__ w1, const float4* __restrict__ w2,
    uint2* __restrict__ h0, uint2* __restrict__ h1, uint2* __restrict__ h2, int n4)
{
    const float4* src = (blockIdx.y == 0) ? w0 : (blockIdx.y == 1) ? w1 : w2;
    uint2* dst        = (blockIdx.y == 0) ? h0 : (blockIdx.y == 1) ? h1 : h2;
    int i = blockIdx.x * 256 + threadIdx.x;
    if (i >= n4) return;
    float4 v = src[i];
    dst[i] = make_uint2(pack_h2(v.x, v.y), pack_h2(v.z, v.w));
}

// ===== 2-pass fp16-split GEMM: C = (Ah+Al) · Bh^T =============================
// CTA tile 128x256, warp tile 64x64 (8 warps), k-chunk 32, 3-stage cp.async.
#define SEGA 10240              // Ah/Al segment: 128 rows x 80B
#define SEGB2 20480             // Bh segment: 256 rows x 80B
#define STAGEB (2*SEGA + SEGB2) // 40960
#define GSMEM (3*STAGEB)        // 122880

// OUTMODE: 0 = hi+lo fp16 out, 1 = hi fp16 out, 2 = fp32 out
template<int OUTMODE>
__device__ __forceinline__ void gemm_body(
    const __half* __restrict__ Ah, const __half* __restrict__ Al,
    const __half* __restrict__ Bh,
    float* __restrict__ Cf, __half* __restrict__ Ch, __half* __restrict__ Cl,
    __half* GS)
{
    const uint32_t base = smem_u32(GS);
    const int tid = threadIdx.x;
    const int l   = tid & 31;
    const int wid = tid >> 5;
    const int wm  = wid >> 2;        // 0..1   (64-row slab)
    const int wn  = wid & 3;         // 0..3   (64-col slab)
    const int bm  = blockIdx.y * 128;
    const int bn  = blockIdx.x * 256;

    const __half* Ah_p = Ah + (size_t)bm * DD;
    const __half* Al_p = Al + (size_t)bm * DD;
    const __half* Bh_p = Bh + (size_t)bn * DD;

    const int rA = wm * 64 + ((l >> 3) & 1) * 8 + (l & 7);
    const int kA = (l >> 4) * 16;
    const int rB = wn * 64 + ((l >> 4) & 1) * 8 + (l & 7);
    const int kB = ((l >> 3) & 1) * 16;

    float acc[4][8][4];
    #pragma unroll
    for (int i = 0; i < 4; i++)
        #pragma unroll
        for (int j = 0; j < 8; j++)
            #pragma unroll
            for (int t = 0; t < 4; t++) acc[i][j][t] = 0.f;

    auto issue_stage = [&](int c, int st) {
        const uint32_t stb = base + (uint32_t)st * STAGEB;
        #pragma unroll
        for (int j = 0; j < 8; j++) {
            int idx = tid + j * 256;           // 2048 float4 per stage
            uint32_t dst; const __half* src;
            if (j < 2) {                       // Ah: idx 0..511
                int row = idx >> 2, c16 = idx & 3;
                dst = stb + (uint32_t)row * 80 + c16 * 16;
                src = Ah_p + (size_t)row * DD + c * 32 + c16 * 8;
            } else if (j < 4) {                // Al: idx 512..1023
                int rem = idx - 512;
                int row = rem >> 2, c16 = rem & 3;
                dst = stb + SEGA + (uint32_t)row * 80 + c16 * 16;
                src = Al_p + (size_t)row * DD + c * 32 + c16 * 8;
            } else {                           // Bh: idx 1024..2047
                int rem = idx - 1024;
                int row = rem >> 2, c16 = rem & 3;
                dst = stb + 2*SEGA + (uint32_t)row * 80 + c16 * 16;
                src = Bh_p + (size_t)row * DD + c * 32 + c16 * 8;
            }
            CP_ASYNC16(dst, src);
        }
        CP_COMMIT();
    };

    issue_stage(0, 0);
    issue_stage(1, 1);

    for (int c = 0; c < DD / 32; c++) {
        CP_WAIT(1);
        __syncthreads();
        if (c + 2 < DD / 32) issue_stage(c + 2, (c + 2) % 3);
        else CP_COMMIT();

        const int st = c % 3;
        const uint32_t sAh = base + (uint32_t)st * STAGEB;
        const uint32_t sAl = sAh + SEGA;
        const uint32_t sBh = sAh + 2*SEGA;

        #pragma unroll
        for (int ks = 0; ks < 2; ks++) {
            uint32_t aH[4][4], aL[4][4];
            #pragma unroll
            for (int mf = 0; mf < 4; mf++) {
                ldsm4(aH[mf], sAh + (uint32_t)(rA + mf*16) * 80 + kA + ks*32);
                ldsm4(aL[mf], sAl + (uint32_t)(rA + mf*16) * 80 + kA + ks*32);
            }
            #pragma unroll
            for (int nf4 = 0; nf4 < 4; nf4++) {
                uint32_t bH[4];
                ldsm4(bH, sBh + (uint32_t)(rB + nf4*16) * 80 + kB + ks*32);
                #pragma unroll
                for (int mf = 0; mf < 4; mf++) {
                    mma16816(acc[mf][2*nf4],   aH[mf], bH + 0);
                    mma16816(acc[mf][2*nf4+1], aH[mf], bH + 2);
                    mma16816(acc[mf][2*nf4],   aL[mf], bH + 0);
                    mma16816(acc[mf][2*nf4+1], aL[mf], bH + 2);
                }
            }
        }
    }

    const int gid = l >> 2, tig = l & 3;
    #pragma unroll
    for (int mf = 0; mf < 4; mf++) {
        #pragma unroll
        for (int nf = 0; nf < 8; nf++) {
            int r0 = bm + wm*64 + mf*16 + gid;
            int cc = bn + wn*64 + nf*8 + tig*2;
            if (OUTMODE == 2) {
                *(float2*)(Cf + (size_t)r0 * DD + cc)       = make_float2(acc[mf][nf][0], acc[mf][nf][1]);
                *(float2*)(Cf + (size_t)(r0 + 8) * DD + cc) = make_float2(acc[mf][nf][2], acc[mf][nf][3]);
            } else if (OUTMODE == 1) {
                *(uint32_t*)(Ch + (size_t)r0 * DD + cc)       = pack_h2(acc[mf][nf][0], acc[mf][nf][1]);
                *(uint32_t*)(Ch + (size_t)(r0 + 8) * DD + cc) = pack_h2(acc[mf][nf][2], acc[mf][nf][3]);
            } else {
                uint32_t h0, l0v, h1, l1v;
                split2(acc[mf][nf][0], acc[mf][nf][1], h0, l0v);
                split2(acc[mf][nf][2], acc[mf][nf][3], h1, l1v);
                *(uint32_t*)(Ch + (size_t)r0 * DD + cc)       = h0;
                *(uint32_t*)(Cl + (size_t)r0 * DD + cc)       = l0v;
                *(uint32_t*)(Ch + (size_t)(r0 + 8) * DD + cc) = h1;
                *(uint32_t*)(Cl + (size_t)(r0 + 8) * DD + cc) = l1v;
            }
        }
    }
}

__global__ __launch_bounds__(256) void gemm_qkv(
    const __half* __restrict__ Ah, const __half* __restrict__ Al,
    const __half* __restrict__ Wqh, __half* __restrict__ Qh, __half* __restrict__ Ql,
    const __half* __restrict__ Wkh, __half* __restrict__ Kh,
    const __half* __restrict__ Wvh, __half* __restrict__ Vh)
{
    extern __shared__ __half GS[];
    if (blockIdx.z == 0)
        gemm_body<0>(Ah, Al, Wqh, nullptr, Qh, Ql, GS);
    else if (blockIdx.z == 1)
        gemm_body<1>(Ah, Al, Wkh, nullptr, Kh, nullptr, GS);
    else
        gemm_body<1>(Ah, Al, Wvh, nullptr, Vh, nullptr, GS);
}

__global__ __launch_bounds__(256) void gemm_o(
    const __half* __restrict__ Ah, const __half* __restrict__ Al,
    const __half* __restrict__ Bh, float* __restrict__ Cf)
{
    extern __shared__ __half GS[];
    gemm_body<2>(Ah, Al, Bh, Cf, nullptr, nullptr, GS);
}

// ===================== rel projection (split-K, fused q/k) ====================
__global__ __launch_bounds__(256) void rel_proj(
    const float* __restrict__ A, const float* __restrict__ Wq,
    const float* __restrict__ Wk, float* __restrict__ part)
{
    __shared__ __align__(16) float As[32][65];
    __shared__ __align__(16) float Ws[32][132];
    const int tid = threadIdx.x;
    const int m0 = blockIdx.x * 64;
    const int kb = blockIdx.y * 512;
    const int r0 = (tid >> 5) * 8;
    const int c0 = (tid & 31) * 4;

    float acc[8][4];
    #pragma unroll
    for (int i = 0; i < 8; i++)
        #pragma unroll
        for (int j = 0; j < 4; j++) acc[i][j] = 0.f;

    for (int k0 = 0; k0 < 512; k0 += 32) {
        #pragma unroll
        for (int t = 0; t < 2; t++) {
            int idx = tid + t * 256;
            int row = idx >> 3, gg = idx & 7;
            float4 v = *(const float4*)(A + (size_t)(m0 + row) * DD + kb + k0 + gg * 4);
            As[gg*4+0][row] = v.x; As[gg*4+1][row] = v.y;
            As[gg*4+2][row] = v.z; As[gg*4+3][row] = v.w;
        }
        #pragma unroll
        for (int t = 0; t < 4; t++) {
            int idx = tid + t * 256;
            int col = idx >> 3, gg = idx & 7;
            const float* src = (col < 64) ? (Wq + (size_t)col * DD)
                                          : (Wk + (size_t)(col - 64) * DD);
            float4 v = *(const float4*)(src + kb + k0 + gg * 4);
            Ws[gg*4+0][col] = v.x; Ws[gg*4+1][col] = v.y;
            Ws[gg*4+2][col] = v.z; Ws[gg*4+3][col] = v.w;
        }
        __syncthreads();
        #pragma unroll 8
        for (int kk = 0; kk < 32; kk++) {
            float4 w = *(const float4*)&Ws[kk][c0];
            #pragma unroll
            for (int i = 0; i < 8; i++) {
                float a = As[kk][r0 + i];
                acc[i][0] += a * w.x; acc[i][1] += a * w.y;
                acc[i][2] += a * w.z; acc[i][3] += a * w.w;
            }
        }
        __syncthreads();
    }
    float* dst = part + (size_t)blockIdx.y * MROWS * 128;
    #pragma unroll
    for (int i = 0; i < 8; i++) {
        float4 o = make_float4(acc[i][0], acc[i][1], acc[i][2], acc[i][3]);
        *(float4*)(dst + (size_t)(m0 + r0 + i) * 128 + c0) = o;
    }
}

__global__ __launch_bounds__(256) void rel_reduce(
    const float* __restrict__ part, float* __restrict__ qrel, float* __restrict__ krel)
{
    int idx = blockIdx.x * 256 + threadIdx.x;
    int row = idx >> 6, col = idx & 63;
    float sq = 0.f, sk = 0.f;
    #pragma unroll
    for (int s = 0; s < 4; s++) {
        const float* p = part + (size_t)s * MROWS * 128 + (size_t)row * 128;
        sq += p[col]; sk += p[col + 64];
    }
    qrel[(size_t)row * 64 + col] = sq;
    krel[(size_t)row * 64 + col] = sk;
}

// ====================== top-K mask build (one block per (b,q)) ================
__device__ __forceinline__ unsigned ford(float f) {
    unsigned u = __float_as_uint(f);
    return (u & 0x80000000u) ? ~u : (u | 0x80000000u);
}

__global__ __launch_bounds__(256) void build_mask(
    const float* __restrict__ qrel, const float* __restrict__ krel,
    unsigned* __restrict__ mask)
{
    const int q = blockIdx.x;
    const int b = blockIdx.y;
    const int tid = threadIdx.x;

    __shared__ float    s[LL];
    __shared__ unsigned mw[LL/32];
    __shared__ float    qv[DREL];
    __shared__ int      hist[256];
    __shared__ int      scan[256];
    __shared__ unsigned sh_prefix;
    __shared__ int      sh_R;

    if (tid < DREL) qv[tid] = qrel[(size_t)(b*LL + q)*DREL + tid];
    if (tid < LL/32) mw[tid] = 0u;
    __syncthreads();

    const int n = q + 1;
    for (int k = tid; k < n; k += 256) {
        const float4* kr = (const float4*)&krel[(size_t)(b*LL + k)*DREL];
        float acc = 0.f;
        #pragma unroll
        for (int j = 0; j < 16; j++) {
            float4 v = kr[j];
            acc += qv[j*4+0]*v.x + qv[j*4+1]*v.y + qv[j*4+2]*v.z + qv[j*4+3]*v.w;
        }
        s[k] = acc;
    }
    __syncthreads();

    if (n <= KSEL) {
        for (int k = tid; k < n; k += 256)
            atomicOr(&mw[k>>5], 1u << (k & 31));
    } else {
        unsigned prefix = 0u; int R = KSEL;
        for (int byte = 3; byte >= 0; byte--) {
            hist[tid] = 0;
            __syncthreads();
            const int shift = byte * 8;
            const unsigned pm = (byte == 3) ? 0u : (0xFFFFFFFFu << (shift + 8));
            for (int k = tid; k < n; k += 256) {
                unsigned u = ford(s[k]);
                if ((u & pm) == (prefix & pm))
                    atomicAdd(&hist[(u >> shift) & 255], 1);
            }
            __syncthreads();
            int hv = hist[tid];
            scan[tid] = hv;
            __syncthreads();
            #pragma unroll
            for (int off = 1; off < 256; off <<= 1) {
                int t = (tid + off < 256) ? scan[tid + off] : 0;
                __syncthreads();
                scan[tid] += t;
                __syncthreads();
            }
            int inc = scan[tid];
            int above = inc - hv;
            if (above < R && inc >= R) {
                sh_prefix = prefix | ((unsigned)tid << shift);
                sh_R = R - above;
            }
            __syncthreads();
            prefix = sh_prefix; R = sh_R;
            __syncthreads();
        }
        const unsigned T = prefix;
        for (int k = tid; k < n; k += 256)
            if (ford(s[k]) > T) atomicOr(&mw[k>>5], 1u << (k & 31));
        const int per = (n + 255) >> 8;
        const int lo = tid * per;
        const int hi = (lo + per < n) ? lo + per : n;
        int cnt = 0;
        for (int k = lo; k < hi; k++)
            if (ford(s[k]) == T) cnt++;
        scan[tid] = cnt;
        __syncthreads();
        #pragma unroll
        for (int off = 1; off < 256; off <<= 1) {
            int t = (tid >= off) ? scan[tid - off] : 0;
            __syncthreads();
            scan[tid] += t;
            __syncthreads();
        }
        int excl = scan[tid] - cnt;
        int r2 = R - excl;
        if (r2 > 0) {
            for (int k = lo; k < hi && r2 > 0; k++)
                if (ford(s[k]) == T) { atomicOr(&mw[k>>5], 1u << (k & 31)); r2--; }
        }
    }
    __syncthreads();
    if (tid == 0) mw[q>>5] |= 1u << (q & 31);
    __syncthreads();
    if (tid < LL/32) mask[(size_t)(b*LL + q)*(LL/32) + tid] = mw[tid];
}

// ====================== flash attention (2-pass fp16 mma) =====================
#define QSEG 17408      // 128*136 halves
#define KSEG 8704       // 64*136 halves
#define FOFF_QH 0
#define FOFF_QL QSEG
#define KVOFF(st, seg) (2*QSEG + (st)*2*KSEG + (seg)*KSEG)
#define FMASK_B ((2*QSEG + 4*KSEG)*2)
#define FSMEM   (FMASK_B + 2*1024)
#define SC2 0.12751744416168355f               // (1/sqrt(128)) * log2(e)

__global__ __launch_bounds__(256) void flash_mma(
    const __half* __restrict__ Qh, const __half* __restrict__ Ql,
    const __half* __restrict__ Kh, const __half* __restrict__ Vh,
    const unsigned* __restrict__ mask,
    __half* __restrict__ Ch, __half* __restrict__ Cl)
{
    extern __shared__ __half FS[];
    const uint32_t base = smem_u32(FS);
    const uint32_t maskB = base + FMASK_B;

    const int qt = blockIdx.x, h = blockIdx.y, b = blockIdx.z;
    const int q0 = qt * 128;
    const int tid = threadIdx.x;
    const int w = tid >> 5, l = tid & 31;
    const int gid = l >> 2, tig = l & 3;

    {
        const __half* qs[2] = {Qh, Ql};
        #pragma unroll
        for (int j = 0; j < 16; j++) {
            int idx = tid + j * 256;
            int seg = idx >> 11, rem = idx & 2047;
            int row = rem >> 4, c16 = rem & 15;
            uint32_t dst = base + (uint32_t)(seg * QSEG + row * 136 + c16 * 8) * 2;
            const __half* src = qs[seg] + (size_t)(b*LL + q0 + row) * DD + h * DHD + c16 * 8;
            CP_ASYNC16(dst, src);
        }
        CP_COMMIT();
    }

    auto issue_kv = [&](int kt, int st) {
        const __half* ks[2] = {Kh, Vh};
        #pragma unroll
        for (int j = 0; j < 8; j++) {
            int idx = tid + j * 256;
            int seg = idx >> 10, rem = idx & 1023;
            int row = rem >> 4, c16 = rem & 15;
            uint32_t dst = base + (uint32_t)(KVOFF(st, seg) + row * 136 + c16 * 8) * 2;
            const __half* src = ks[seg] + (size_t)(b*LL + kt*64 + row) * DD + h * DHD + c16 * 8;
            CP_ASYNC16(dst, src);
        }
        if (tid < 128) {
            uint32_t dst = maskB + st * 1024 + tid * 8;
            const unsigned* src = &mask[(size_t)(b*LL + q0 + tid) * (LL/32) + kt*2];
            CP_ASYNC8(dst, src);
        }
        CP_COMMIT();
    };

    issue_kv(0, 0);

    const int qa_row = w * 16 + ((l >> 3) & 1) * 8 + (l & 7);
    const int qa_colB = (l >> 4) * 16;
    const int kb_rowBase = ((l >> 4) & 1) * 8 + (l & 7);
    const int kb_colB = ((l >> 3) & 1) * 16;
    const int v_row = l & 15;
    const int v_colB = (l >> 4) * 16;

    float O[16][4];
    #pragma unroll
    for (int i = 0; i < 16; i++)
        #pragma unroll
        for (int t = 0; t < 4; t++) O[i][t] = 0.f;
    float m0 = -1e30f, m1 = -1e30f, rl0 = 0.f, rl1 = 0.f;

    const int rlo2 = (w*16 + gid) * 2;
    const int rhi2 = rlo2 + 16;

    const int ktiles = 2 * qt + 2;
    for (int kt = 0; kt < ktiles; kt++) {
        const int st = kt & 1;
        if (kt + 1 < ktiles) {
            __syncthreads();
            issue_kv(kt + 1, st ^ 1);
            CP_WAIT(1);
        } else {
            CP_WAIT(0);
        }
        __syncthreads();

        const uint32_t sKH = base + (uint32_t)KVOFF(st, 0) * 2;
        const uint32_t sVH = base + (uint32_t)KVOFF(st, 1) * 2;
        const uint32_t* maskS = (const uint32_t*)(FS) + (FMASK_B >> 2) + st * 256;

        float Sc[8][4];
        #pragma unroll
        for (int i = 0; i < 8; i++)
            #pragma unroll
            for (int t = 0; t < 4; t++) Sc[i][t] = 0.f;

        #pragma unroll
        for (int kf = 0; kf < 8; kf++) {
            uint32_t aH[4], aL[4];
            ldsm4(aH, base + (uint32_t)(FOFF_QH + qa_row * 136) * 2 + kf*32 + qa_colB);
            ldsm4(aL, base + (uint32_t)(FOFF_QL + qa_row * 136) * 2 + kf*32 + qa_colB);
            #pragma unroll
            for (int nf2 = 0; nf2 < 4; nf2++) {
                uint32_t bH[4];
                ldsm4(bH, sKH + (uint32_t)((nf2*16 + kb_rowBase) * 136) * 2 + kf*32 + kb_colB);
                mma16816(Sc[2*nf2],   aH, bH + 0);
                mma16816(Sc[2*nf2+1], aH, bH + 2);
                mma16816(Sc[2*nf2],   aL, bH + 0);
                mma16816(Sc[2*nf2+1], aL, bH + 2);
            }
        }

        #pragma unroll
        for (int nf = 0; nf < 8; nf++) {
            unsigned wlo = maskS[rlo2 + (nf >> 2)];
            unsigned whi = maskS[rhi2 + (nf >> 2)];
            int sh = ((nf & 3) << 3) + (tig << 1);
            Sc[nf][0] = ((wlo >> sh) & 1u)     ? Sc[nf][0] : -1e30f;
            Sc[nf][1] = ((wlo >> (sh+1)) & 1u) ? Sc[nf][1] : -1e30f;
            Sc[nf][2] = ((whi >> sh) & 1u)     ? Sc[nf][2] : -1e30f;
            Sc[nf][3] = ((whi >> (sh+1)) & 1u) ? Sc[nf][3] : -1e30f;
        }

        float mx0 = -1e30f, mx1 = -1e30f;
        #pragma unroll
        for (int nf = 0; nf < 8; nf++) {
            mx0 = fmaxf(mx0, fmaxf(Sc[nf][0], Sc[nf][1]));
            mx1 = fmaxf(mx1, fmaxf(Sc[nf][2], Sc[nf][3]));
        }
        mx0 = fmaxf(mx0, __shfl_xor_sync(0xffffffffu, mx0, 1));
        mx0 = fmaxf(mx0, __shfl_xor_sync(0xffffffffu, mx0, 2));
        mx1 = fmaxf(mx1, __shfl_xor_sync(0xffffffffu, mx1, 1));
        mx1 = fmaxf(mx1, __shfl_xor_sync(0xffffffffu, mx1, 2));
        float nm0 = fmaxf(m0, mx0), nm1 = fmaxf(m1, mx1);
        float a0 = ex2f((m0 - nm0) * SC2), a1 = ex2f((m1 - nm1) * SC2);
        m0 = nm0; m1 = nm1;

        float s0 = 0.f, s1 = 0.f;
        #pragma unroll
        for (int nf = 0; nf < 8; nf++) {
            float p0 = ex2f((Sc[nf][0] - m0) * SC2);
            float p1 = ex2f((Sc[nf][1] - m0) * SC2);
            float p2 = ex2f((Sc[nf][2] - m1) * SC2);
            float p3 = ex2f((Sc[nf][3] - m1) * SC2);
            Sc[nf][0] = p0; Sc[nf][1] = p1; Sc[nf][2] = p2; Sc[nf][3] = p3;
            s0 += p0 + p1; s1 += p2 + p3;
        }
        s0 += __shfl_xor_sync(0xffffffffu, s0, 1);
        s0 += __shfl_xor_sync(0xffffffffu, s0, 2);
        s1 += __shfl_xor_sync(0xffffffffu, s1, 1);
        s1 += __shfl_xor_sync(0xffffffffu, s1, 2);
        rl0 = rl0 * a0 + s0;
        rl1 = rl1 * a1 + s1;

        #pragma unroll
        for (int df = 0; df < 16; df++) {
            O[df][0] *= a0; O[df][1] *= a0;
            O[df][2] *= a1; O[df][3] *= a1;
        }

        #pragma unroll
        for (int kf = 0; kf < 4; kf++) {
            uint32_t Pha[4], Pla[4];
            split2(Sc[2*kf][0],   Sc[2*kf][1],   Pha[0], Pla[0]);
            split2(Sc[2*kf][2],   Sc[2*kf][3],   Pha[1], Pla[1]);
            split2(Sc[2*kf+1][0], Sc[2*kf+1][1], Pha[2], Pla[2]);
            split2(Sc[2*kf+1][2], Sc[2*kf+1][3], Pha[3], Pla[3]);
            #pragma unroll
            for (int df2 = 0; df2 < 8; df2++) {
                uint32_t vh4[4];
                ldsm4t(vh4, sVH + (uint32_t)((kf*16 + v_row) * 136) * 2 + df2*32 + v_colB);
                mma16816(O[2*df2],   Pha, vh4 + 0);
                mma16816(O[2*df2+1], Pha, vh4 + 2);
                mma16816(O[2*df2],   Pla, vh4 + 0);
                mma16816(O[2*df2+1], Pla, vh4 + 2);
            }
        }
    }

    float inv0 = 1.f / rl0, inv1 = 1.f / rl1;
    const size_t rowlo = (size_t)(b*LL + q0 + w*16 + gid) * DD + h * DHD + tig * 2;
    const size_t rowhi = rowlo + 8 * DD;
    #pragma unroll
    for (int df = 0; df < 16; df++) {
        uint32_t hv, lv;
        split2(O[df][0] * inv0, O[df][1] * inv0, hv, lv);
        *(uint32_t*)(Ch + rowlo + df*8) = hv;
        *(uint32_t*)(Cl + rowlo + df*8) = lv;
        split2(O[df][2] * inv1, O[df][3] * inv1, hv, lv);
        *(uint32_t*)(Ch + rowhi + df*8) = hv;
        *(uint32_t*)(Cl + rowhi + df*8) = lv;
    }
}

// ================================ launch ======================================
extern "C" void kernel_launch(void* const* d_in, const int* in_sizes, int n_in,
                              void* d_out, int out_size)
{
    const float* hidden    = (const float*)d_in[0];
    const float* relevance = (const float*)d_in[1];
    const float* Wqr       = (const float*)d_in[2];
    const float* Wkr       = (const float*)d_in[3];
    const float* Wq        = (const float*)d_in[4];
    const float* Wk        = (const float*)d_in[5];
    const float* Wv        = (const float*)d_in[6];
    const float* Wo        = (const float*)d_in[7];
    float* out = (float*)d_out;

    __half *hidh,*hidl,*wqh,*wkh,*wvh,*woh;
    __half *qh,*ql,*kh,*vh,*ctxh,*ctxl;
    float *qrel,*krel,*relp; unsigned* mask;
    cudaGetSymbolAddress((void**)&hidh, g_hidh); cudaGetSymbolAddress((void**)&hidl, g_hidl);
    cudaGetSymbolAddress((void**)&wqh,  g_wqh);
    cudaGetSymbolAddress((void**)&wkh,  g_wkh);
    cudaGetSymbolAddress((void**)&wvh,  g_wvh);
    cudaGetSymbolAddress((void**)&woh,  g_woh);
    cudaGetSymbolAddress((void**)&qh,   g_qh);   cudaGetSymbolAddress((void**)&ql,   g_ql);
    cudaGetSymbolAddress((void**)&kh,   g_kh);
    cudaGetSymbolAddress((void**)&vh,   g_vh);
    cudaGetSymbolAddress((void**)&ctxh, g_ctxh); cudaGetSymbolAddress((void**)&ctxl, g_ctxl);
    cudaGetSymbolAddress((void**)&qrel, g_qrel); cudaGetSymbolAddress((void**)&krel, g_krel);
    cudaGetSymbolAddress((void**)&relp, g_relp); cudaGetSymbolAddress((void**)&mask, g_mask);

    cudaFuncSetAttribute(gemm_qkv, cudaFuncAttributeMaxDynamicSharedMemorySize, GSMEM);
    cudaFuncSetAttribute(gemm_o,   cudaFuncAttributeMaxDynamicSharedMemorySize, GSMEM);
    cudaFuncSetAttribute(flash_mma, cudaFuncAttributeMaxDynamicSharedMemorySize, FSMEM);

    // persistent side stream + fork/join events (created once, eagerly, on the
    // first [correctness] call; reused identically on every call — work is
    // deterministic and identical per invocation)
    static cudaStream_t sSide = nullptr;
    static cudaEvent_t  evFork = nullptr, evJoin = nullptr;
    if (sSide == nullptr) {
        cudaStreamCreateWithFlags(&sSide, cudaStreamNonBlocking);
        cudaEventCreateWithFlags(&evFork, cudaEventDisableTiming);
        cudaEventCreateWithFlags(&evJoin, cudaEventDisableTiming);
    }

    const int nh4 = MROWS * DD / 4, nw4 = DD * DD / 4;

    // ---- fork: independent relevance/mask path (+ Wo cvt) on side stream ----
    cudaEventRecord(evFork, 0);
    cudaStreamWaitEvent(sSide, evFork, 0);
    rel_proj<<<dim3(MROWS/64, 4), 256, 0, sSide>>>(relevance, Wqr, Wkr, relp);
    rel_reduce<<<(MROWS*64)/256, 256, 0, sSide>>>(relp, qrel, krel);
    build_mask<<<dim3(LL, BB), 256, 0, sSide>>>(qrel, krel, mask);
    cvt_hi<<<(nw4 + 255)/256, 256, 0, sSide>>>((const float4*)Wo, (uint2*)woh, nw4);
    cudaEventRecord(evJoin, sSide);

    // ---- main stream: conversions + QKV ----
    cvt_split<<<(nh4 + 255)/256, 256>>>((const float4*)hidden, (uint2*)hidh, (uint2*)hidl, nh4);
    cvt_hi3<<<dim3((nw4 + 255)/256, 3), 256>>>(
        (const float4*)Wq, (const float4*)Wk, (const float4*)Wv,
        (uint2*)wqh, (uint2*)wkh, (uint2*)wvh, nw4);

    gemm_qkv<<<dim3(DD/256, MROWS/128, 3), 256, GSMEM>>>(
        hidh, hidl, wqh, qh, ql, wkh, kh, wvh, vh);

    // ---- join, then attention + output projection ----
    cudaStreamWaitEvent(0, evJoin, 0);
    flash_mma<<<dim3(LL/128, HH, BB), 256, FSMEM>>>(qh, ql, kh, vh, mask, ctxh, ctxl);
    gemm_o<<<dim3(DD/256, MROWS/128), 256, GSMEM>>>(ctxh, ctxl, woh, out);
}

// round 8
// speedup vs baseline: 5.2174x; 1.0804x over previous
#include <cuda_runtime.h>
#include <cuda_fp16.h>
#include <cstdint>
#include <math.h>

// Problem constants
#define BB   2
#define LL   2048
#define DD   2048
#define HH   16
#define DHD  128
#define DREL 64
#define KSEL 512
#define MROWS (BB*LL)   // 4096

// -------------------- scratch (device globals; no cudaMalloc allowed) ---------
__device__ __align__(256) __half g_hidh[MROWS*DD];
__device__ __align__(256) __half g_hidl[MROWS*DD];
__device__ __align__(256) __half g_wqh [DD*DD];
__device__ __align__(256) __half g_wkh [DD*DD];
__device__ __align__(256) __half g_wvh [DD*DD];
__device__ __align__(256) __half g_woh [DD*DD];
__device__ __align__(256) __half g_qh  [MROWS*DD];
__device__ __align__(256) __half g_ql  [MROWS*DD];
__device__ __align__(256) __half g_kh  [MROWS*DD];
__device__ __align__(256) __half g_vh  [MROWS*DD];
__device__ __align__(256) __half g_ctxh[MROWS*DD];
__device__ __align__(256) float    g_qrel[BB*LL*DREL];
__device__ __align__(256) float    g_krel[BB*LL*DREL];
__device__ __align__(256) float    g_relp[4*MROWS*128];
__device__ __align__(256) unsigned g_mask[BB*LL*(LL/32)];

// ========================= inline PTX helpers =================================
__device__ __forceinline__ uint32_t smem_u32(const void* p) {
    uint32_t a;
    asm("{ .reg .u64 t; cvta.to.shared.u64 t, %1; cvt.u32.u64 %0, t; }" : "=r"(a) : "l"(p));
    return a;
}
__device__ __forceinline__ void ldsm4(uint32_t* r, uint32_t addr) {
    asm volatile("ldmatrix.sync.aligned.m8n8.x4.shared.b16 {%0,%1,%2,%3}, [%4];"
        : "=r"(r[0]), "=r"(r[1]), "=r"(r[2]), "=r"(r[3]) : "r"(addr));
}
__device__ __forceinline__ void ldsm4t(uint32_t* r, uint32_t addr) {
    asm volatile("ldmatrix.sync.aligned.m8n8.x4.trans.shared.b16 {%0,%1,%2,%3}, [%4];"
        : "=r"(r[0]), "=r"(r[1]), "=r"(r[2]), "=r"(r[3]) : "r"(addr));
}
__device__ __forceinline__ void mma16816(float* c, const uint32_t* a, const uint32_t* b) {
    asm volatile("mma.sync.aligned.m16n8k16.row.col.f32.f16.f16.f32 "
        "{%0,%1,%2,%3}, {%4,%5,%6,%7}, {%8,%9}, {%0,%1,%2,%3};"
        : "+f"(c[0]), "+f"(c[1]), "+f"(c[2]), "+f"(c[3])
        : "r"(a[0]), "r"(a[1]), "r"(a[2]), "r"(a[3]), "r"(b[0]), "r"(b[1]));
}
#define CP_ASYNC16(dst, src) \
    asm volatile("cp.async.cg.shared.global [%0], [%1], 16;" :: "r"(dst), "l"(src) : "memory")
#define CP_ASYNC8(dst, src) \
    asm volatile("cp.async.ca.shared.global [%0], [%1], 8;" :: "r"(dst), "l"(src) : "memory")
#define CP_COMMIT() asm volatile("cp.async.commit_group;" ::: "memory")
#define CP_WAIT(n)  asm volatile("cp.async.wait_group %0;" :: "n"(n) : "memory")

__device__ __forceinline__ float ex2f(float x) {
    float y; asm("ex2.approx.f32 %0, %1;" : "=f"(y) : "f"(x)); return y;
}
__device__ __forceinline__ void split2(float x, float y, uint32_t& hi, uint32_t& lo) {
    __half hx = __float2half_rn(x), hy = __float2half_rn(y);
    __half lx = __float2half_rn(x - __half2float(hx));
    __half ly = __float2half_rn(y - __half2float(hy));
    hi = ((uint32_t)__half_as_ushort(hy) << 16) | __half_as_ushort(hx);
    lo = ((uint32_t)__half_as_ushort(ly) << 16) | __half_as_ushort(lx);
}
__device__ __forceinline__ uint32_t pack_h2(float x, float y) {
    __half hx = __float2half_rn(x), hy = __float2half_rn(y);
    return ((uint32_t)__half_as_ushort(hy) << 16) | __half_as_ushort(hx);
}

// =========================== fp32 -> fp16 conversions =========================
__global__ __launch_bounds__(256) void cvt_split(
    const float4* __restrict__ x, uint2* __restrict__ h, uint2* __restrict__ lo, int n4)
{
    int i = blockIdx.x * 256 + threadIdx.x;
    if (i >= n4) return;
    float4 v = x[i];
    uint32_t h0, l0, h1, l1;
    split2(v.x, v.y, h0, l0);
    split2(v.z, v.w, h1, l1);
    h[i]  = make_uint2(h0, h1);
    lo[i] = make_uint2(l0, l1);
}

__global__ __launch_bounds__(256) void cvt_hi(
    const float4* __restrict__ x, uint2* __restrict__ h, int n4)
{
    int i = blockIdx.x * 256 + threadIdx.x;
    if (i >= n4) return;
    float4 v = x[i];
    h[i] = make_uint2(pack_h2(v.x, v.y), pack_h2(v.z, v.w));
}

__global__ __launch_bounds__(256) void cvt_hi3(
    const float4* __restrict__ w0, const float4* __restrict__ w1, const float4* __restrict__ w2,
    uint2* __restrict__ h0, uint2* __restrict__ h1, uint2* __restrict__ h2, int n4)
{
    const float4* src = (blockIdx.y == 0) ? w0 : (blockIdx.y == 1) ? w1 : w2;
    uint2* dst        = (blockIdx.y == 0) ? h0 : (blockIdx.y == 1) ? h1 : h2;
    int i = blockIdx.x * 256 + threadIdx.x;
    if (i >= n4) return;
    float4 v = src[i];
    dst[i] = make_uint2(pack_h2(v.x, v.y), pack_h2(v.z, v.w));
}

// ===== fp16-split GEMM: C = (Ah[+Al]) · Bh^T ==================================
// CTA tile 128x256, warp tile 64x64 (8 warps), k-chunk 32, 3-stage cp.async.
#define SEGA 10240               // Ah/Al segment: 128 rows x 80B
#define SEGB2 20480              // Bh segment: 256 rows x 80B
#define STAGE2B (2*SEGA + SEGB2) // 40960 (2-pass stage)
#define STAGE1B (SEGA + SEGB2)   // 30720 (1-pass stage)
#define GSMEM (3*STAGE2B)        // 122880

// OUTMODE: 0 = hi+lo fp16 out, 1 = hi fp16 out, 2 = fp32 out
template<int OUTMODE, int TWOPASS>
__device__ __forceinline__ void gemm_body(
    const __half* __restrict__ Ah, const __half* __restrict__ Al,
    const __half* __restrict__ Bh,
    float* __restrict__ Cf, __half* __restrict__ Ch, __half* __restrict__ Cl,
    __half* GS)
{
    const uint32_t base = smem_u32(GS);
    const int tid = threadIdx.x;
    const int l   = tid & 31;
    const int wid = tid >> 5;
    const int wm  = wid >> 2;
    const int wn  = wid & 3;
    const int bm  = blockIdx.y * 128;
    const int bn  = blockIdx.x * 256;
    const uint32_t STB = TWOPASS ? STAGE2B : STAGE1B;
    const uint32_t BOFF = TWOPASS ? 2*SEGA : SEGA;

    const __half* Ah_p = Ah + (size_t)bm * DD;
    const __half* Al_p = TWOPASS ? (Al + (size_t)bm * DD) : nullptr;
    const __half* Bh_p = Bh + (size_t)bn * DD;

    const int rA = wm * 64 + ((l >> 3) & 1) * 8 + (l & 7);
    const int kA = (l >> 4) * 16;
    const int rB = wn * 64 + ((l >> 4) & 1) * 8 + (l & 7);
    const int kB = ((l >> 3) & 1) * 16;

    float acc[4][8][4];
    #pragma unroll
    for (int i = 0; i < 4; i++)
        #pragma unroll
        for (int j = 0; j < 8; j++)
            #pragma unroll
            for (int t = 0; t < 4; t++) acc[i][j][t] = 0.f;

    auto issue_stage = [&](int c, int st) {
        const uint32_t stb = base + (uint32_t)st * STB;
        const int NJ = TWOPASS ? 8 : 6;
        #pragma unroll
        for (int j = 0; j < 8; j++) {
            if (j >= NJ) break;
            int idx = tid + j * 256;
            uint32_t dst; const __half* src;
            if (j < 2) {                       // Ah: idx 0..511
                int row = idx >> 2, c16 = idx & 3;
                dst = stb + (uint32_t)row * 80 + c16 * 16;
                src = Ah_p + (size_t)row * DD + c * 32 + c16 * 8;
            } else if (TWOPASS && j < 4) {     // Al: idx 512..1023
                int rem = idx - 512;
                int row = rem >> 2, c16 = rem & 3;
                dst = stb + SEGA + (uint32_t)row * 80 + c16 * 16;
                src = Al_p + (size_t)row * DD + c * 32 + c16 * 8;
            } else {                           // Bh
                int rem = idx - (TWOPASS ? 1024 : 512);
                int row = rem >> 2, c16 = rem & 3;
                dst = stb + BOFF + (uint32_t)row * 80 + c16 * 16;
                src = Bh_p + (size_t)row * DD + c * 32 + c16 * 8;
            }
            CP_ASYNC16(dst, src);
        }
        CP_COMMIT();
    };

    issue_stage(0, 0);
    issue_stage(1, 1);

    for (int c = 0; c < DD / 32; c++) {
        CP_WAIT(1);
        __syncthreads();
        if (c + 2 < DD / 32) issue_stage(c + 2, (c + 2) % 3);
        else CP_COMMIT();

        const int st = c % 3;
        const uint32_t sAh = base + (uint32_t)st * STB;
        const uint32_t sAl = sAh + SEGA;
        const uint32_t sBh = sAh + BOFF;

        #pragma unroll
        for (int ks = 0; ks < 2; ks++) {
            uint32_t aH[4][4], aL[4][4];
            #pragma unroll
            for (int mf = 0; mf < 4; mf++) {
                ldsm4(aH[mf], sAh + (uint32_t)(rA + mf*16) * 80 + kA + ks*32);
                if (TWOPASS)
                    ldsm4(aL[mf], sAl + (uint32_t)(rA + mf*16) * 80 + kA + ks*32);
            }
            #pragma unroll
            for (int nf4 = 0; nf4 < 4; nf4++) {
                uint32_t bH[4];
                ldsm4(bH, sBh + (uint32_t)(rB + nf4*16) * 80 + kB + ks*32);
                #pragma unroll
                for (int mf = 0; mf < 4; mf++) {
                    mma16816(acc[mf][2*nf4],   aH[mf], bH + 0);
                    mma16816(acc[mf][2*nf4+1], aH[mf], bH + 2);
                    if (TWOPASS) {
                        mma16816(acc[mf][2*nf4],   aL[mf], bH + 0);
                        mma16816(acc[mf][2*nf4+1], aL[mf], bH + 2);
                    }
                }
            }
        }
    }

    const int gid = l >> 2, tig = l & 3;
    #pragma unroll
    for (int mf = 0; mf < 4; mf++) {
        #pragma unroll
        for (int nf = 0; nf < 8; nf++) {
            int r0 = bm + wm*64 + mf*16 + gid;
            int cc = bn + wn*64 + nf*8 + tig*2;
            if (OUTMODE == 2) {
                *(float2*)(Cf + (size_t)r0 * DD + cc)       = make_float2(acc[mf][nf][0], acc[mf][nf][1]);
                *(float2*)(Cf + (size_t)(r0 + 8) * DD + cc) = make_float2(acc[mf][nf][2], acc[mf][nf][3]);
            } else if (OUTMODE == 1) {
                *(uint32_t*)(Ch + (size_t)r0 * DD + cc)       = pack_h2(acc[mf][nf][0], acc[mf][nf][1]);
                *(uint32_t*)(Ch + (size_t)(r0 + 8) * DD + cc) = pack_h2(acc[mf][nf][2], acc[mf][nf][3]);
            } else {
                uint32_t h0, l0v, h1, l1v;
                split2(acc[mf][nf][0], acc[mf][nf][1], h0, l0v);
                split2(acc[mf][nf][2], acc[mf][nf][3], h1, l1v);
                *(uint32_t*)(Ch + (size_t)r0 * DD + cc)       = h0;
                *(uint32_t*)(Cl + (size_t)r0 * DD + cc)       = l0v;
                *(uint32_t*)(Ch + (size_t)(r0 + 8) * DD + cc) = h1;
                *(uint32_t*)(Cl + (size_t)(r0 + 8) * DD + cc) = l1v;
            }
        }
    }
}

__global__ __launch_bounds__(256) void gemm_qkv(
    const __half* __restrict__ Ah, const __half* __restrict__ Al,
    const __half* __restrict__ Wqh, __half* __restrict__ Qh, __half* __restrict__ Ql,
    const __half* __restrict__ Wkh, __half* __restrict__ Kh,
    const __half* __restrict__ Wvh, __half* __restrict__ Vh)
{
    extern __shared__ __half GS[];
    if (blockIdx.z == 0)
        gemm_body<0,1>(Ah, Al, Wqh, nullptr, Qh, Ql, GS);
    else if (blockIdx.z == 1)
        gemm_body<1,1>(Ah, Al, Wkh, nullptr, Kh, nullptr, GS);
    else
        gemm_body<1,1>(Ah, Al, Wvh, nullptr, Vh, nullptr, GS);
}

__global__ __launch_bounds__(256) void gemm_o(
    const __half* __restrict__ Ah,
    const __half* __restrict__ Bh, float* __restrict__ Cf)
{
    extern __shared__ __half GS[];
    gemm_body<2,0>(Ah, nullptr, Bh, Cf, nullptr, nullptr, GS);
}

// ===================== rel projection (split-K, fused q/k) ====================
__global__ __launch_bounds__(256) void rel_proj(
    const float* __restrict__ A, const float* __restrict__ Wq,
    const float* __restrict__ Wk, float* __restrict__ part)
{
    __shared__ __align__(16) float As[32][65];
    __shared__ __align__(16) float Ws[32][132];
    const int tid = threadIdx.x;
    const int m0 = blockIdx.x * 64;
    const int kb = blockIdx.y * 512;
    const int r0 = (tid >> 5) * 8;
    const int c0 = (tid & 31) * 4;

    float acc[8][4];
    #pragma unroll
    for (int i = 0; i < 8; i++)
        #pragma unroll
        for (int j = 0; j < 4; j++) acc[i][j] = 0.f;

    for (int k0 = 0; k0 < 512; k0 += 32) {
        #pragma unroll
        for (int t = 0; t < 2; t++) {
            int idx = tid + t * 256;
            int row = idx >> 3, gg = idx & 7;
            float4 v = *(const float4*)(A + (size_t)(m0 + row) * DD + kb + k0 + gg * 4);
            As[gg*4+0][row] = v.x; As[gg*4+1][row] = v.y;
            As[gg*4+2][row] = v.z; As[gg*4+3][row] = v.w;
        }
        #pragma unroll
        for (int t = 0; t < 4; t++) {
            int idx = tid + t * 256;
            int col = idx >> 3, gg = idx & 7;
            const float* src = (col < 64) ? (Wq + (size_t)col * DD)
                                          : (Wk + (size_t)(col - 64) * DD);
            float4 v = *(const float4*)(src + kb + k0 + gg * 4);
            Ws[gg*4+0][col] = v.x; Ws[gg*4+1][col] = v.y;
            Ws[gg*4+2][col] = v.z; Ws[gg*4+3][col] = v.w;
        }
        __syncthreads();
        #pragma unroll 8
        for (int kk = 0; kk < 32; kk++) {
            float4 w = *(const float4*)&Ws[kk][c0];
            #pragma unroll
            for (int i = 0; i < 8; i++) {
                float a = As[kk][r0 + i];
                acc[i][0] += a * w.x; acc[i][1] += a * w.y;
                acc[i][2] += a * w.z; acc[i][3] += a * w.w;
            }
        }
        __syncthreads();
    }
    float* dst = part + (size_t)blockIdx.y * MROWS * 128;
    #pragma unroll
    for (int i = 0; i < 8; i++) {
        float4 o = make_float4(acc[i][0], acc[i][1], acc[i][2], acc[i][3]);
        *(float4*)(dst + (size_t)(m0 + r0 + i) * 128 + c0) = o;
    }
}

__global__ __launch_bounds__(256) void rel_reduce(
    const float* __restrict__ part, float* __restrict__ qrel, float* __restrict__ krel)
{
    int idx = blockIdx.x * 256 + threadIdx.x;
    int row = idx >> 6, col = idx & 63;
    float sq = 0.f, sk = 0.f;
    #pragma unroll
    for (int s = 0; s < 4; s++) {
        const float* p = part + (size_t)s * MROWS * 128 + (size_t)row * 128;
        sq += p[col]; sk += p[col + 64];
    }
    qrel[(size_t)row * 64 + col] = sq;
    krel[(size_t)row * 64 + col] = sk;
}

// ====================== top-K mask build (one block per (b,q)) ================
__device__ __forceinline__ unsigned ford(float f) {
    unsigned u = __float_as_uint(f);
    return (u & 0x80000000u) ? ~u : (u | 0x80000000u);
}

__global__ __launch_bounds__(256) void build_mask(
    const float* __restrict__ qrel, const float* __restrict__ krel,
    unsigned* __restrict__ mask)
{
    const int q = blockIdx.x;
    const int b = blockIdx.y;
    const int tid = threadIdx.x;

    __shared__ float    s[LL];
    __shared__ unsigned mw[LL/32];
    __shared__ float    qv[DREL];
    __shared__ int      hist[256];
    __shared__ int      scan[256];
    __shared__ unsigned sh_prefix;
    __shared__ int      sh_R;

    if (tid < DREL) qv[tid] = qrel[(size_t)(b*LL + q)*DREL + tid];
    if (tid < LL/32) mw[tid] = 0u;
    __syncthreads();

    const int n = q + 1;
    for (int k = tid; k < n; k += 256) {
        const float4* kr = (const float4*)&krel[(size_t)(b*LL + k)*DREL];
        float acc = 0.f;
        #pragma unroll
        for (int j = 0; j < 16; j++) {
            float4 v = kr[j];
            acc += qv[j*4+0]*v.x + qv[j*4+1]*v.y + qv[j*4+2]*v.z + qv[j*4+3]*v.w;
        }
        s[k] = acc;
    }
    __syncthreads();

    if (n <= KSEL) {
        for (int k = tid; k < n; k += 256)
            atomicOr(&mw[k>>5], 1u << (k & 31));
    } else {
        unsigned prefix = 0u; int R = KSEL;
        for (int byte = 3; byte >= 0; byte--) {
            hist[tid] = 0;
            __syncthreads();
            const int shift = byte * 8;
            const unsigned pm = (byte == 3) ? 0u : (0xFFFFFFFFu << (shift + 8));
            for (int k = tid; k < n; k += 256) {
                unsigned u = ford(s[k]);
                if ((u & pm) == (prefix & pm))
                    atomicAdd(&hist[(u >> shift) & 255], 1);
            }
            __syncthreads();
            int hv = hist[tid];
            scan[tid] = hv;
            __syncthreads();
            #pragma unroll
            for (int off = 1; off < 256; off <<= 1) {
                int t = (tid + off < 256) ? scan[tid + off] : 0;
                __syncthreads();
                scan[tid] += t;
                __syncthreads();
            }
            int inc = scan[tid];
            int above = inc - hv;
            if (above < R && inc >= R) {
                sh_prefix = prefix | ((unsigned)tid << shift);
                sh_R = R - above;
            }
            __syncthreads();
            prefix = sh_prefix; R = sh_R;
            __syncthreads();
        }
        const unsigned T = prefix;
        for (int k = tid; k < n; k += 256)
            if (ford(s[k]) > T) atomicOr(&mw[k>>5], 1u << (k & 31));
        const int per = (n + 255) >> 8;
        const int lo = tid * per;
        const int hi = (lo + per < n) ? lo + per : n;
        int cnt = 0;
        for (int k = lo; k < hi; k++)
            if (ford(s[k]) == T) cnt++;
        scan[tid] = cnt;
        __syncthreads();
        #pragma unroll
        for (int off = 1; off < 256; off <<= 1) {
            int t = (tid >= off) ? scan[tid - off] : 0;
            __syncthreads();
            scan[tid] += t;
            __syncthreads();
        }
        int excl = scan[tid] - cnt;
        int r2 = R - excl;
        if (r2 > 0) {
            for (int k = lo; k < hi && r2 > 0; k++)
                if (ford(s[k]) == T) { atomicOr(&mw[k>>5], 1u << (k & 31)); r2--; }
        }
    }
    __syncthreads();
    if (tid == 0) mw[q>>5] |= 1u << (q & 31);
    __syncthreads();
    if (tid < LL/32) mask[(size_t)(b*LL + q)*(LL/32) + tid] = mw[tid];
}

// ====================== flash attention (2-pass fp16 mma) =====================
// 4 warps, Q-tile 64 rows (hi+lo), K/V tiles 64 (hi), double-buffered.
// smem ~103 KB -> 2 CTAs/SM (softmax ALU overlaps tensor across CTAs).
#define QSEG 8704       // 64*136 halves
#define KSEG 8704
#define FOFF_QH 0
#define FOFF_QL QSEG
#define KVOFF(st, seg) (2*QSEG + (st)*2*KSEG + (seg)*KSEG)
#define FMASK_B ((2*QSEG + 4*KSEG)*2)
#define FSMEM   (FMASK_B + 2*512)
#define SC2 0.12751744416168355f               // (1/sqrt(128)) * log2(e)

__global__ __launch_bounds__(128) void flash_mma(
    const __half* __restrict__ Qh, const __half* __restrict__ Ql,
    const __half* __restrict__ Kh, const __half* __restrict__ Vh,
    const unsigned* __restrict__ mask,
    __half* __restrict__ Ch)
{
    extern __shared__ __half FS[];
    const uint32_t base = smem_u32(FS);
    const uint32_t maskB = base + FMASK_B;

    const int qt = (int)gridDim.x - 1 - (int)blockIdx.x;   // heavy tiles first
    const int h = blockIdx.y, b = blockIdx.z;
    const int q0 = qt * 64;
    const int tid = threadIdx.x;
    const int w = tid >> 5, l = tid & 31;
    const int gid = l >> 2, tig = l & 3;

    // Q load (one-time): 2 segs x 64 rows x 16 chunks = 2048 float4 -> 16/thread
    {
        const __half* qs[2] = {Qh, Ql};
        #pragma unroll
        for (int j = 0; j < 16; j++) {
            int idx = tid + j * 128;
            int seg = idx >> 10, rem = idx & 1023;
            int row = rem >> 4, c16 = rem & 15;
            uint32_t dst = base + (uint32_t)(seg * QSEG + row * 136 + c16 * 8) * 2;
            const __half* src = qs[seg] + (size_t)(b*LL + q0 + row) * DD + h * DHD + c16 * 8;
            CP_ASYNC16(dst, src);
        }
        CP_COMMIT();
    }

    auto issue_kv = [&](int kt, int st) {
        const __half* ks[2] = {Kh, Vh};
        #pragma unroll
        for (int j = 0; j < 16; j++) {
            int idx = tid + j * 128;
            int seg = idx >> 10, rem = idx & 1023;
            int row = rem >> 4, c16 = rem & 15;
            uint32_t dst = base + (uint32_t)(KVOFF(st, seg) + row * 136 + c16 * 8) * 2;
            const __half* src = ks[seg] + (size_t)(b*LL + kt*64 + row) * DD + h * DHD + c16 * 8;
            CP_ASYNC16(dst, src);
        }
        if (tid < 64) {
            uint32_t dst = maskB + st * 512 + tid * 8;
            const unsigned* src = &mask[(size_t)(b*LL + q0 + tid) * (LL/32) + kt*2];
            CP_ASYNC8(dst, src);
        }
        CP_COMMIT();
    };

    issue_kv(0, 0);

    const int qa_row = w * 16 + ((l >> 3) & 1) * 8 + (l & 7);
    const int qa_colB = (l >> 4) * 16;
    const int kb_rowBase = ((l >> 4) & 1) * 8 + (l & 7);
    const int kb_colB = ((l >> 3) & 1) * 16;
    const int v_row = l & 15;
    const int v_colB = (l >> 4) * 16;

    float O[16][4];
    #pragma unroll
    for (int i = 0; i < 16; i++)
        #pragma unroll
        for (int t = 0; t < 4; t++) O[i][t] = 0.f;
    float m0 = -1e30f, m1 = -1e30f, rl0 = 0.f, rl1 = 0.f;

    const int rlo2 = (w*16 + gid) * 2;
    const int rhi2 = rlo2 + 16;

    const int ktiles = qt + 1;
    for (int kt = 0; kt < ktiles; kt++) {
        const int st = kt & 1;
        if (kt + 1 < ktiles) {
            __syncthreads();
            issue_kv(kt + 1, st ^ 1);
            CP_WAIT(1);
        } else {
            CP_WAIT(0);
        }
        __syncthreads();

        const uint32_t sKH = base + (uint32_t)KVOFF(st, 0) * 2;
        const uint32_t sVH = base + (uint32_t)KVOFF(st, 1) * 2;
        const uint32_t* maskS = (const uint32_t*)(FS) + (FMASK_B >> 2) + st * 128;

        // ---- S = Q K^T (2-pass: Qh·Kh + Ql·Kh) ----
        float Sc[8][4];
        #pragma unroll
        for (int i = 0; i < 8; i++)
            #pragma unroll
            for (int t = 0; t < 4; t++) Sc[i][t] = 0.f;

        #pragma unroll
        for (int kf = 0; kf < 8; kf++) {
            uint32_t aH[4], aL[4];
            ldsm4(aH, base + (uint32_t)(FOFF_QH + qa_row * 136) * 2 + kf*32 + qa_colB);
            ldsm4(aL, base + (uint32_t)(FOFF_QL + qa_row * 136) * 2 + kf*32 + qa_colB);
            #pragma unroll
            for (int nf2 = 0; nf2 < 4; nf2++) {
                uint32_t bH[4];
                ldsm4(bH, sKH + (uint32_t)((nf2*16 + kb_rowBase) * 136) * 2 + kf*32 + kb_colB);
                mma16816(Sc[2*nf2],   aH, bH + 0);
                mma16816(Sc[2*nf2+1], aH, bH + 2);
                mma16816(Sc[2*nf2],   aL, bH + 0);
                mma16816(Sc[2*nf2+1], aL, bH + 2);
            }
        }

        // ---- mask ----
        #pragma unroll
        for (int nf = 0; nf < 8; nf++) {
            unsigned wlo = maskS[rlo2 + (nf >> 2)];
            unsigned whi = maskS[rhi2 + (nf >> 2)];
            int sh = ((nf & 3) << 3) + (tig << 1);
            Sc[nf][0] = ((wlo >> sh) & 1u)     ? Sc[nf][0] : -1e30f;
            Sc[nf][1] = ((wlo >> (sh+1)) & 1u) ? Sc[nf][1] : -1e30f;
            Sc[nf][2] = ((whi >> sh) & 1u)     ? Sc[nf][2] : -1e30f;
            Sc[nf][3] = ((whi >> (sh+1)) & 1u) ? Sc[nf][3] : -1e30f;
        }

        // ---- online softmax ----
        float mx0 = -1e30f, mx1 = -1e30f;
        #pragma unroll
        for (int nf = 0; nf < 8; nf++) {
            mx0 = fmaxf(mx0, fmaxf(Sc[nf][0], Sc[nf][1]));
            mx1 = fmaxf(mx1, fmaxf(Sc[nf][2], Sc[nf][3]));
        }
        mx0 = fmaxf(mx0, __shfl_xor_sync(0xffffffffu, mx0, 1));
        mx0 = fmaxf(mx0, __shfl_xor_sync(0xffffffffu, mx0, 2));
        mx1 = fmaxf(mx1, __shfl_xor_sync(0xffffffffu, mx1, 1));
        mx1 = fmaxf(mx1, __shfl_xor_sync(0xffffffffu, mx1, 2));
        float nm0 = fmaxf(m0, mx0), nm1 = fmaxf(m1, mx1);
        float a0 = ex2f((m0 - nm0) * SC2), a1 = ex2f((m1 - nm1) * SC2);
        m0 = nm0; m1 = nm1;

        float s0 = 0.f, s1 = 0.f;
        #pragma unroll
        for (int nf = 0; nf < 8; nf++) {
            float p0 = ex2f((Sc[nf][0] - m0) * SC2);
            float p1 = ex2f((Sc[nf][1] - m0) * SC2);
            float p2 = ex2f((Sc[nf][2] - m1) * SC2);
            float p3 = ex2f((Sc[nf][3] - m1) * SC2);
            Sc[nf][0] = p0; Sc[nf][1] = p1; Sc[nf][2] = p2; Sc[nf][3] = p3;
            s0 += p0 + p1; s1 += p2 + p3;
        }
        s0 += __shfl_xor_sync(0xffffffffu, s0, 1);
        s0 += __shfl_xor_sync(0xffffffffu, s0, 2);
        s1 += __shfl_xor_sync(0xffffffffu, s1, 1);
        s1 += __shfl_xor_sync(0xffffffffu, s1, 2);
        rl0 = rl0 * a0 + s0;
        rl1 = rl1 * a1 + s1;

        #pragma unroll
        for (int df = 0; df < 16; df++) {
            O[df][0] *= a0; O[df][1] *= a0;
            O[df][2] *= a1; O[df][3] *= a1;
        }

        // ---- O += P V (2-pass: Ph·Vh + Pl·Vh) ----
        #pragma unroll
        for (int kf = 0; kf < 4; kf++) {
            uint32_t Pha[4], Pla[4];
            split2(Sc[2*kf][0],   Sc[2*kf][1],   Pha[0], Pla[0]);
            split2(Sc[2*kf][2],   Sc[2*kf][3],   Pha[1], Pla[1]);
            split2(Sc[2*kf+1][0], Sc[2*kf+1][1], Pha[2], Pla[2]);
            split2(Sc[2*kf+1][2], Sc[2*kf+1][3], Pha[3], Pla[3]);
            #pragma unroll
            for (int df2 = 0; df2 < 8; df2++) {
                uint32_t vh4[4];
                ldsm4t(vh4, sVH + (uint32_t)((kf*16 + v_row) * 136) * 2 + df2*32 + v_colB);
                mma16816(O[2*df2],   Pha, vh4 + 0);
                mma16816(O[2*df2+1], Pha, vh4 + 2);
                mma16816(O[2*df2],   Pla, vh4 + 0);
                mma16816(O[2*df2+1], Pla, vh4 + 2);
            }
        }
    }

    // ---- epilogue: ctx hi only ----
    float inv0 = 1.f / rl0, inv1 = 1.f / rl1;
    const size_t rowlo = (size_t)(b*LL + q0 + w*16 + gid) * DD + h * DHD + tig * 2;
    const size_t rowhi = rowlo + 8 * DD;
    #pragma unroll
    for (int df = 0; df < 16; df++) {
        *(uint32_t*)(Ch + rowlo + df*8) = pack_h2(O[df][0] * inv0, O[df][1] * inv0);
        *(uint32_t*)(Ch + rowhi + df*8) = pack_h2(O[df][2] * inv1, O[df][3] * inv1);
    }
}

// ================================ launch ======================================
extern "C" void kernel_launch(void* const* d_in, const int* in_sizes, int n_in,
                              void* d_out, int out_size)
{
    const float* hidden    = (const float*)d_in[0];
    const float* relevance = (const float*)d_in[1];
    const float* Wqr       = (const float*)d_in[2];
    const float* Wkr       = (const float*)d_in[3];
    const float* Wq        = (const float*)d_in[4];
    const float* Wk        = (const float*)d_in[5];
    const float* Wv        = (const float*)d_in[6];
    const float* Wo        = (const float*)d_in[7];
    float* out = (float*)d_out;

    __half *hidh,*hidl,*wqh,*wkh,*wvh,*woh;
    __half *qh,*ql,*kh,*vh,*ctxh;
    float *qrel,*krel,*relp; unsigned* mask;
    cudaGetSymbolAddress((void**)&hidh, g_hidh); cudaGetSymbolAddress((void**)&hidl, g_hidl);
    cudaGetSymbolAddress((void**)&wqh,  g_wqh);
    cudaGetSymbolAddress((void**)&wkh,  g_wkh);
    cudaGetSymbolAddress((void**)&wvh,  g_wvh);
    cudaGetSymbolAddress((void**)&woh,  g_woh);
    cudaGetSymbolAddress((void**)&qh,   g_qh);   cudaGetSymbolAddress((void**)&ql,   g_ql);
    cudaGetSymbolAddress((void**)&kh,   g_kh);
    cudaGetSymbolAddress((void**)&vh,   g_vh);
    cudaGetSymbolAddress((void**)&ctxh, g_ctxh);
    cudaGetSymbolAddress((void**)&qrel, g_qrel); cudaGetSymbolAddress((void**)&krel, g_krel);
    cudaGetSymbolAddress((void**)&relp, g_relp); cudaGetSymbolAddress((void**)&mask, g_mask);

    cudaFuncSetAttribute(gemm_qkv, cudaFuncAttributeMaxDynamicSharedMemorySize, GSMEM);
    cudaFuncSetAttribute(gemm_o,   cudaFuncAttributeMaxDynamicSharedMemorySize, GSMEM);
    cudaFuncSetAttribute(flash_mma, cudaFuncAttributeMaxDynamicSharedMemorySize, FSMEM);

    static cudaStream_t sSide = nullptr;
    static cudaEvent_t  evFork = nullptr, evJoin = nullptr;
    if (sSide == nullptr) {
        cudaStreamCreateWithFlags(&sSide, cudaStreamNonBlocking);
        cudaEventCreateWithFlags(&evFork, cudaEventDisableTiming);
        cudaEventCreateWithFlags(&evJoin, cudaEventDisableTiming);
    }

    const int nh4 = MROWS * DD / 4, nw4 = DD * DD / 4;

    // ---- fork: independent relevance/mask path (+ Wo cvt) on side stream ----
    cudaEventRecord(evFork, 0);
    cudaStreamWaitEvent(sSide, evFork, 0);
    rel_proj<<<dim3(MROWS/64, 4), 256, 0, sSide>>>(relevance, Wqr, Wkr, relp);
    rel_reduce<<<(MROWS*64)/256, 256, 0, sSide>>>(relp, qrel, krel);
    build_mask<<<dim3(LL, BB), 256, 0, sSide>>>(qrel, krel, mask);
    cvt_hi<<<(nw4 + 255)/256, 256, 0, sSide>>>((const float4*)Wo, (uint2*)woh, nw4);
    cudaEventRecord(evJoin, sSide);

    // ---- main stream: conversions + QKV ----
    cvt_split<<<(nh4 + 255)/256, 256>>>((const float4*)hidden, (uint2*)hidh, (uint2*)hidl, nh4);
    cvt_hi3<<<dim3((nw4 + 255)/256, 3), 256>>>(
        (const float4*)Wq, (const float4*)Wk, (const float4*)Wv,
        (uint2*)wqh, (uint2*)wkh, (uint2*)wvh, nw4);

    gemm_qkv<<<dim3(DD/256, MROWS/128, 3), 256, GSMEM>>>(
        hidh, hidl, wqh, qh, ql, wkh, kh, wvh, vh);

    // ---- join, then attention + output projection ----
    cudaStreamWaitEvent(0, evJoin, 0);
    flash_mma<<<dim3(LL/64, HH, BB), 128, FSMEM>>>(qh, ql, kh, vh, mask, ctxh);
    gemm_o<<<dim3(DD/256, MROWS/128), 256, GSMEM>>>(ctxh, woh, out);
}

// round 9
// speedup vs baseline: 6.1530x; 1.1793x over previous
#include <cuda_runtime.h>
#include <cuda_fp16.h>
#include <cstdint>
#include <math.h>

// Problem constants
#define BB   2
#define LL   2048
#define DD   2048
#define HH   16
#define DHD  128
#define DREL 64
#define KSEL 512
#define MROWS (BB*LL)   // 4096

// -------------------- scratch (device globals; no cudaMalloc allowed) ---------
__device__ __align__(256) __half g_hidh[MROWS*DD];
__device__ __align__(256) __half g_hidl[MROWS*DD];
__device__ __align__(256) __half g_wqh [DD*DD];
__device__ __align__(256) __half g_wkh [DD*DD];
__device__ __align__(256) __half g_wvh [DD*DD];
__device__ __align__(256) __half g_woh [DD*DD];
__device__ __align__(256) __half g_qh  [MROWS*DD];
__device__ __align__(256) __half g_ql  [MROWS*DD];
__device__ __align__(256) __half g_kh  [MROWS*DD];
__device__ __align__(256) __half g_vh  [MROWS*DD];
__device__ __align__(256) __half g_ctxh[MROWS*DD];
__device__ __align__(256) __half g_qrelh[MROWS*DREL];
__device__ __align__(256) __half g_qrell[MROWS*DREL];
__device__ __align__(256) __half g_krelh[MROWS*DREL];
__device__ __align__(256) __half g_krell[MROWS*DREL];
__device__ __align__(256) float    g_scores[(size_t)BB*LL*LL];
__device__ __align__(256) float    g_relp[4*MROWS*128];
__device__ __align__(256) unsigned g_mask[BB*LL*(LL/32)];

// ========================= inline PTX helpers =================================
__device__ __forceinline__ uint32_t smem_u32(const void* p) {
    uint32_t a;
    asm("{ .reg .u64 t; cvta.to.shared.u64 t, %1; cvt.u32.u64 %0, t; }" : "=r"(a) : "l"(p));
    return a;
}
__device__ __forceinline__ void ldsm4(uint32_t* r, uint32_t addr) {
    asm volatile("ldmatrix.sync.aligned.m8n8.x4.shared.b16 {%0,%1,%2,%3}, [%4];"
        : "=r"(r[0]), "=r"(r[1]), "=r"(r[2]), "=r"(r[3]) : "r"(addr));
}
__device__ __forceinline__ void ldsm4t(uint32_t* r, uint32_t addr) {
    asm volatile("ldmatrix.sync.aligned.m8n8.x4.trans.shared.b16 {%0,%1,%2,%3}, [%4];"
        : "=r"(r[0]), "=r"(r[1]), "=r"(r[2]), "=r"(r[3]) : "r"(addr));
}
__device__ __forceinline__ void mma16816(float* c, const uint32_t* a, const uint32_t* b) {
    asm volatile("mma.sync.aligned.m16n8k16.row.col.f32.f16.f16.f32 "
        "{%0,%1,%2,%3}, {%4,%5,%6,%7}, {%8,%9}, {%0,%1,%2,%3};"
        : "+f"(c[0]), "+f"(c[1]), "+f"(c[2]), "+f"(c[3])
        : "r"(a[0]), "r"(a[1]), "r"(a[2]), "r"(a[3]), "r"(b[0]), "r"(b[1]));
}
#define CP_ASYNC16(dst, src) \
    asm volatile("cp.async.cg.shared.global [%0], [%1], 16;" :: "r"(dst), "l"(src) : "memory")
#define CP_ASYNC8(dst, src) \
    asm volatile("cp.async.ca.shared.global [%0], [%1], 8;" :: "r"(dst), "l"(src) : "memory")
#define CP_COMMIT() asm volatile("cp.async.commit_group;" ::: "memory")
#define CP_WAIT(n)  asm volatile("cp.async.wait_group %0;" :: "n"(n) : "memory")

__device__ __forceinline__ float ex2f(float x) {
    float y; asm("ex2.approx.f32 %0, %1;" : "=f"(y) : "f"(x)); return y;
}
__device__ __forceinline__ void split2(float x, float y, uint32_t& hi, uint32_t& lo) {
    __half hx = __float2half_rn(x), hy = __float2half_rn(y);
    __half lx = __float2half_rn(x - __half2float(hx));
    __half ly = __float2half_rn(y - __half2float(hy));
    hi = ((uint32_t)__half_as_ushort(hy) << 16) | __half_as_ushort(hx);
    lo = ((uint32_t)__half_as_ushort(ly) << 16) | __half_as_ushort(lx);
}
__device__ __forceinline__ uint32_t pack_h2(float x, float y) {
    __half hx = __float2half_rn(x), hy = __float2half_rn(y);
    return ((uint32_t)__half_as_ushort(hy) << 16) | __half_as_ushort(hx);
}

// =========================== fp32 -> fp16 conversions =========================
__global__ __launch_bounds__(256) void cvt_split(
    const float4* __restrict__ x, uint2* __restrict__ h, uint2* __restrict__ lo, int n4)
{
    int i = blockIdx.x * 256 + threadIdx.x;
    if (i >= n4) return;
    float4 v = x[i];
    uint32_t h0, l0, h1, l1;
    split2(v.x, v.y, h0, l0);
    split2(v.z, v.w, h1, l1);
    h[i]  = make_uint2(h0, h1);
    lo[i] = make_uint2(l0, l1);
}

__global__ __launch_bounds__(256) void cvt_hi(
    const float4* __restrict__ x, uint2* __restrict__ h, int n4)
{
    int i = blockIdx.x * 256 + threadIdx.x;
    if (i >= n4) return;
    float4 v = x[i];
    h[i] = make_uint2(pack_h2(v.x, v.y), pack_h2(v.z, v.w));
}

__global__ __launch_bounds__(256) void cvt_hi3(
    const float4* __restrict__ w0, const float4* __restrict__ w1, const float4* __restrict__ w2,
    uint2* __restrict__ h0, uint2* __restrict__ h1, uint2* __restrict__ h2, int n4)
{
    const float4* src = (blockIdx.y == 0) ? w0 : (blockIdx.y == 1) ? w1 : w2;
    uint2* dst        = (blockIdx.y == 0) ? h0 : (blockIdx.y == 1) ? h1 : h2;
    int i = blockIdx.x * 256 + threadIdx.x;
    if (i >= n4) return;
    float4 v = src[i];
    dst[i] = make_uint2(pack_h2(v.x, v.y), pack_h2(v.z, v.w));
}

// ===== fp16-split GEMM: C = (Ah[+Al]) · Bh^T ==================================
// CTA tile 128x256, warp tile 64x64 (8 warps), k-chunk 32, 3-stage cp.async.
#define SEGA 10240               // Ah/Al segment: 128 rows x 80B
#define SEGB2 20480              // Bh segment: 256 rows x 80B
#define STAGE2B (2*SEGA + SEGB2) // 40960 (2-pass stage)
#define STAGE1B (SEGA + SEGB2)   // 30720 (1-pass stage)
#define GSMEM (3*STAGE2B)        // 122880

// OUTMODE: 0 = hi+lo fp16 out, 1 = hi fp16 out, 2 = fp32 out
template<int OUTMODE, int TWOPASS>
__device__ __forceinline__ void gemm_body(
    const __half* __restrict__ Ah, const __half* __restrict__ Al,
    const __half* __restrict__ Bh,
    float* __restrict__ Cf, __half* __restrict__ Ch, __half* __restrict__ Cl,
    __half* GS)
{
    const uint32_t base = smem_u32(GS);
    const int tid = threadIdx.x;
    const int l   = tid & 31;
    const int wid = tid >> 5;
    const int wm  = wid >> 2;
    const int wn  = wid & 3;
    const int bm  = blockIdx.y * 128;
    const int bn  = blockIdx.x * 256;
    const uint32_t STB = TWOPASS ? STAGE2B : STAGE1B;
    const uint32_t BOFF = TWOPASS ? 2*SEGA : SEGA;

    const __half* Ah_p = Ah + (size_t)bm * DD;
    const __half* Al_p = TWOPASS ? (Al + (size_t)bm * DD) : nullptr;
    const __half* Bh_p = Bh + (size_t)bn * DD;

    const int rA = wm * 64 + ((l >> 3) & 1) * 8 + (l & 7);
    const int kA = (l >> 4) * 16;
    const int rB = wn * 64 + ((l >> 4) & 1) * 8 + (l & 7);
    const int kB = ((l >> 3) & 1) * 16;

    float acc[4][8][4];
    #pragma unroll
    for (int i = 0; i < 4; i++)
        #pragma unroll
        for (int j = 0; j < 8; j++)
            #pragma unroll
            for (int t = 0; t < 4; t++) acc[i][j][t] = 0.f;

    auto issue_stage = [&](int c, int st) {
        const uint32_t stb = base + (uint32_t)st * STB;
        const int NJ = TWOPASS ? 8 : 6;
        #pragma unroll
        for (int j = 0; j < 8; j++) {
            if (j >= NJ) break;
            int idx = tid + j * 256;
            uint32_t dst; const __half* src;
            if (j < 2) {
                int row = idx >> 2, c16 = idx & 3;
                dst = stb + (uint32_t)row * 80 + c16 * 16;
                src = Ah_p + (size_t)row * DD + c * 32 + c16 * 8;
            } else if (TWOPASS && j < 4) {
                int rem = idx - 512;
                int row = rem >> 2, c16 = rem & 3;
                dst = stb + SEGA + (uint32_t)row * 80 + c16 * 16;
                src = Al_p + (size_t)row * DD + c * 32 + c16 * 8;
            } else {
                int rem = idx - (TWOPASS ? 1024 : 512);
                int row = rem >> 2, c16 = rem & 3;
                dst = stb + BOFF + (uint32_t)row * 80 + c16 * 16;
                src = Bh_p + (size_t)row * DD + c * 32 + c16 * 8;
            }
            CP_ASYNC16(dst, src);
        }
        CP_COMMIT();
    };

    issue_stage(0, 0);
    issue_stage(1, 1);

    for (int c = 0; c < DD / 32; c++) {
        CP_WAIT(1);
        __syncthreads();
        if (c + 2 < DD / 32) issue_stage(c + 2, (c + 2) % 3);
        else CP_COMMIT();

        const int st = c % 3;
        const uint32_t sAh = base + (uint32_t)st * STB;
        const uint32_t sAl = sAh + SEGA;
        const uint32_t sBh = sAh + BOFF;

        #pragma unroll
        for (int ks = 0; ks < 2; ks++) {
            uint32_t aH[4][4], aL[4][4];
            #pragma unroll
            for (int mf = 0; mf < 4; mf++) {
                ldsm4(aH[mf], sAh + (uint32_t)(rA + mf*16) * 80 + kA + ks*32);
                if (TWOPASS)
                    ldsm4(aL[mf], sAl + (uint32_t)(rA + mf*16) * 80 + kA + ks*32);
            }
            #pragma unroll
            for (int nf4 = 0; nf4 < 4; nf4++) {
                uint32_t bH[4];
                ldsm4(bH, sBh + (uint32_t)(rB + nf4*16) * 80 + kB + ks*32);
                #pragma unroll
                for (int mf = 0; mf < 4; mf++) {
                    mma16816(acc[mf][2*nf4],   aH[mf], bH + 0);
                    mma16816(acc[mf][2*nf4+1], aH[mf], bH + 2);
                    if (TWOPASS) {
                        mma16816(acc[mf][2*nf4],   aL[mf], bH + 0);
                        mma16816(acc[mf][2*nf4+1], aL[mf], bH + 2);
                    }
                }
            }
        }
    }

    const int gid = l >> 2, tig = l & 3;
    #pragma unroll
    for (int mf = 0; mf < 4; mf++) {
        #pragma unroll
        for (int nf = 0; nf < 8; nf++) {
            int r0 = bm + wm*64 + mf*16 + gid;
            int cc = bn + wn*64 + nf*8 + tig*2;
            if (OUTMODE == 2) {
                *(float2*)(Cf + (size_t)r0 * DD + cc)       = make_float2(acc[mf][nf][0], acc[mf][nf][1]);
                *(float2*)(Cf + (size_t)(r0 + 8) * DD + cc) = make_float2(acc[mf][nf][2], acc[mf][nf][3]);
            } else if (OUTMODE == 1) {
                *(uint32_t*)(Ch + (size_t)r0 * DD + cc)       = pack_h2(acc[mf][nf][0], acc[mf][nf][1]);
                *(uint32_t*)(Ch + (size_t)(r0 + 8) * DD + cc) = pack_h2(acc[mf][nf][2], acc[mf][nf][3]);
            } else {
                uint32_t h0, l0v, h1, l1v;
                split2(acc[mf][nf][0], acc[mf][nf][1], h0, l0v);
                split2(acc[mf][nf][2], acc[mf][nf][3], h1, l1v);
                *(uint32_t*)(Ch + (size_t)r0 * DD + cc)       = h0;
                *(uint32_t*)(Cl + (size_t)r0 * DD + cc)       = l0v;
                *(uint32_t*)(Ch + (size_t)(r0 + 8) * DD + cc) = h1;
                *(uint32_t*)(Cl + (size_t)(r0 + 8) * DD + cc) = l1v;
            }
        }
    }
}

__global__ __launch_bounds__(256) void gemm_qkv(
    const __half* __restrict__ Ah, const __half* __restrict__ Al,
    const __half* __restrict__ Wqh, __half* __restrict__ Qh, __half* __restrict__ Ql,
    const __half* __restrict__ Wkh, __half* __restrict__ Kh,
    const __half* __restrict__ Wvh, __half* __restrict__ Vh)
{
    extern __shared__ __half GS[];
    if (blockIdx.z == 0)
        gemm_body<0,1>(Ah, Al, Wqh, nullptr, Qh, Ql, GS);
    else if (blockIdx.z == 1)
        gemm_body<1,1>(Ah, Al, Wkh, nullptr, Kh, nullptr, GS);
    else
        gemm_body<1,1>(Ah, Al, Wvh, nullptr, Vh, nullptr, GS);
}

__global__ __launch_bounds__(256) void gemm_o(
    const __half* __restrict__ Ah,
    const __half* __restrict__ Bh, float* __restrict__ Cf)
{
    extern __shared__ __half GS[];
    gemm_body<2,0>(Ah, nullptr, Bh, Cf, nullptr, nullptr, GS);
}

// ===================== rel projection (split-K, fused q/k) ====================
__global__ __launch_bounds__(256) void rel_proj(
    const float* __restrict__ A, const float* __restrict__ Wq,
    const float* __restrict__ Wk, float* __restrict__ part)
{
    __shared__ __align__(16) float As[32][65];
    __shared__ __align__(16) float Ws[32][132];
    const int tid = threadIdx.x;
    const int m0 = blockIdx.x * 64;
    const int kb = blockIdx.y * 512;
    const int r0 = (tid >> 5) * 8;
    const int c0 = (tid & 31) * 4;

    float acc[8][4];
    #pragma unroll
    for (int i = 0; i < 8; i++)
        #pragma unroll
        for (int j = 0; j < 4; j++) acc[i][j] = 0.f;

    for (int k0 = 0; k0 < 512; k0 += 32) {
        #pragma unroll
        for (int t = 0; t < 2; t++) {
            int idx = tid + t * 256;
            int row = idx >> 3, gg = idx & 7;
            float4 v = *(const float4*)(A + (size_t)(m0 + row) * DD + kb + k0 + gg * 4);
            As[gg*4+0][row] = v.x; As[gg*4+1][row] = v.y;
            As[gg*4+2][row] = v.z; As[gg*4+3][row] = v.w;
        }
        #pragma unroll
        for (int t = 0; t < 4; t++) {
            int idx = tid + t * 256;
            int col = idx >> 3, gg = idx & 7;
            const float* src = (col < 64) ? (Wq + (size_t)col * DD)
                                          : (Wk + (size_t)(col - 64) * DD);
            float4 v = *(const float4*)(src + kb + k0 + gg * 4);
            Ws[gg*4+0][col] = v.x; Ws[gg*4+1][col] = v.y;
            Ws[gg*4+2][col] = v.z; Ws[gg*4+3][col] = v.w;
        }
        __syncthreads();
        #pragma unroll 8
        for (int kk = 0; kk < 32; kk++) {
            float4 w = *(const float4*)&Ws[kk][c0];
            #pragma unroll
            for (int i = 0; i < 8; i++) {
                float a = As[kk][r0 + i];
                acc[i][0] += a * w.x; acc[i][1] += a * w.y;
                acc[i][2] += a * w.z; acc[i][3] += a * w.w;
            }
        }
        __syncthreads();
    }
    float* dst = part + (size_t)blockIdx.y * MROWS * 128;
    #pragma unroll
    for (int i = 0; i < 8; i++) {
        float4 o = make_float4(acc[i][0], acc[i][1], acc[i][2], acc[i][3]);
        *(float4*)(dst + (size_t)(m0 + r0 + i) * 128 + c0) = o;
    }
}

// reduce split-K partials -> qrel/krel emitted as hi/lo fp16
__global__ __launch_bounds__(256) void rel_reduce(
    const float* __restrict__ part,
    __half* __restrict__ qh, __half* __restrict__ ql,
    __half* __restrict__ kh, __half* __restrict__ kl)
{
    int idx = blockIdx.x * 256 + threadIdx.x;
    int row = idx >> 6, col = idx & 63;
    float sq = 0.f, sk = 0.f;
    #pragma unroll
    for (int s = 0; s < 4; s++) {
        const float* p = part + (size_t)s * MROWS * 128 + (size_t)row * 128;
        sq += p[col]; sk += p[col + 64];
    }
    __half hq = __float2half_rn(sq);
    __half hk = __float2half_rn(sk);
    qh[(size_t)row * 64 + col] = hq;
    ql[(size_t)row * 64 + col] = __float2half_rn(sq - __half2float(hq));
    kh[(size_t)row * 64 + col] = hk;
    kl[(size_t)row * 64 + col] = __float2half_rn(sk - __half2float(hk));
}

// ======== rel score GEMM: S[b] = qrel · krel^T (3-pass fp16 split, fp32 out) ==
// Tile 128x128, causal lower-triangle tiles only. K=64, no pipeline needed.
#define RSTRIDE 144              // bytes per row (128B data + 16B pad; conflict-free)
#define RSEGB (128*RSTRIDE)      // 18432 B
#define RSMEM (4*RSEGB)          // 73728 B

__global__ __launch_bounds__(256) void score_mma(
    const __half* __restrict__ Qrh, const __half* __restrict__ Qrl,
    const __half* __restrict__ Krh, const __half* __restrict__ Krl,
    float* __restrict__ scores)
{
    const int j = blockIdx.x, i = blockIdx.y, b = blockIdx.z;
    if (j > i) return;
    extern __shared__ __half RS[];
    const uint32_t base = smem_u32(RS);
    const int tid = threadIdx.x;
    const int l = tid & 31, wid = tid >> 5;
    const int wm = wid >> 2, wn = wid & 3;
    const int q0 = i * 128, k0 = j * 128;

    const __half* srcs[4] = {
        Qrh + (size_t)(b*LL + q0) * DREL, Qrl + (size_t)(b*LL + q0) * DREL,
        Krh + (size_t)(b*LL + k0) * DREL, Krl + (size_t)(b*LL + k0) * DREL};

    #pragma unroll
    for (int jj = 0; jj < 16; jj++) {
        int idx = tid + jj * 256;            // 4096 16B chunks
        int seg = idx >> 10, rem = idx & 1023;
        int row = rem >> 3, c16 = rem & 7;
        uint32_t dst = base + (uint32_t)seg * RSEGB + (uint32_t)row * RSTRIDE + c16 * 16;
        const __half* src = srcs[seg] + (size_t)row * DREL + c16 * 8;
        CP_ASYNC16(dst, src);
    }
    CP_COMMIT();
    CP_WAIT(0);
    __syncthreads();

    const int rA = wm * 64 + ((l >> 3) & 1) * 8 + (l & 7);
    const int kA = (l >> 4) * 16;
    const int rB = wn * 32 + ((l >> 4) & 1) * 8 + (l & 7);
    const int kB = ((l >> 3) & 1) * 16;
    const uint32_t sQh = base, sQl = base + RSEGB;
    const uint32_t sKh = base + 2*RSEGB, sKl = base + 3*RSEGB;

    float acc[4][4][4];
    #pragma unroll
    for (int a = 0; a < 4; a++)
        #pragma unroll
        for (int c = 0; c < 4; c++)
            #pragma unroll
            for (int t = 0; t < 4; t++) acc[a][c][t] = 0.f;

    #pragma unroll
    for (int ks = 0; ks < 4; ks++) {          // K=64 halves = 4 k16 steps
        uint32_t aH[4][4], aL[4][4];
        #pragma unroll
        for (int mf = 0; mf < 4; mf++) {
            ldsm4(aH[mf], sQh + (uint32_t)(rA + mf*16) * RSTRIDE + kA + ks*32);
            ldsm4(aL[mf], sQl + (uint32_t)(rA + mf*16) * RSTRIDE + kA + ks*32);
        }
        #pragma unroll
        for (int nf2 = 0; nf2 < 2; nf2++) {
            uint32_t bH[4], bL[4];
            ldsm4(bH, sKh + (uint32_t)(rB + nf2*16) * RSTRIDE + kB + ks*32);
            #pragma unroll
            for (int mf = 0; mf < 4; mf++) {
                mma16816(acc[mf][2*nf2],   aH[mf], bH + 0);
                mma16816(acc[mf][2*nf2+1], aH[mf], bH + 2);
                mma16816(acc[mf][2*nf2],   aL[mf], bH + 0);
                mma16816(acc[mf][2*nf2+1], aL[mf], bH + 2);
            }
            ldsm4(bL, sKl + (uint32_t)(rB + nf2*16) * RSTRIDE + kB + ks*32);
            #pragma unroll
            for (int mf = 0; mf < 4; mf++) {
                mma16816(acc[mf][2*nf2],   aH[mf], bL + 0);
                mma16816(acc[mf][2*nf2+1], aH[mf], bL + 2);
            }
        }
    }

    const int gid = l >> 2, tig = l & 3;
    #pragma unroll
    for (int mf = 0; mf < 4; mf++) {
        #pragma unroll
        for (int nf = 0; nf < 4; nf++) {
            int r0 = q0 + wm*64 + mf*16 + gid;
            int cc = k0 + wn*32 + nf*8 + tig*2;
            float* s0p = scores + ((size_t)(b*LL) + r0) * LL + cc;
            *(float2*)s0p            = make_float2(acc[mf][nf][0], acc[mf][nf][1]);
            *(float2*)(s0p + 8 * LL) = make_float2(acc[mf][nf][2], acc[mf][nf][3]);
        }
    }
}

// ====================== top-K mask build (one block per (b,q)) ================
__device__ __forceinline__ unsigned ford(float f) {
    unsigned u = __float_as_uint(f);
    return (u & 0x80000000u) ? ~u : (u | 0x80000000u);
}

__global__ __launch_bounds__(256) void build_mask(
    const float* __restrict__ scores, unsigned* __restrict__ mask)
{
    const int q = blockIdx.x;
    const int b = blockIdx.y;
    const int tid = threadIdx.x;

    __shared__ float    s[LL];
    __shared__ unsigned mw[LL/32];
    __shared__ int      hist[256];
    __shared__ int      scan[256];
    __shared__ unsigned sh_prefix;
    __shared__ int      sh_R;

    if (tid < LL/32) mw[tid] = 0u;
    const int n = q + 1;

    if (n <= KSEL) {
        __syncthreads();
        for (int k = tid; k < n; k += 256)
            atomicOr(&mw[k>>5], 1u << (k & 31));
    } else {
        const float* srow = scores + ((size_t)(b*LL + q)) * LL;
        for (int k = tid; k < n; k += 256) s[k] = srow[k];
        __syncthreads();

        unsigned prefix = 0u; int R = KSEL;
        for (int byte = 3; byte >= 0; byte--) {
            hist[tid] = 0;
            __syncthreads();
            const int shift = byte * 8;
            const unsigned pm = (byte == 3) ? 0u : (0xFFFFFFFFu << (shift + 8));
            for (int k = tid; k < n; k += 256) {
                unsigned u = ford(s[k]);
                if ((u & pm) == (prefix & pm))
                    atomicAdd(&hist[(u >> shift) & 255], 1);
            }
            __syncthreads();
            int hv = hist[tid];
            scan[tid] = hv;
            __syncthreads();
            #pragma unroll
            for (int off = 1; off < 256; off <<= 1) {
                int t = (tid + off < 256) ? scan[tid + off] : 0;
                __syncthreads();
                scan[tid] += t;
                __syncthreads();
            }
            int inc = scan[tid];
            int above = inc - hv;
            if (above < R && inc >= R) {
                sh_prefix = prefix | ((unsigned)tid << shift);
                sh_R = R - above;
            }
            __syncthreads();
            prefix = sh_prefix; R = sh_R;
            __syncthreads();
        }
        const unsigned T = prefix;
        for (int k = tid; k < n; k += 256)
            if (ford(s[k]) > T) atomicOr(&mw[k>>5], 1u << (k & 31));
        const int per = (n + 255) >> 8;
        const int lo = tid * per;
        const int hi = (lo + per < n) ? lo + per : n;
        int cnt = 0;
        for (int k = lo; k < hi; k++)
            if (ford(s[k]) == T) cnt++;
        scan[tid] = cnt;
        __syncthreads();
        #pragma unroll
        for (int off = 1; off < 256; off <<= 1) {
            int t = (tid >= off) ? scan[tid - off] : 0;
            __syncthreads();
            scan[tid] += t;
            __syncthreads();
        }
        int excl = scan[tid] - cnt;
        int r2 = R - excl;
        if (r2 > 0) {
            for (int k = lo; k < hi && r2 > 0; k++)
                if (ford(s[k]) == T) { atomicOr(&mw[k>>5], 1u << (k & 31)); r2--; }
        }
    }
    __syncthreads();
    if (tid == 0) mw[q>>5] |= 1u << (q & 31);
    __syncthreads();
    if (tid < LL/32) mask[(size_t)(b*LL + q)*(LL/32) + tid] = mw[tid];
}

// ====================== flash attention (2-pass fp16 mma) =====================
// 4 warps, Q-tile 64 rows (hi+lo), K/V tiles 64 (hi), double-buffered, 2 CTAs/SM.
#define QSEG 8704       // 64*136 halves
#define KSEG 8704
#define FOFF_QH 0
#define FOFF_QL QSEG
#define KVOFF(st, seg) (2*QSEG + (st)*2*KSEG + (seg)*KSEG)
#define FMASK_B ((2*QSEG + 4*KSEG)*2)
#define FSMEM   (FMASK_B + 2*512)
#define SC2 0.12751744416168355f               // (1/sqrt(128)) * log2(e)

__global__ __launch_bounds__(128) void flash_mma(
    const __half* __restrict__ Qh, const __half* __restrict__ Ql,
    const __half* __restrict__ Kh, const __half* __restrict__ Vh,
    const unsigned* __restrict__ mask,
    __half* __restrict__ Ch)
{
    extern __shared__ __half FS[];
    const uint32_t base = smem_u32(FS);
    const uint32_t maskB = base + FMASK_B;

    const int qt = (int)gridDim.x - 1 - (int)blockIdx.x;   // heavy tiles first
    const int h = blockIdx.y, b = blockIdx.z;
    const int q0 = qt * 64;
    const int tid = threadIdx.x;
    const int w = tid >> 5, l = tid & 31;
    const int gid = l >> 2, tig = l & 3;

    {
        const __half* qs[2] = {Qh, Ql};
        #pragma unroll
        for (int j = 0; j < 16; j++) {
            int idx = tid + j * 128;
            int seg = idx >> 10, rem = idx & 1023;
            int row = rem >> 4, c16 = rem & 15;
            uint32_t dst = base + (uint32_t)(seg * QSEG + row * 136 + c16 * 8) * 2;
            const __half* src = qs[seg] + (size_t)(b*LL + q0 + row) * DD + h * DHD + c16 * 8;
            CP_ASYNC16(dst, src);
        }
        CP_COMMIT();
    }

    auto issue_kv = [&](int kt, int st) {
        const __half* ks[2] = {Kh, Vh};
        #pragma unroll
        for (int j = 0; j < 16; j++) {
            int idx = tid + j * 128;
            int seg = idx >> 10, rem = idx & 1023;
            int row = rem >> 4, c16 = rem & 15;
            uint32_t dst = base + (uint32_t)(KVOFF(st, seg) + row * 136 + c16 * 8) * 2;
            const __half* src = ks[seg] + (size_t)(b*LL + kt*64 + row) * DD + h * DHD + c16 * 8;
            CP_ASYNC16(dst, src);
        }
        if (tid < 64) {
            uint32_t dst = maskB + st * 512 + tid * 8;
            const unsigned* src = &mask[(size_t)(b*LL + q0 + tid) * (LL/32) + kt*2];
            CP_ASYNC8(dst, src);
        }
        CP_COMMIT();
    };

    issue_kv(0, 0);

    const int qa_row = w * 16 + ((l >> 3) & 1) * 8 + (l & 7);
    const int qa_colB = (l >> 4) * 16;
    const int kb_rowBase = ((l >> 4) & 1) * 8 + (l & 7);
    const int kb_colB = ((l >> 3) & 1) * 16;
    const int v_row = l & 15;
    const int v_colB = (l >> 4) * 16;

    float O[16][4];
    #pragma unroll
    for (int i = 0; i < 16; i++)
        #pragma unroll
        for (int t = 0; t < 4; t++) O[i][t] = 0.f;
    float m0 = -1e30f, m1 = -1e30f, rl0 = 0.f, rl1 = 0.f;

    const int rlo2 = (w*16 + gid) * 2;
    const int rhi2 = rlo2 + 16;

    const int ktiles = qt + 1;
    for (int kt = 0; kt < ktiles; kt++) {
        const int st = kt & 1;
        if (kt + 1 < ktiles) {
            __syncthreads();
            issue_kv(kt + 1, st ^ 1);
            CP_WAIT(1);
        } else {
            CP_WAIT(0);
        }
        __syncthreads();

        const uint32_t sKH = base + (uint32_t)KVOFF(st, 0) * 2;
        const uint32_t sVH = base + (uint32_t)KVOFF(st, 1) * 2;
        const uint32_t* maskS = (const uint32_t*)(FS) + (FMASK_B >> 2) + st * 128;

        float Sc[8][4];
        #pragma unroll
        for (int i = 0; i < 8; i++)
            #pragma unroll
            for (int t = 0; t < 4; t++) Sc[i][t] = 0.f;

        #pragma unroll
        for (int kf = 0; kf < 8; kf++) {
            uint32_t aH[4], aL[4];
            ldsm4(aH, base + (uint32_t)(FOFF_QH + qa_row * 136) * 2 + kf*32 + qa_colB);
            ldsm4(aL, base + (uint32_t)(FOFF_QL + qa_row * 136) * 2 + kf*32 + qa_colB);
            #pragma unroll
            for (int nf2 = 0; nf2 < 4; nf2++) {
                uint32_t bH[4];
                ldsm4(bH, sKH + (uint32_t)((nf2*16 + kb_rowBase) * 136) * 2 + kf*32 + kb_colB);
                mma16816(Sc[2*nf2],   aH, bH + 0);
                mma16816(Sc[2*nf2+1], aH, bH + 2);
                mma16816(Sc[2*nf2],   aL, bH + 0);
                mma16816(Sc[2*nf2+1], aL, bH + 2);
            }
        }

        #pragma unroll
        for (int nf = 0; nf < 8; nf++) {
            unsigned wlo = maskS[rlo2 + (nf >> 2)];
            unsigned whi = maskS[rhi2 + (nf >> 2)];
            int sh = ((nf & 3) << 3) + (tig << 1);
            Sc[nf][0] = ((wlo >> sh) & 1u)     ? Sc[nf][0] : -1e30f;
            Sc[nf][1] = ((wlo >> (sh+1)) & 1u) ? Sc[nf][1] : -1e30f;
            Sc[nf][2] = ((whi >> sh) & 1u)     ? Sc[nf][2] : -1e30f;
            Sc[nf][3] = ((whi >> (sh+1)) & 1u) ? Sc[nf][3] : -1e30f;
        }

        float mx0 = -1e30f, mx1 = -1e30f;
        #pragma unroll
        for (int nf = 0; nf < 8; nf++) {
            mx0 = fmaxf(mx0, fmaxf(Sc[nf][0], Sc[nf][1]));
            mx1 = fmaxf(mx1, fmaxf(Sc[nf][2], Sc[nf][3]));
        }
        mx0 = fmaxf(mx0, __shfl_xor_sync(0xffffffffu, mx0, 1));
        mx0 = fmaxf(mx0, __shfl_xor_sync(0xffffffffu, mx0, 2));
        mx1 = fmaxf(mx1, __shfl_xor_sync(0xffffffffu, mx1, 1));
        mx1 = fmaxf(mx1, __shfl_xor_sync(0xffffffffu, mx1, 2));
        float nm0 = fmaxf(m0, mx0), nm1 = fmaxf(m1, mx1);
        float a0 = ex2f((m0 - nm0) * SC2), a1 = ex2f((m1 - nm1) * SC2);
        m0 = nm0; m1 = nm1;

        float s0 = 0.f, s1 = 0.f;
        #pragma unroll
        for (int nf = 0; nf < 8; nf++) {
            float p0 = ex2f((Sc[nf][0] - m0) * SC2);
            float p1 = ex2f((Sc[nf][1] - m0) * SC2);
            float p2 = ex2f((Sc[nf][2] - m1) * SC2);
            float p3 = ex2f((Sc[nf][3] - m1) * SC2);
            Sc[nf][0] = p0; Sc[nf][1] = p1; Sc[nf][2] = p2; Sc[nf][3] = p3;
            s0 += p0 + p1; s1 += p2 + p3;
        }
        s0 += __shfl_xor_sync(0xffffffffu, s0, 1);
        s0 += __shfl_xor_sync(0xffffffffu, s0, 2);
        s1 += __shfl_xor_sync(0xffffffffu, s1, 1);
        s1 += __shfl_xor_sync(0xffffffffu, s1, 2);
        rl0 = rl0 * a0 + s0;
        rl1 = rl1 * a1 + s1;

        #pragma unroll
        for (int df = 0; df < 16; df++) {
            O[df][0] *= a0; O[df][1] *= a0;
            O[df][2] *= a1; O[df][3] *= a1;
        }

        #pragma unroll
        for (int kf = 0; kf < 4; kf++) {
            uint32_t Pha[4], Pla[4];
            split2(Sc[2*kf][0],   Sc[2*kf][1],   Pha[0], Pla[0]);
            split2(Sc[2*kf][2],   Sc[2*kf][3],   Pha[1], Pla[1]);
            split2(Sc[2*kf+1][0], Sc[2*kf+1][1], Pha[2], Pla[2]);
            split2(Sc[2*kf+1][2], Sc[2*kf+1][3], Pha[3], Pla[3]);
            #pragma unroll
            for (int df2 = 0; df2 < 8; df2++) {
                uint32_t vh4[4];
                ldsm4t(vh4, sVH + (uint32_t)((kf*16 + v_row) * 136) * 2 + df2*32 + v_colB);
                mma16816(O[2*df2],   Pha, vh4 + 0);
                mma16816(O[2*df2+1], Pha, vh4 + 2);
                mma16816(O[2*df2],   Pla, vh4 + 0);
                mma16816(O[2*df2+1], Pla, vh4 + 2);
            }
        }
    }

    float inv0 = 1.f / rl0, inv1 = 1.f / rl1;
    const size_t rowlo = (size_t)(b*LL + q0 + w*16 + gid) * DD + h * DHD + tig * 2;
    const size_t rowhi = rowlo + 8 * DD;
    #pragma unroll
    for (int df = 0; df < 16; df++) {
        *(uint32_t*)(Ch + rowlo + df*8) = pack_h2(O[df][0] * inv0, O[df][1] * inv0);
        *(uint32_t*)(Ch + rowhi + df*8) = pack_h2(O[df][2] * inv1, O[df][3] * inv1);
    }
}

// ================================ launch ======================================
extern "C" void kernel_launch(void* const* d_in, const int* in_sizes, int n_in,
                              void* d_out, int out_size)
{
    const float* hidden    = (const float*)d_in[0];
    const float* relevance = (const float*)d_in[1];
    const float* Wqr       = (const float*)d_in[2];
    const float* Wkr       = (const float*)d_in[3];
    const float* Wq        = (const float*)d_in[4];
    const float* Wk        = (const float*)d_in[5];
    const float* Wv        = (const float*)d_in[6];
    const float* Wo        = (const float*)d_in[7];
    float* out = (float*)d_out;

    __half *hidh,*hidl,*wqh,*wkh,*wvh,*woh;
    __half *qh,*ql,*kh,*vh,*ctxh;
    __half *qrelh,*qrell,*krelh,*krell;
    float *relp,*scores; unsigned* mask;
    cudaGetSymbolAddress((void**)&hidh, g_hidh); cudaGetSymbolAddress((void**)&hidl, g_hidl);
    cudaGetSymbolAddress((void**)&wqh,  g_wqh);
    cudaGetSymbolAddress((void**)&wkh,  g_wkh);
    cudaGetSymbolAddress((void**)&wvh,  g_wvh);
    cudaGetSymbolAddress((void**)&woh,  g_woh);
    cudaGetSymbolAddress((void**)&qh,   g_qh);   cudaGetSymbolAddress((void**)&ql,   g_ql);
    cudaGetSymbolAddress((void**)&kh,   g_kh);
    cudaGetSymbolAddress((void**)&vh,   g_vh);
    cudaGetSymbolAddress((void**)&ctxh, g_ctxh);
    cudaGetSymbolAddress((void**)&qrelh, g_qrelh); cudaGetSymbolAddress((void**)&qrell, g_qrell);
    cudaGetSymbolAddress((void**)&krelh, g_krelh); cudaGetSymbolAddress((void**)&krell, g_krell);
    cudaGetSymbolAddress((void**)&scores, g_scores);
    cudaGetSymbolAddress((void**)&relp, g_relp); cudaGetSymbolAddress((void**)&mask, g_mask);

    cudaFuncSetAttribute(gemm_qkv, cudaFuncAttributeMaxDynamicSharedMemorySize, GSMEM);
    cudaFuncSetAttribute(gemm_o,   cudaFuncAttributeMaxDynamicSharedMemorySize, GSMEM);
    cudaFuncSetAttribute(flash_mma, cudaFuncAttributeMaxDynamicSharedMemorySize, FSMEM);
    cudaFuncSetAttribute(score_mma, cudaFuncAttributeMaxDynamicSharedMemorySize, RSMEM);

    static cudaStream_t sSide = nullptr;
    static cudaEvent_t  evFork = nullptr, evJoin = nullptr;
    if (sSide == nullptr) {
        cudaStreamCreateWithFlags(&sSide, cudaStreamNonBlocking);
        cudaEventCreateWithFlags(&evFork, cudaEventDisableTiming);
        cudaEventCreateWithFlags(&evJoin, cudaEventDisableTiming);
    }

    const int nh4 = MROWS * DD / 4, nw4 = DD * DD / 4;

    // ---- fork: relevance/mask path (+ Wo cvt) on side stream ----
    cudaEventRecord(evFork, 0);
    cudaStreamWaitEvent(sSide, evFork, 0);
    rel_proj<<<dim3(MROWS/64, 4), 256, 0, sSide>>>(relevance, Wqr, Wkr, relp);
    rel_reduce<<<(MROWS*64)/256, 256, 0, sSide>>>(relp, qrelh, qrell, krelh, krell);
    score_mma<<<dim3(16, 16, BB), 256, RSMEM, sSide>>>(qrelh, qrell, krelh, krell, scores);
    build_mask<<<dim3(LL, BB), 256, 0, sSide>>>(scores, mask);
    cvt_hi<<<(nw4 + 255)/256, 256, 0, sSide>>>((const float4*)Wo, (uint2*)woh, nw4);
    cudaEventRecord(evJoin, sSide);

    // ---- main stream: conversions + QKV ----
    cvt_split<<<(nh4 + 255)/256, 256>>>((const float4*)hidden, (uint2*)hidh, (uint2*)hidl, nh4);
    cvt_hi3<<<dim3((nw4 + 255)/256, 3), 256>>>(
        (const float4*)Wq, (const float4*)Wk, (const float4*)Wv,
        (uint2*)wqh, (uint2*)wkh, (uint2*)wvh, nw4);

    gemm_qkv<<<dim3(DD/256, MROWS/128, 3), 256, GSMEM>>>(
        hidh, hidl, wqh, qh, ql, wkh, kh, wvh, vh);

    // ---- join, then attention + output projection ----
    cudaStreamWaitEvent(0, evJoin, 0);
    flash_mma<<<dim3(LL/64, HH, BB), 128, FSMEM>>>(qh, ql, kh, vh, mask, ctxh);
    gemm_o<<<dim3(DD/256, MROWS/128), 256, GSMEM>>>(ctxh, woh, out);
}

// round 10
// speedup vs baseline: 7.7812x; 1.2646x over previous
#include <cuda_runtime.h>
#include <cuda_fp16.h>
#include <cstdint>
#include <math.h>

// Problem constants
#define BB   2
#define LL   2048
#define DD   2048
#define HH   16
#define DHD  128
#define DREL 64
#define KSEL 512
#define MROWS (BB*LL)   // 4096

// -------------------- scratch (device globals; no cudaMalloc allowed) ---------
__device__ __align__(256) __half g_hidh[MROWS*DD];
__device__ __align__(256) __half g_hidl[MROWS*DD];
__device__ __align__(256) __half g_wqh [DD*DD];
__device__ __align__(256) __half g_wkh [DD*DD];
__device__ __align__(256) __half g_wvh [DD*DD];
__device__ __align__(256) __half g_woh [DD*DD];
__device__ __align__(256) __half g_qh  [MROWS*DD];
__device__ __align__(256) __half g_kh  [MROWS*DD];
__device__ __align__(256) __half g_vh  [MROWS*DD];
__device__ __align__(256) __half g_ctxh[MROWS*DD];
__device__ __align__(256) __half g_qrelh[MROWS*DREL];
__device__ __align__(256) __half g_qrell[MROWS*DREL];
__device__ __align__(256) __half g_krelh[MROWS*DREL];
__device__ __align__(256) __half g_krell[MROWS*DREL];
__device__ __align__(256) float    g_scores[(size_t)BB*LL*LL];
__device__ __align__(256) float    g_relp[4*MROWS*128];
__device__ __align__(256) unsigned g_mask[BB*LL*(LL/32)];

// ========================= inline PTX helpers =================================
__device__ __forceinline__ uint32_t smem_u32(const void* p) {
    uint32_t a;
    asm("{ .reg .u64 t; cvta.to.shared.u64 t, %1; cvt.u32.u64 %0, t; }" : "=r"(a) : "l"(p));
    return a;
}
__device__ __forceinline__ void ldsm4(uint32_t* r, uint32_t addr) {
    asm volatile("ldmatrix.sync.aligned.m8n8.x4.shared.b16 {%0,%1,%2,%3}, [%4];"
        : "=r"(r[0]), "=r"(r[1]), "=r"(r[2]), "=r"(r[3]) : "r"(addr));
}
__device__ __forceinline__ void ldsm4t(uint32_t* r, uint32_t addr) {
    asm volatile("ldmatrix.sync.aligned.m8n8.x4.trans.shared.b16 {%0,%1,%2,%3}, [%4];"
        : "=r"(r[0]), "=r"(r[1]), "=r"(r[2]), "=r"(r[3]) : "r"(addr));
}
__device__ __forceinline__ void mma16816(float* c, const uint32_t* a, const uint32_t* b) {
    asm volatile("mma.sync.aligned.m16n8k16.row.col.f32.f16.f16.f32 "
        "{%0,%1,%2,%3}, {%4,%5,%6,%7}, {%8,%9}, {%0,%1,%2,%3};"
        : "+f"(c[0]), "+f"(c[1]), "+f"(c[2]), "+f"(c[3])
        : "r"(a[0]), "r"(a[1]), "r"(a[2]), "r"(a[3]), "r"(b[0]), "r"(b[1]));
}
#define CP_ASYNC16(dst, src) \
    asm volatile("cp.async.cg.shared.global [%0], [%1], 16;" :: "r"(dst), "l"(src) : "memory")
#define CP_ASYNC8(dst, src) \
    asm volatile("cp.async.ca.shared.global [%0], [%1], 8;" :: "r"(dst), "l"(src) : "memory")
#define CP_COMMIT() asm volatile("cp.async.commit_group;" ::: "memory")
#define CP_WAIT(n)  asm volatile("cp.async.wait_group %0;" :: "n"(n) : "memory")

__device__ __forceinline__ float ex2f(float x) {
    float y; asm("ex2.approx.f32 %0, %1;" : "=f"(y) : "f"(x)); return y;
}
__device__ __forceinline__ void split2(float x, float y, uint32_t& hi, uint32_t& lo) {
    __half hx = __float2half_rn(x), hy = __float2half_rn(y);
    __half lx = __float2half_rn(x - __half2float(hx));
    __half ly = __float2half_rn(y - __half2float(hy));
    hi = ((uint32_t)__half_as_ushort(hy) << 16) | __half_as_ushort(hx);
    lo = ((uint32_t)__half_as_ushort(ly) << 16) | __half_as_ushort(lx);
}
__device__ __forceinline__ uint32_t pack_h2(float x, float y) {
    __half hx = __float2half_rn(x), hy = __float2half_rn(y);
    return ((uint32_t)__half_as_ushort(hy) << 16) | __half_as_ushort(hx);
}

// =========================== fp32 -> fp16 conversions =========================
__global__ __launch_bounds__(256) void cvt_split(
    const float4* __restrict__ x, uint2* __restrict__ h, uint2* __restrict__ lo, int n4)
{
    int i = blockIdx.x * 256 + threadIdx.x;
    if (i >= n4) return;
    float4 v = x[i];
    uint32_t h0, l0, h1, l1;
    split2(v.x, v.y, h0, l0);
    split2(v.z, v.w, h1, l1);
    h[i]  = make_uint2(h0, h1);
    lo[i] = make_uint2(l0, l1);
}

__global__ __launch_bounds__(256) void cvt_hi(
    const float4* __restrict__ x, uint2* __restrict__ h, int n4)
{
    int i = blockIdx.x * 256 + threadIdx.x;
    if (i >= n4) return;
    float4 v = x[i];
    h[i] = make_uint2(pack_h2(v.x, v.y), pack_h2(v.z, v.w));
}

__global__ __launch_bounds__(256) void cvt_hi3(
    const float4* __restrict__ w0, const float4* __restrict__ w1, const float4* __restrict__ w2,
    uint2* __restrict__ h0, uint2* __restrict__ h1, uint2* __restrict__ h2, int n4)
{
    const float4* src = (blockIdx.y == 0) ? w0 : (blockIdx.y == 1) ? w1 : w2;
    uint2* dst        = (blockIdx.y == 0) ? h0 : (blockIdx.y == 1) ? h1 : h2;
    int i = blockIdx.x * 256 + threadIdx.x;
    if (i >= n4) return;
    float4 v = src[i];
    dst[i] = make_uint2(pack_h2(v.x, v.y), pack_h2(v.z, v.w));
}

// ===== fp16-split GEMM: C = (Ah[+Al]) · Bh^T ==================================
// CTA tile 128x256, warp tile 64x64 (8 warps), k-chunk 32, 3-stage cp.async.
#define SEGA 10240               // Ah/Al segment: 128 rows x 80B
#define SEGB2 20480              // Bh segment: 256 rows x 80B
#define STAGE2B (2*SEGA + SEGB2) // 40960 (2-pass stage)
#define STAGE1B (SEGA + SEGB2)   // 30720 (1-pass stage)
#define GSMEM (3*STAGE2B)        // 122880

// OUTMODE: 1 = hi fp16 out, 2 = fp32 out
template<int OUTMODE, int TWOPASS>
__device__ __forceinline__ void gemm_body(
    const __half* __restrict__ Ah, const __half* __restrict__ Al,
    const __half* __restrict__ Bh,
    float* __restrict__ Cf, __half* __restrict__ Ch,
    __half* GS)
{
    const uint32_t base = smem_u32(GS);
    const int tid = threadIdx.x;
    const int l   = tid & 31;
    const int wid = tid >> 5;
    const int wm  = wid >> 2;
    const int wn  = wid & 3;
    const int bm  = blockIdx.y * 128;
    const int bn  = blockIdx.x * 256;
    const uint32_t STB = TWOPASS ? STAGE2B : STAGE1B;
    const uint32_t BOFF = TWOPASS ? 2*SEGA : SEGA;

    const __half* Ah_p = Ah + (size_t)bm * DD;
    const __half* Al_p = TWOPASS ? (Al + (size_t)bm * DD) : nullptr;
    const __half* Bh_p = Bh + (size_t)bn * DD;

    const int rA = wm * 64 + ((l >> 3) & 1) * 8 + (l & 7);
    const int kA = (l >> 4) * 16;
    const int rB = wn * 64 + ((l >> 4) & 1) * 8 + (l & 7);
    const int kB = ((l >> 3) & 1) * 16;

    float acc[4][8][4];
    #pragma unroll
    for (int i = 0; i < 4; i++)
        #pragma unroll
        for (int j = 0; j < 8; j++)
            #pragma unroll
            for (int t = 0; t < 4; t++) acc[i][j][t] = 0.f;

    auto issue_stage = [&](int c, int st) {
        const uint32_t stb = base + (uint32_t)st * STB;
        const int NJ = TWOPASS ? 8 : 6;
        #pragma unroll
        for (int j = 0; j < 8; j++) {
            if (j >= NJ) break;
            int idx = tid + j * 256;
            uint32_t dst; const __half* src;
            if (j < 2) {
                int row = idx >> 2, c16 = idx & 3;
                dst = stb + (uint32_t)row * 80 + c16 * 16;
                src = Ah_p + (size_t)row * DD + c * 32 + c16 * 8;
            } else if (TWOPASS && j < 4) {
                int rem = idx - 512;
                int row = rem >> 2, c16 = rem & 3;
                dst = stb + SEGA + (uint32_t)row * 80 + c16 * 16;
                src = Al_p + (size_t)row * DD + c * 32 + c16 * 8;
            } else {
                int rem = idx - (TWOPASS ? 1024 : 512);
                int row = rem >> 2, c16 = rem & 3;
                dst = stb + BOFF + (uint32_t)row * 80 + c16 * 16;
                src = Bh_p + (size_t)row * DD + c * 32 + c16 * 8;
            }
            CP_ASYNC16(dst, src);
        }
        CP_COMMIT();
    };

    issue_stage(0, 0);
    issue_stage(1, 1);

    for (int c = 0; c < DD / 32; c++) {
        CP_WAIT(1);
        __syncthreads();
        if (c + 2 < DD / 32) issue_stage(c + 2, (c + 2) % 3);
        else CP_COMMIT();

        const int st = c % 3;
        const uint32_t sAh = base + (uint32_t)st * STB;
        const uint32_t sAl = sAh + SEGA;
        const uint32_t sBh = sAh + BOFF;

        #pragma unroll
        for (int ks = 0; ks < 2; ks++) {
            uint32_t aH[4][4], aL[4][4];
            #pragma unroll
            for (int mf = 0; mf < 4; mf++) {
                ldsm4(aH[mf], sAh + (uint32_t)(rA + mf*16) * 80 + kA + ks*32);
                if (TWOPASS)
                    ldsm4(aL[mf], sAl + (uint32_t)(rA + mf*16) * 80 + kA + ks*32);
            }
            #pragma unroll
            for (int nf4 = 0; nf4 < 4; nf4++) {
                uint32_t bH[4];
                ldsm4(bH, sBh + (uint32_t)(rB + nf4*16) * 80 + kB + ks*32);
                #pragma unroll
                for (int mf = 0; mf < 4; mf++) {
                    mma16816(acc[mf][2*nf4],   aH[mf], bH + 0);
                    mma16816(acc[mf][2*nf4+1], aH[mf], bH + 2);
                    if (TWOPASS) {
                        mma16816(acc[mf][2*nf4],   aL[mf], bH + 0);
                        mma16816(acc[mf][2*nf4+1], aL[mf], bH + 2);
                    }
                }
            }
        }
    }

    const int gid = l >> 2, tig = l & 3;
    #pragma unroll
    for (int mf = 0; mf < 4; mf++) {
        #pragma unroll
        for (int nf = 0; nf < 8; nf++) {
            int r0 = bm + wm*64 + mf*16 + gid;
            int cc = bn + wn*64 + nf*8 + tig*2;
            if (OUTMODE == 2) {
                *(float2*)(Cf + (size_t)r0 * DD + cc)       = make_float2(acc[mf][nf][0], acc[mf][nf][1]);
                *(float2*)(Cf + (size_t)(r0 + 8) * DD + cc) = make_float2(acc[mf][nf][2], acc[mf][nf][3]);
            } else {
                *(uint32_t*)(Ch + (size_t)r0 * DD + cc)       = pack_h2(acc[mf][nf][0], acc[mf][nf][1]);
                *(uint32_t*)(Ch + (size_t)(r0 + 8) * DD + cc) = pack_h2(acc[mf][nf][2], acc[mf][nf][3]);
            }
        }
    }
}

// Q: 2-pass input, hi out. K/V: 1-pass input, hi out.
__global__ __launch_bounds__(256) void gemm_qkv(
    const __half* __restrict__ Ah, const __half* __restrict__ Al,
    const __half* __restrict__ Wqh, __half* __restrict__ Qh,
    const __half* __restrict__ Wkh, __half* __restrict__ Kh,
    const __half* __restrict__ Wvh, __half* __restrict__ Vh)
{
    extern __shared__ __half GS[];
    if (blockIdx.z == 0)
        gemm_body<1,1>(Ah, Al, Wqh, nullptr, Qh, GS);
    else if (blockIdx.z == 1)
        gemm_body<1,0>(Ah, nullptr, Wkh, nullptr, Kh, GS);
    else
        gemm_body<1,0>(Ah, nullptr, Wvh, nullptr, Vh, GS);
}

__global__ __launch_bounds__(256) void gemm_o(
    const __half* __restrict__ Ah,
    const __half* __restrict__ Bh, float* __restrict__ Cf)
{
    extern __shared__ __half GS[];
    gemm_body<2,0>(Ah, nullptr, Bh, Cf, nullptr, GS);
}

// ===================== rel projection (split-K, fused q/k) ====================
__global__ __launch_bounds__(256) void rel_proj(
    const float* __restrict__ A, const float* __restrict__ Wq,
    const float* __restrict__ Wk, float* __restrict__ part)
{
    __shared__ __align__(16) float As[32][65];
    __shared__ __align__(16) float Ws[32][132];
    const int tid = threadIdx.x;
    const int m0 = blockIdx.x * 64;
    const int kb = blockIdx.y * 512;
    const int r0 = (tid >> 5) * 8;
    const int c0 = (tid & 31) * 4;

    float acc[8][4];
    #pragma unroll
    for (int i = 0; i < 8; i++)
        #pragma unroll
        for (int j = 0; j < 4; j++) acc[i][j] = 0.f;

    for (int k0 = 0; k0 < 512; k0 += 32) {
        #pragma unroll
        for (int t = 0; t < 2; t++) {
            int idx = tid + t * 256;
            int row = idx >> 3, gg = idx & 7;
            float4 v = *(const float4*)(A + (size_t)(m0 + row) * DD + kb + k0 + gg * 4);
            As[gg*4+0][row] = v.x; As[gg*4+1][row] = v.y;
            As[gg*4+2][row] = v.z; As[gg*4+3][row] = v.w;
        }
        #pragma unroll
        for (int t = 0; t < 4; t++) {
            int idx = tid + t * 256;
            int col = idx >> 3, gg = idx & 7;
            const float* src = (col < 64) ? (Wq + (size_t)col * DD)
                                          : (Wk + (size_t)(col - 64) * DD);
            float4 v = *(const float4*)(src + kb + k0 + gg * 4);
            Ws[gg*4+0][col] = v.x; Ws[gg*4+1][col] = v.y;
            Ws[gg*4+2][col] = v.z; Ws[gg*4+3][col] = v.w;
        }
        __syncthreads();
        #pragma unroll 8
        for (int kk = 0; kk < 32; kk++) {
            float4 w = *(const float4*)&Ws[kk][c0];
            #pragma unroll
            for (int i = 0; i < 8; i++) {
                float a = As[kk][r0 + i];
                acc[i][0] += a * w.x; acc[i][1] += a * w.y;
                acc[i][2] += a * w.z; acc[i][3] += a * w.w;
            }
        }
        __syncthreads();
    }
    float* dst = part + (size_t)blockIdx.y * MROWS * 128;
    #pragma unroll
    for (int i = 0; i < 8; i++) {
        float4 o = make_float4(acc[i][0], acc[i][1], acc[i][2], acc[i][3]);
        *(float4*)(dst + (size_t)(m0 + r0 + i) * 128 + c0) = o;
    }
}

__global__ __launch_bounds__(256) void rel_reduce(
    const float* __restrict__ part,
    __half* __restrict__ qh, __half* __restrict__ ql,
    __half* __restrict__ kh, __half* __restrict__ kl)
{
    int idx = blockIdx.x * 256 + threadIdx.x;
    int row = idx >> 6, col = idx & 63;
    float sq = 0.f, sk = 0.f;
    #pragma unroll
    for (int s = 0; s < 4; s++) {
        const float* p = part + (size_t)s * MROWS * 128 + (size_t)row * 128;
        sq += p[col]; sk += p[col + 64];
    }
    __half hq = __float2half_rn(sq);
    __half hk = __float2half_rn(sk);
    qh[(size_t)row * 64 + col] = hq;
    ql[(size_t)row * 64 + col] = __float2half_rn(sq - __half2float(hq));
    kh[(size_t)row * 64 + col] = hk;
    kl[(size_t)row * 64 + col] = __float2half_rn(sk - __half2float(hk));
}

// ======== rel score GEMM: S[b] = qrel · krel^T (3-pass fp16 split, fp32 out) ==
#define RSTRIDE 144
#define RSEGB (128*RSTRIDE)
#define RSMEM (4*RSEGB)

__global__ __launch_bounds__(256) void score_mma(
    const __half* __restrict__ Qrh, const __half* __restrict__ Qrl,
    const __half* __restrict__ Krh, const __half* __restrict__ Krl,
    float* __restrict__ scores)
{
    const int j = blockIdx.x, i = blockIdx.y, b = blockIdx.z;
    if (j > i) return;
    extern __shared__ __half RS[];
    const uint32_t base = smem_u32(RS);
    const int tid = threadIdx.x;
    const int l = tid & 31, wid = tid >> 5;
    const int wm = wid >> 2, wn = wid & 3;
    const int q0 = i * 128, k0 = j * 128;

    const __half* srcs[4] = {
        Qrh + (size_t)(b*LL + q0) * DREL, Qrl + (size_t)(b*LL + q0) * DREL,
        Krh + (size_t)(b*LL + k0) * DREL, Krl + (size_t)(b*LL + k0) * DREL};

    #pragma unroll
    for (int jj = 0; jj < 16; jj++) {
        int idx = tid + jj * 256;
        int seg = idx >> 10, rem = idx & 1023;
        int row = rem >> 3, c16 = rem & 7;
        uint32_t dst = base + (uint32_t)seg * RSEGB + (uint32_t)row * RSTRIDE + c16 * 16;
        const __half* src = srcs[seg] + (size_t)row * DREL + c16 * 8;
        CP_ASYNC16(dst, src);
    }
    CP_COMMIT();
    CP_WAIT(0);
    __syncthreads();

    const int rA = wm * 64 + ((l >> 3) & 1) * 8 + (l & 7);
    const int kA = (l >> 4) * 16;
    const int rB = wn * 32 + ((l >> 4) & 1) * 8 + (l & 7);
    const int kB = ((l >> 3) & 1) * 16;
    const uint32_t sQh = base, sQl = base + RSEGB;
    const uint32_t sKh = base + 2*RSEGB, sKl = base + 3*RSEGB;

    float acc[4][4][4];
    #pragma unroll
    for (int a = 0; a < 4; a++)
        #pragma unroll
        for (int c = 0; c < 4; c++)
            #pragma unroll
            for (int t = 0; t < 4; t++) acc[a][c][t] = 0.f;

    #pragma unroll
    for (int ks = 0; ks < 4; ks++) {
        uint32_t aH[4][4], aL[4][4];
        #pragma unroll
        for (int mf = 0; mf < 4; mf++) {
            ldsm4(aH[mf], sQh + (uint32_t)(rA + mf*16) * RSTRIDE + kA + ks*32);
            ldsm4(aL[mf], sQl + (uint32_t)(rA + mf*16) * RSTRIDE + kA + ks*32);
        }
        #pragma unroll
        for (int nf2 = 0; nf2 < 2; nf2++) {
            uint32_t bH[4], bL[4];
            ldsm4(bH, sKh + (uint32_t)(rB + nf2*16) * RSTRIDE + kB + ks*32);
            #pragma unroll
            for (int mf = 0; mf < 4; mf++) {
                mma16816(acc[mf][2*nf2],   aH[mf], bH + 0);
                mma16816(acc[mf][2*nf2+1], aH[mf], bH + 2);
                mma16816(acc[mf][2*nf2],   aL[mf], bH + 0);
                mma16816(acc[mf][2*nf2+1], aL[mf], bH + 2);
            }
            ldsm4(bL, sKl + (uint32_t)(rB + nf2*16) * RSTRIDE + kB + ks*32);
            #pragma unroll
            for (int mf = 0; mf < 4; mf++) {
                mma16816(acc[mf][2*nf2],   aH[mf], bL + 0);
                mma16816(acc[mf][2*nf2+1], aH[mf], bL + 2);
            }
        }
    }

    const int gid = l >> 2, tig = l & 3;
    #pragma unroll
    for (int mf = 0; mf < 4; mf++) {
        #pragma unroll
        for (int nf = 0; nf < 4; nf++) {
            int r0 = q0 + wm*64 + mf*16 + gid;
            int cc = k0 + wn*32 + nf*8 + tig*2;
            float* s0p = scores + ((size_t)(b*LL) + r0) * LL + cc;
            *(float2*)s0p            = make_float2(acc[mf][nf][0], acc[mf][nf][1]);
            *(float2*)(s0p + 8 * LL) = make_float2(acc[mf][nf][2], acc[mf][nf][3]);
        }
    }
}

// ====================== top-K mask build (one block per (b,q)) ================
__device__ __forceinline__ unsigned ford(float f) {
    unsigned u = __float_as_uint(f);
    return (u & 0x80000000u) ? ~u : (u | 0x80000000u);
}

__global__ __launch_bounds__(256) void build_mask(
    const float* __restrict__ scores, unsigned* __restrict__ mask)
{
    const int q = blockIdx.x;
    const int b = blockIdx.y;
    const int tid = threadIdx.x;

    __shared__ float    s[LL];
    __shared__ unsigned mw[LL/32];
    __shared__ int      hist[256];
    __shared__ int      scan[256];
    __shared__ unsigned sh_prefix;
    __shared__ int      sh_R;

    if (tid < LL/32) mw[tid] = 0u;
    const int n = q + 1;

    if (n <= KSEL) {
        __syncthreads();
        for (int k = tid; k < n; k += 256)
            atomicOr(&mw[k>>5], 1u << (k & 31));
    } else {
        const float* srow = scores + ((size_t)(b*LL + q)) * LL;
        for (int k = tid; k < n; k += 256) s[k] = srow[k];
        __syncthreads();

        unsigned prefix = 0u; int R = KSEL;
        for (int byte = 3; byte >= 0; byte--) {
            hist[tid] = 0;
            __syncthreads();
            const int shift = byte * 8;
            const unsigned pm = (byte == 3) ? 0u : (0xFFFFFFFFu << (shift + 8));
            for (int k = tid; k < n; k += 256) {
                unsigned u = ford(s[k]);
                if ((u & pm) == (prefix & pm))
                    atomicAdd(&hist[(u >> shift) & 255], 1);
            }
            __syncthreads();
            int hv = hist[tid];
            scan[tid] = hv;
            __syncthreads();
            #pragma unroll
            for (int off = 1; off < 256; off <<= 1) {
                int t = (tid + off < 256) ? scan[tid + off] : 0;
                __syncthreads();
                scan[tid] += t;
                __syncthreads();
            }
            int inc = scan[tid];
            int above = inc - hv;
            if (above < R && inc >= R) {
                sh_prefix = prefix | ((unsigned)tid << shift);
                sh_R = R - above;
            }
            __syncthreads();
            prefix = sh_prefix; R = sh_R;
            __syncthreads();
        }
        const unsigned T = prefix;
        for (int k = tid; k < n; k += 256)
            if (ford(s[k]) > T) atomicOr(&mw[k>>5], 1u << (k & 31));
        const int per = (n + 255) >> 8;
        const int lo = tid * per;
        const int hi = (lo + per < n) ? lo + per : n;
        int cnt = 0;
        for (int k = lo; k < hi; k++)
            if (ford(s[k]) == T) cnt++;
        scan[tid] = cnt;
        __syncthreads();
        #pragma unroll
        for (int off = 1; off < 256; off <<= 1) {
            int t = (tid >= off) ? scan[tid - off] : 0;
            __syncthreads();
            scan[tid] += t;
            __syncthreads();
        }
        int excl = scan[tid] - cnt;
        int r2 = R - excl;
        if (r2 > 0) {
            for (int k = lo; k < hi && r2 > 0; k++)
                if (ford(s[k]) == T) { atomicOr(&mw[k>>5], 1u << (k & 31)); r2--; }
        }
    }
    __syncthreads();
    if (tid == 0) mw[q>>5] |= 1u << (q & 31);
    __syncthreads();
    if (tid < LL/32) mask[(size_t)(b*LL + q)*(LL/32) + tid] = mw[tid];
}

// ====================== flash attention (fp16 mma) ============================
// 4 warps, Q-tile 64 (hi only), K/V tiles 64 (hi), double-buffered, 2 CTAs/SM.
// QK 1-pass; PV 2-pass (P hi+lo).
#define QSEG 8704       // 64*136 halves
#define KSEG 8704
#define FOFF_QH 0
#define KVOFF(st, seg) (QSEG + (st)*2*KSEG + (seg)*KSEG)
#define FMASK_B ((QSEG + 4*KSEG)*2)
#define FSMEM   (FMASK_B + 2*512)
#define SC2 0.12751744416168355f               // (1/sqrt(128)) * log2(e)

__global__ __launch_bounds__(128) void flash_mma(
    const __half* __restrict__ Qh,
    const __half* __restrict__ Kh, const __half* __restrict__ Vh,
    const unsigned* __restrict__ mask,
    __half* __restrict__ Ch)
{
    extern __shared__ __half FS[];
    const uint32_t base = smem_u32(FS);
    const uint32_t maskB = base + FMASK_B;

    const int qt = (int)gridDim.x - 1 - (int)blockIdx.x;   // heavy tiles first
    const int h = blockIdx.y, b = blockIdx.z;
    const int q0 = qt * 64;
    const int tid = threadIdx.x;
    const int w = tid >> 5, l = tid & 31;
    const int gid = l >> 2, tig = l & 3;

    // Q load (one-time): 64 rows x 16 chunks = 1024 float4 -> 8/thread
    {
        #pragma unroll
        for (int j = 0; j < 8; j++) {
            int idx = tid + j * 128;
            int row = idx >> 4, c16 = idx & 15;
            uint32_t dst = base + (uint32_t)(row * 136 + c16 * 8) * 2;
            const __half* src = Qh + (size_t)(b*LL + q0 + row) * DD + h * DHD + c16 * 8;
            CP_ASYNC16(dst, src);
        }
        CP_COMMIT();
    }

    auto issue_kv = [&](int kt, int st) {
        const __half* ks[2] = {Kh, Vh};
        #pragma unroll
        for (int j = 0; j < 16; j++) {
            int idx = tid + j * 128;
            int seg = idx >> 10, rem = idx & 1023;
            int row = rem >> 4, c16 = rem & 15;
            uint32_t dst = base + (uint32_t)(KVOFF(st, seg) + row * 136 + c16 * 8) * 2;
            const __half* src = ks[seg] + (size_t)(b*LL + kt*64 + row) * DD + h * DHD + c16 * 8;
            CP_ASYNC16(dst, src);
        }
        if (tid < 64) {
            uint32_t dst = maskB + st * 512 + tid * 8;
            const unsigned* src = &mask[(size_t)(b*LL + q0 + tid) * (LL/32) + kt*2];
            CP_ASYNC8(dst, src);
        }
        CP_COMMIT();
    };

    issue_kv(0, 0);

    const int qa_row = w * 16 + ((l >> 3) & 1) * 8 + (l & 7);
    const int qa_colB = (l >> 4) * 16;
    const int kb_rowBase = ((l >> 4) & 1) * 8 + (l & 7);
    const int kb_colB = ((l >> 3) & 1) * 16;
    const int v_row = l & 15;
    const int v_colB = (l >> 4) * 16;

    float O[16][4];
    #pragma unroll
    for (int i = 0; i < 16; i++)
        #pragma unroll
        for (int t = 0; t < 4; t++) O[i][t] = 0.f;
    float m0 = -1e30f, m1 = -1e30f, rl0 = 0.f, rl1 = 0.f;

    const int rlo2 = (w*16 + gid) * 2;
    const int rhi2 = rlo2 + 16;

    const int ktiles = qt + 1;
    for (int kt = 0; kt < ktiles; kt++) {
        const int st = kt & 1;
        if (kt + 1 < ktiles) {
            __syncthreads();
            issue_kv(kt + 1, st ^ 1);
            CP_WAIT(1);
        } else {
            CP_WAIT(0);
        }
        __syncthreads();

        const uint32_t sKH = base + (uint32_t)KVOFF(st, 0) * 2;
        const uint32_t sVH = base + (uint32_t)KVOFF(st, 1) * 2;
        const uint32_t* maskS = (const uint32_t*)(FS) + (FMASK_B >> 2) + st * 128;

        // ---- S = Qh Kh^T (1-pass) ----
        float Sc[8][4];
        #pragma unroll
        for (int i = 0; i < 8; i++)
            #pragma unroll
            for (int t = 0; t < 4; t++) Sc[i][t] = 0.f;

        #pragma unroll
        for (int kf = 0; kf < 8; kf++) {
            uint32_t aH[4];
            ldsm4(aH, base + (uint32_t)(FOFF_QH + qa_row * 136) * 2 + kf*32 + qa_colB);
            #pragma unroll
            for (int nf2 = 0; nf2 < 4; nf2++) {
                uint32_t bH[4];
                ldsm4(bH, sKH + (uint32_t)((nf2*16 + kb_rowBase) * 136) * 2 + kf*32 + kb_colB);
                mma16816(Sc[2*nf2],   aH, bH + 0);
                mma16816(Sc[2*nf2+1], aH, bH + 2);
            }
        }

        // ---- mask ----
        #pragma unroll
        for (int nf = 0; nf < 8; nf++) {
            unsigned wlo = maskS[rlo2 + (nf >> 2)];
            unsigned whi = maskS[rhi2 + (nf >> 2)];
            int sh = ((nf & 3) << 3) + (tig << 1);
            Sc[nf][0] = ((wlo >> sh) & 1u)     ? Sc[nf][0] : -1e30f;
            Sc[nf][1] = ((wlo >> (sh+1)) & 1u) ? Sc[nf][1] : -1e30f;
            Sc[nf][2] = ((whi >> sh) & 1u)     ? Sc[nf][2] : -1e30f;
            Sc[nf][3] = ((whi >> (sh+1)) & 1u) ? Sc[nf][3] : -1e30f;
        }

        // ---- online softmax ----
        float mx0 = -1e30f, mx1 = -1e30f;
        #pragma unroll
        for (int nf = 0; nf < 8; nf++) {
            mx0 = fmaxf(mx0, fmaxf(Sc[nf][0], Sc[nf][1]));
            mx1 = fmaxf(mx1, fmaxf(Sc[nf][2], Sc[nf][3]));
        }
        mx0 = fmaxf(mx0, __shfl_xor_sync(0xffffffffu, mx0, 1));
        mx0 = fmaxf(mx0, __shfl_xor_sync(0xffffffffu, mx0, 2));
        mx1 = fmaxf(mx1, __shfl_xor_sync(0xffffffffu, mx1, 1));
        mx1 = fmaxf(mx1, __shfl_xor_sync(0xffffffffu, mx1, 2));
        float nm0 = fmaxf(m0, mx0), nm1 = fmaxf(m1, mx1);
        float a0 = ex2f((m0 - nm0) * SC2), a1 = ex2f((m1 - nm1) * SC2);
        m0 = nm0; m1 = nm1;

        float s0 = 0.f, s1 = 0.f;
        #pragma unroll
        for (int nf = 0; nf < 8; nf++) {
            float p0 = ex2f((Sc[nf][0] - m0) * SC2);
            float p1 = ex2f((Sc[nf][1] - m0) * SC2);
            float p2 = ex2f((Sc[nf][2] - m1) * SC2);
            float p3 = ex2f((Sc[nf][3] - m1) * SC2);
            Sc[nf][0] = p0; Sc[nf][1] = p1; Sc[nf][2] = p2; Sc[nf][3] = p3;
            s0 += p0 + p1; s1 += p2 + p3;
        }
        s0 += __shfl_xor_sync(0xffffffffu, s0, 1);
        s0 += __shfl_xor_sync(0xffffffffu, s0, 2);
        s1 += __shfl_xor_sync(0xffffffffu, s1, 1);
        s1 += __shfl_xor_sync(0xffffffffu, s1, 2);
        rl0 = rl0 * a0 + s0;
        rl1 = rl1 * a1 + s1;

        #pragma unroll
        for (int df = 0; df < 16; df++) {
            O[df][0] *= a0; O[df][1] *= a0;
            O[df][2] *= a1; O[df][3] *= a1;
        }

        // ---- O += P V (2-pass: Ph·Vh + Pl·Vh) ----
        #pragma unroll
        for (int kf = 0; kf < 4; kf++) {
            uint32_t Pha[4], Pla[4];
            split2(Sc[2*kf][0],   Sc[2*kf][1],   Pha[0], Pla[0]);
            split2(Sc[2*kf][2],   Sc[2*kf][3],   Pha[1], Pla[1]);
            split2(Sc[2*kf+1][0], Sc[2*kf+1][1], Pha[2], Pla[2]);
            split2(Sc[2*kf+1][2], Sc[2*kf+1][3], Pha[3], Pla[3]);
            #pragma unroll
            for (int df2 = 0; df2 < 8; df2++) {
                uint32_t vh4[4];
                ldsm4t(vh4, sVH + (uint32_t)((kf*16 + v_row) * 136) * 2 + df2*32 + v_colB);
                mma16816(O[2*df2],   Pha, vh4 + 0);
                mma16816(O[2*df2+1], Pha, vh4 + 2);
                mma16816(O[2*df2],   Pla, vh4 + 0);
                mma16816(O[2*df2+1], Pla, vh4 + 2);
            }
        }
    }

    float inv0 = 1.f / rl0, inv1 = 1.f / rl1;
    const size_t rowlo = (size_t)(b*LL + q0 + w*16 + gid) * DD + h * DHD + tig * 2;
    const size_t rowhi = rowlo + 8 * DD;
    #pragma unroll
    for (int df = 0; df < 16; df++) {
        *(uint32_t*)(Ch + rowlo + df*8) = pack_h2(O[df][0] * inv0, O[df][1] * inv0);
        *(uint32_t*)(Ch + rowhi + df*8) = pack_h2(O[df][2] * inv1, O[df][3] * inv1);
    }
}

// ================================ launch ======================================
extern "C" void kernel_launch(void* const* d_in, const int* in_sizes, int n_in,
                              void* d_out, int out_size)
{
    const float* hidden    = (const float*)d_in[0];
    const float* relevance = (const float*)d_in[1];
    const float* Wqr       = (const float*)d_in[2];
    const float* Wkr       = (const float*)d_in[3];
    const float* Wq        = (const float*)d_in[4];
    const float* Wk        = (const float*)d_in[5];
    const float* Wv        = (const float*)d_in[6];
    const float* Wo        = (const float*)d_in[7];
    float* out = (float*)d_out;

    __half *hidh,*hidl,*wqh,*wkh,*wvh,*woh;
    __half *qh,*kh,*vh,*ctxh;
    __half *qrelh,*qrell,*krelh,*krell;
    float *relp,*scores; unsigned* mask;
    cudaGetSymbolAddress((void**)&hidh, g_hidh); cudaGetSymbolAddress((void**)&hidl, g_hidl);
    cudaGetSymbolAddress((void**)&wqh,  g_wqh);
    cudaGetSymbolAddress((void**)&wkh,  g_wkh);
    cudaGetSymbolAddress((void**)&wvh,  g_wvh);
    cudaGetSymbolAddress((void**)&woh,  g_woh);
    cudaGetSymbolAddress((void**)&qh,   g_qh);
    cudaGetSymbolAddress((void**)&kh,   g_kh);
    cudaGetSymbolAddress((void**)&vh,   g_vh);
    cudaGetSymbolAddress((void**)&ctxh, g_ctxh);
    cudaGetSymbolAddress((void**)&qrelh, g_qrelh); cudaGetSymbolAddress((void**)&qrell, g_qrell);
    cudaGetSymbolAddress((void**)&krelh, g_krelh); cudaGetSymbolAddress((void**)&krell, g_krell);
    cudaGetSymbolAddress((void**)&scores, g_scores);
    cudaGetSymbolAddress((void**)&relp, g_relp); cudaGetSymbolAddress((void**)&mask, g_mask);

    cudaFuncSetAttribute(gemm_qkv, cudaFuncAttributeMaxDynamicSharedMemorySize, GSMEM);
    cudaFuncSetAttribute(gemm_o,   cudaFuncAttributeMaxDynamicSharedMemorySize, GSMEM);
    cudaFuncSetAttribute(flash_mma, cudaFuncAttributeMaxDynamicSharedMemorySize, FSMEM);
    cudaFuncSetAttribute(score_mma, cudaFuncAttributeMaxDynamicSharedMemorySize, RSMEM);

    static cudaStream_t sSide = nullptr;
    static cudaEvent_t  evFork = nullptr, evJoin = nullptr;
    if (sSide == nullptr) {
        cudaStreamCreateWithFlags(&sSide, cudaStreamNonBlocking);
        cudaEventCreateWithFlags(&evFork, cudaEventDisableTiming);
        cudaEventCreateWithFlags(&evJoin, cudaEventDisableTiming);
    }

    const int nh4 = MROWS * DD / 4, nw4 = DD * DD / 4;

    // ---- fork: relevance/mask path (+ Wo cvt) on side stream ----
    cudaEventRecord(evFork, 0);
    cudaStreamWaitEvent(sSide, evFork, 0);
    rel_proj<<<dim3(MROWS/64, 4), 256, 0, sSide>>>(relevance, Wqr, Wkr, relp);
    rel_reduce<<<(MROWS*64)/256, 256, 0, sSide>>>(relp, qrelh, qrell, krelh, krell);
    score_mma<<<dim3(16, 16, BB), 256, RSMEM, sSide>>>(qrelh, qrell, krelh, krell, scores);
    build_mask<<<dim3(LL, BB), 256, 0, sSide>>>(scores, mask);
    cvt_hi<<<(nw4 + 255)/256, 256, 0, sSide>>>((const float4*)Wo, (uint2*)woh, nw4);
    cudaEventRecord(evJoin, sSide);

    // ---- main stream: conversions + QKV ----
    cvt_split<<<(nh4 + 255)/256, 256>>>((const float4*)hidden, (uint2*)hidh, (uint2*)hidl, nh4);
    cvt_hi3<<<dim3((nw4 + 255)/256, 3), 256>>>(
        (const float4*)Wq, (const float4*)Wk, (const float4*)Wv,
        (uint2*)wqh, (uint2*)wkh, (uint2*)wvh, nw4);

    gemm_qkv<<<dim3(DD/256, MROWS/128, 3), 256, GSMEM>>>(
        hidh, hidl, wqh, qh, wkh, kh, wvh, vh);

    // ---- join, then attention + output projection ----
    cudaStreamWaitEvent(0, evJoin, 0);
    flash_mma<<<dim3(LL/64, HH, BB), 128, FSMEM>>>(qh, kh, vh, mask, ctxh);
    gemm_o<<<dim3(DD/256, MROWS/128), 256, GSMEM>>>(ctxh, woh, out);
}